// round 1
// baseline (speedup 1.0000x reference)
#include <cuda_runtime.h>
#include <math.h>

#define BSZ 64
#define HID 512
#define EMB 300
#define VQ  32000
#define SOS 1

// ---------------- persistent device state ----------------
__device__ float g_hbuf[2][BSZ * HID];          // ping-pong h
__device__ float g_c[BSZ * HID];                // cell state
__device__ int   g_idx[BSZ];                    // current token (full-dict index)
__device__ unsigned long long g_amax[BSZ];      // packed (max, ~argmax)
__device__ float g_lse[BSZ];                    // per-row logsumexp

// order-preserving float <-> u32
__device__ __forceinline__ unsigned int fmono(float f) {
    unsigned int u = __float_as_uint(f);
    return (u & 0x80000000u) ? ~u : (u | 0x80000000u);
}
__device__ __forceinline__ float fmono_inv(unsigned int u) {
    return (u & 0x80000000u) ? __uint_as_float(u & 0x7FFFFFFFu)
                             : __uint_as_float(~u);
}

// ---------------- init ----------------
__global__ void k_init(const float* __restrict__ q_att,
                       const int*   __restrict__ qix) {
    int t = threadIdx.x;
    if (t < BSZ) { g_idx[t] = qix[SOS]; g_amax[t] = 0ull; }
    for (int i = t; i < BSZ * HID; i += blockDim.x) {
        g_hbuf[0][i] = q_att[i];
        g_c[i] = 0.f;
    }
}

// ---------------- fused LSTM step ----------------
// grid: 64 blocks x 256 thr. Block b covers 8 hidden units (j0..j0+7),
// i.e. 32 gate rows (i,f,g,o x 8) over all 64 batch rows.
__global__ void k_lstm(const float* __restrict__ emb,
                       const float* __restrict__ W_ih,
                       const float* __restrict__ W_hh,
                       const float* __restrict__ b_ih,
                       const float* __restrict__ b_hh,
                       int par) {
    __shared__ float xh_s[32][66];     // [k][batch]
    __shared__ float w_s[32][36];      // [k][gate-row-local]
    __shared__ float gates_s[32][66];  // [gate-row-local][batch]
    __shared__ int   sidx[BSZ];

    const float* hin  = g_hbuf[par];
    float*       hout = g_hbuf[par ^ 1];

    int t  = threadIdx.x;
    int tx = t & 7, ty = t >> 3;
    int j0 = blockIdx.x * 8;
    int r0 = tx * 4, m0 = ty * 2;

    if (t < BSZ) sidx[t] = g_idx[t];

    float acc[4][2];
#pragma unroll
    for (int i = 0; i < 4; i++)
#pragma unroll
        for (int j = 0; j < 2; j++) acc[i][j] = 0.f;
    __syncthreads();

    // ---- phase 1: x = relu(emb[idx]) against W_ih (K = 300, ragged) ----
    for (int k0 = 0; k0 < EMB; k0 += 32) {
        for (int i = t; i < 2048; i += 256) {
            int kk = i & 31, m = i >> 5;
            int k = k0 + kk;
            float v = 0.f;
            if (k < EMB) v = fmaxf(emb[(long)sidx[m] * EMB + k], 0.f);
            xh_s[kk][m] = v;
        }
        for (int i = t; i < 1024; i += 256) {
            int kk = i & 31, r = i >> 5;
            int k = k0 + kk;
            int gr = (r >> 3) * HID + j0 + (r & 7);
            w_s[kk][r] = (k < EMB) ? W_ih[(long)gr * EMB + k] : 0.f;
        }
        __syncthreads();
#pragma unroll
        for (int kk = 0; kk < 32; kk++) {
            float4 w4 = *(const float4*)&w_s[kk][r0];
            float2 a2 = *(const float2*)&xh_s[kk][m0];
            float w[4] = {w4.x, w4.y, w4.z, w4.w};
            float a[2] = {a2.x, a2.y};
#pragma unroll
            for (int i = 0; i < 4; i++)
#pragma unroll
                for (int j = 0; j < 2; j++)
                    acc[i][j] = fmaf(w[i], a[j], acc[i][j]);
        }
        __syncthreads();
    }

    // ---- phase 2: h against W_hh (K = 512) ----
    for (int k0 = 0; k0 < HID; k0 += 32) {
        for (int i = t; i < 2048; i += 256) {
            int kk = i & 31, m = i >> 5;
            xh_s[kk][m] = hin[m * HID + k0 + kk];
        }
        for (int i = t; i < 1024; i += 256) {
            int kk = i & 31, r = i >> 5;
            int gr = (r >> 3) * HID + j0 + (r & 7);
            w_s[kk][r] = W_hh[(long)gr * HID + k0 + kk];
        }
        __syncthreads();
#pragma unroll
        for (int kk = 0; kk < 32; kk++) {
            float4 w4 = *(const float4*)&w_s[kk][r0];
            float2 a2 = *(const float2*)&xh_s[kk][m0];
            float w[4] = {w4.x, w4.y, w4.z, w4.w};
            float a[2] = {a2.x, a2.y};
#pragma unroll
            for (int i = 0; i < 4; i++)
#pragma unroll
                for (int j = 0; j < 2; j++)
                    acc[i][j] = fmaf(w[i], a[j], acc[i][j]);
        }
        __syncthreads();
    }

    // ---- epilogue: bias, cell update ----
#pragma unroll
    for (int i = 0; i < 4; i++) {
        int r  = r0 + i;
        int gr = (r >> 3) * HID + j0 + (r & 7);
        float bs = b_ih[gr] + b_hh[gr];
        gates_s[r][m0]     = acc[i][0] + bs;
        gates_s[r][m0 + 1] = acc[i][1] + bs;
    }
    __syncthreads();

    for (int p = t; p < 512; p += 256) {
        int u = p >> 6, m = p & 63;
        float gi = gates_s[u][m];
        float gf = gates_s[8 + u][m];
        float gg = gates_s[16 + u][m];
        float go = gates_s[24 + u][m];
        int ci = m * HID + j0 + u;
        float c  = g_c[ci];
        float si = 1.f / (1.f + expf(-gi));
        float sf = 1.f / (1.f + expf(-gf));
        float so = 1.f / (1.f + expf(-go));
        float nc = sf * c + si * tanhf(gg);
        float nh = so * tanhf(nc);
        g_c[ci]  = nc;
        hout[ci] = nh;
    }
}

// ---------------- logits GEMM (64 x 32000, K=512) + fused argmax ----------------
// grid: 250 blocks (128 vocab cols each) x 256 thr. Writes raw logits to out,
// atomically merges (max, argmax) per batch row.
__global__ void __launch_bounds__(256, 2)
k_logits(const float* __restrict__ out_W,
         const float* __restrict__ out_b,
         float* __restrict__ out,
         int hpar, int step, int steps) {
    __shared__ float A_s[32][68];    // [k][batch]
    __shared__ float B_s[32][132];   // [k][vocab-local]

    const float* h = g_hbuf[hpar];
    int t  = threadIdx.x;
    int tx = t & 15, ty = t >> 4;
    int v0 = blockIdx.x * 128;

    float acc[4][8];
#pragma unroll
    for (int i = 0; i < 4; i++)
#pragma unroll
        for (int j = 0; j < 8; j++) acc[i][j] = 0.f;

    for (int k0 = 0; k0 < HID; k0 += 32) {
        for (int i = t; i < 2048; i += 256) {
            int kk = i & 31, m = i >> 5;
            A_s[kk][m] = h[m * HID + k0 + kk];
        }
        for (int i = t; i < 4096; i += 256) {
            int kk = i & 31, v = i >> 5;
            B_s[kk][v] = out_W[(long)(v0 + v) * HID + k0 + kk];
        }
        __syncthreads();
#pragma unroll
        for (int kk = 0; kk < 32; kk++) {
            float4 a4 = *(const float4*)&A_s[kk][ty * 4];
            float4 b0 = *(const float4*)&B_s[kk][tx * 8];
            float4 b1 = *(const float4*)&B_s[kk][tx * 8 + 4];
            float a[4]  = {a4.x, a4.y, a4.z, a4.w};
            float bb[8] = {b0.x, b0.y, b0.z, b0.w, b1.x, b1.y, b1.z, b1.w};
#pragma unroll
            for (int i = 0; i < 4; i++)
#pragma unroll
                for (int j = 0; j < 8; j++)
                    acc[i][j] = fmaf(a[i], bb[j], acc[i][j]);
        }
        __syncthreads();
    }

    float ob[8];
#pragma unroll
    for (int j = 0; j < 8; j++) ob[j] = out_b[v0 + tx * 8 + j];

#pragma unroll
    for (int i = 0; i < 4; i++) {
        int mb = ty * 4 + i;
        float* orow = out + (long)mb * steps * VQ + (long)step * VQ + v0 + tx * 8;
        float vmax = -3.4e38f;
        int   vidx = 0;
        float vals[8];
#pragma unroll
        for (int j = 0; j < 8; j++) {
            vals[j] = acc[i][j] + ob[j];
            if (vals[j] > vmax) { vmax = vals[j]; vidx = v0 + tx * 8 + j; }
        }
        *(float4*)orow       = make_float4(vals[0], vals[1], vals[2], vals[3]);
        *(float4*)(orow + 4) = make_float4(vals[4], vals[5], vals[6], vals[7]);

        unsigned long long key =
            ((unsigned long long)fmono(vmax) << 32) |
            (unsigned int)(~(unsigned int)vidx);
#pragma unroll
        for (int ofs = 8; ofs >= 1; ofs >>= 1) {
            unsigned long long other = __shfl_xor_sync(0xFFFFFFFFu, key, ofs);
            if (other > key) key = other;
        }
        if (tx == 0) atomicMax(&g_amax[mb], key);
    }
}

// ---------------- per-row logsumexp + next token ----------------
__global__ void k_reduce(const float* __restrict__ out,
                         const int*   __restrict__ qix,
                         int step, int steps) {
    int b = blockIdx.x;
    int t = threadIdx.x;
    unsigned long long key = g_amax[b];
    float m = fmono_inv((unsigned int)(key >> 32));

    const float4* row4 =
        (const float4*)(out + (long)b * steps * VQ + (long)step * VQ);
    float s = 0.f;
    for (int v = t; v < VQ / 4; v += blockDim.x) {
        float4 x = row4[v];
        s += expf(x.x - m) + expf(x.y - m) + expf(x.z - m) + expf(x.w - m);
    }
    __shared__ float red[8];
#pragma unroll
    for (int o = 16; o >= 1; o >>= 1) s += __shfl_xor_sync(0xFFFFFFFFu, s, o);
    if ((t & 31) == 0) red[t >> 5] = s;
    __syncthreads();
    if (t < 8) {
        s = red[t];
#pragma unroll
        for (int o = 4; o >= 1; o >>= 1) s += __shfl_xor_sync(0xFFu, s, o);
        if (t == 0) {
            g_lse[b] = m + logf(s);
            unsigned int vv = ~(unsigned int)(key & 0xFFFFFFFFull);
            g_idx[b]  = qix[vv];
            g_amax[b] = 0ull;   // ready for next step
        }
    }
}

// ---------------- logp = logits - lse (in place) ----------------
__global__ void k_fix(float* __restrict__ out, int step, int steps) {
    long i  = (long)blockIdx.x * blockDim.x + threadIdx.x;  // over 64*8000 float4
    int  b  = (int)(i / (VQ / 4));
    int  v4 = (int)(i % (VQ / 4));
    float lse = g_lse[b];
    float4* p = (float4*)(out + (long)b * steps * VQ + (long)step * VQ) + v4;
    float4 x = *p;
    x.x -= lse; x.y -= lse; x.z -= lse; x.w -= lse;
    *p = x;
}

// ---------------- launch ----------------
extern "C" void kernel_launch(void* const* d_in, const int* in_sizes, int n_in,
                              void* d_out, int out_size) {
    (void)in_sizes; (void)n_in;
    const float* q_att = (const float*)d_in[1];
    const float* emb   = (const float*)d_in[2];
    const float* W_ih  = (const float*)d_in[3];
    const float* W_hh  = (const float*)d_in[4];
    const float* b_ih  = (const float*)d_in[5];
    const float* b_hh  = (const float*)d_in[6];
    const float* out_W = (const float*)d_in[7];
    const float* out_b = (const float*)d_in[8];
    const int*   qix   = (const int*)d_in[9];

    int steps = out_size / (BSZ * VQ);  // 33

    k_init<<<1, 256>>>(q_att, qix);
    for (int s = 0; s < steps; s++) {
        int par = s & 1;
        k_lstm<<<64, 256>>>(emb, W_ih, W_hh, b_ih, b_hh, par);
        k_logits<<<250, 256>>>(out_W, out_b, (float*)d_out, par ^ 1, s, steps);
        k_reduce<<<BSZ, 256>>>((const float*)d_out, qix, s, steps);
        k_fix<<<BSZ * (VQ / 4) / 256, 256>>>((float*)d_out, s, steps);
    }
}

// round 2
// speedup vs baseline: 1.4021x; 1.4021x over previous
#include <cuda_runtime.h>
#include <math.h>

#define BSZ 64
#define HID 512
#define EMB 300
#define VQ  32000
#define SOS 1
#define NBLK 125            // VQ / 256

// ---------------- persistent device state ----------------
__device__ float g_hbuf[2][BSZ * HID];          // ping-pong h
__device__ float g_c[BSZ * HID];                // cell state
__device__ int   g_idx[BSZ];                    // current token (full-dict index)
__device__ unsigned long long g_amax[BSZ];      // packed (max, ~argmax)
__device__ float g_lse[BSZ];                    // per-row logsumexp
__device__ float2 g_part[BSZ][NBLK];            // per-(row, block) softmax partials

// order-preserving float <-> u32
__device__ __forceinline__ unsigned int fmono(float f) {
    unsigned int u = __float_as_uint(f);
    return (u & 0x80000000u) ? ~u : (u | 0x80000000u);
}
__device__ __forceinline__ float fmono_inv(unsigned int u) {
    return (u & 0x80000000u) ? __uint_as_float(u & 0x7FFFFFFFu)
                             : __uint_as_float(~u);
}

// FFMA-only exp (no MUFU). |rel err| ~ 2.4e-6. Valid for x <= ~80.
__device__ __forceinline__ float fexp(float x) {
    x = fmaxf(x, -80.0f);
    float t = fmaf(x, 1.4426950408889634f, 12582912.0f);   // round(x*log2e)+magic
    float i = t - 12582912.0f;
    float f = fmaf(x, 1.4426950408889634f, -i);            // frac in [-0.5, 0.5]
    float p = 1.3333558e-3f;
    p = fmaf(p, f, 9.6181291e-3f);
    p = fmaf(p, f, 5.5504110e-2f);
    p = fmaf(p, f, 2.4022651e-1f);
    p = fmaf(p, f, 6.9314718e-1f);
    p = fmaf(p, f, 1.0f);
    int ei = __float_as_int(t) - 0x4B400000;               // = round(x*log2e)
    float sc = __int_as_float((ei + 127) << 23);
    return sc * p;
}

// ---------------- init ----------------
__global__ void k_init(const float* __restrict__ q_att,
                       const int*   __restrict__ qix) {
    int t = threadIdx.x;
    if (t < BSZ) { g_idx[t] = qix[SOS]; g_amax[t] = 0ull; }
    for (int i = t; i < BSZ * HID; i += blockDim.x) {
        g_hbuf[0][i] = q_att[i];
        g_c[i] = 0.f;
    }
}

// ---------------- fused LSTM step (unchanged from R1) ----------------
__global__ void k_lstm(const float* __restrict__ emb,
                       const float* __restrict__ W_ih,
                       const float* __restrict__ W_hh,
                       const float* __restrict__ b_ih,
                       const float* __restrict__ b_hh,
                       int par) {
    __shared__ float xh_s[32][66];
    __shared__ float w_s[32][36];
    __shared__ float gates_s[32][66];
    __shared__ int   sidx[BSZ];

    const float* hin  = g_hbuf[par];
    float*       hout = g_hbuf[par ^ 1];

    int t  = threadIdx.x;
    int tx = t & 7, ty = t >> 3;
    int j0 = blockIdx.x * 8;
    int r0 = tx * 4, m0 = ty * 2;

    if (t < BSZ) sidx[t] = g_idx[t];

    float acc[4][2];
#pragma unroll
    for (int i = 0; i < 4; i++)
#pragma unroll
        for (int j = 0; j < 2; j++) acc[i][j] = 0.f;
    __syncthreads();

    for (int k0 = 0; k0 < EMB; k0 += 32) {
        for (int i = t; i < 2048; i += 256) {
            int kk = i & 31, m = i >> 5;
            int k = k0 + kk;
            float v = 0.f;
            if (k < EMB) v = fmaxf(emb[(long)sidx[m] * EMB + k], 0.f);
            xh_s[kk][m] = v;
        }
        for (int i = t; i < 1024; i += 256) {
            int kk = i & 31, r = i >> 5;
            int k = k0 + kk;
            int gr = (r >> 3) * HID + j0 + (r & 7);
            w_s[kk][r] = (k < EMB) ? W_ih[(long)gr * EMB + k] : 0.f;
        }
        __syncthreads();
#pragma unroll
        for (int kk = 0; kk < 32; kk++) {
            float4 w4 = *(const float4*)&w_s[kk][r0];
            float2 a2 = *(const float2*)&xh_s[kk][m0];
            float w[4] = {w4.x, w4.y, w4.z, w4.w};
            float a[2] = {a2.x, a2.y};
#pragma unroll
            for (int i = 0; i < 4; i++)
#pragma unroll
                for (int j = 0; j < 2; j++)
                    acc[i][j] = fmaf(w[i], a[j], acc[i][j]);
        }
        __syncthreads();
    }

    for (int k0 = 0; k0 < HID; k0 += 32) {
        for (int i = t; i < 2048; i += 256) {
            int kk = i & 31, m = i >> 5;
            xh_s[kk][m] = hin[m * HID + k0 + kk];
        }
        for (int i = t; i < 1024; i += 256) {
            int kk = i & 31, r = i >> 5;
            int gr = (r >> 3) * HID + j0 + (r & 7);
            w_s[kk][r] = W_hh[(long)gr * HID + k0 + kk];
        }
        __syncthreads();
#pragma unroll
        for (int kk = 0; kk < 32; kk++) {
            float4 w4 = *(const float4*)&w_s[kk][r0];
            float2 a2 = *(const float2*)&xh_s[kk][m0];
            float w[4] = {w4.x, w4.y, w4.z, w4.w};
            float a[2] = {a2.x, a2.y};
#pragma unroll
            for (int i = 0; i < 4; i++)
#pragma unroll
                for (int j = 0; j < 2; j++)
                    acc[i][j] = fmaf(w[i], a[j], acc[i][j]);
        }
        __syncthreads();
    }

#pragma unroll
    for (int i = 0; i < 4; i++) {
        int r  = r0 + i;
        int gr = (r >> 3) * HID + j0 + (r & 7);
        float bs = b_ih[gr] + b_hh[gr];
        gates_s[r][m0]     = acc[i][0] + bs;
        gates_s[r][m0 + 1] = acc[i][1] + bs;
    }
    __syncthreads();

    for (int p = t; p < 512; p += 256) {
        int u = p >> 6, m = p & 63;
        float gi = gates_s[u][m];
        float gf = gates_s[8 + u][m];
        float gg = gates_s[16 + u][m];
        float go = gates_s[24 + u][m];
        int ci = m * HID + j0 + u;
        float c  = g_c[ci];
        float si = 1.f / (1.f + expf(-gi));
        float sf = 1.f / (1.f + expf(-gf));
        float so = 1.f / (1.f + expf(-go));
        float nc = sf * c + si * tanhf(gg);
        float nh = so * tanhf(nc);
        g_c[ci]  = nc;
        hout[ci] = nh;
    }
}

// ---------------- logits GEMM: 64 x 32000, K=512 ----------------
// 125 blocks x 256 threads, block tile 64(M) x 256(N), thread tile 8x8,
// BK=16 double-buffered. Fused: bias add, raw-logit store, per-row packed
// argmax atomic, per-(row,block) softmax partials (max, sum-exp).
__global__ void __launch_bounds__(256)
k_logits(const float* __restrict__ out_W,
         const float* __restrict__ out_b,
         float* __restrict__ out,
         int hpar, int step, int steps) {
    __shared__ float A_s[2][16][68];     // [k][m], pad 68 (272B: 16B-aligned rows)
    __shared__ float B_s[2][16][260];    // [k][n], pad 260 (1040B rows)

    const float* h = g_hbuf[hpar];
    const int t  = threadIdx.x;
    const int v0 = blockIdx.x * 256;

    const int m0  = (t >> 5) * 8;        // warp -> 8 batch rows (row lives in warp)
    const int ln  = t & 31;
    const int n0  = ln * 4;              // thread cols: n0..n0+3, n0+128..n0+131

    // global-load mapping: thread -> (row = t>>2, float4 chunk = t&3)
    const int gv = t >> 2, gc = (t & 3) * 4;

    float4 aR;
    float4 bR[4];

    // prefetch chunk 0
    {
        aR = *(const float4*)&h[gv * HID + gc];
#pragma unroll
        for (int r = 0; r < 4; r++)
            bR[r] = *(const float4*)&out_W[(size_t)(v0 + gv + r * 64) * HID + gc];
    }
    {
        A_s[0][gc + 0][gv] = aR.x; A_s[0][gc + 1][gv] = aR.y;
        A_s[0][gc + 2][gv] = aR.z; A_s[0][gc + 3][gv] = aR.w;
#pragma unroll
        for (int r = 0; r < 4; r++) {
            B_s[0][gc + 0][gv + r * 64] = bR[r].x;
            B_s[0][gc + 1][gv + r * 64] = bR[r].y;
            B_s[0][gc + 2][gv + r * 64] = bR[r].z;
            B_s[0][gc + 3][gv + r * 64] = bR[r].w;
        }
    }
    __syncthreads();

    float acc[8][8];
#pragma unroll
    for (int i = 0; i < 8; i++)
#pragma unroll
        for (int j = 0; j < 8; j++) acc[i][j] = 0.f;

    int buf = 0;
    for (int chunk = 0; chunk < HID / 16; chunk++) {
        if (chunk < HID / 16 - 1) {
            int k0 = (chunk + 1) * 16;
            aR = *(const float4*)&h[gv * HID + k0 + gc];
#pragma unroll
            for (int r = 0; r < 4; r++)
                bR[r] = *(const float4*)&out_W[(size_t)(v0 + gv + r * 64) * HID + k0 + gc];
        }
#pragma unroll
        for (int kk = 0; kk < 16; kk++) {
            float4 a0 = *(const float4*)&A_s[buf][kk][m0];
            float4 a1 = *(const float4*)&A_s[buf][kk][m0 + 4];
            float4 b0 = *(const float4*)&B_s[buf][kk][n0];
            float4 b1 = *(const float4*)&B_s[buf][kk][n0 + 128];
            float a[8] = {a0.x, a0.y, a0.z, a0.w, a1.x, a1.y, a1.z, a1.w};
            float b[8] = {b0.x, b0.y, b0.z, b0.w, b1.x, b1.y, b1.z, b1.w};
#pragma unroll
            for (int i = 0; i < 8; i++)
#pragma unroll
                for (int j = 0; j < 8; j++)
                    acc[i][j] = fmaf(a[i], b[j], acc[i][j]);
        }
        if (chunk < HID / 16 - 1) {
            int nb = buf ^ 1;
            A_s[nb][gc + 0][gv] = aR.x; A_s[nb][gc + 1][gv] = aR.y;
            A_s[nb][gc + 2][gv] = aR.z; A_s[nb][gc + 3][gv] = aR.w;
#pragma unroll
            for (int r = 0; r < 4; r++) {
                B_s[nb][gc + 0][gv + r * 64] = bR[r].x;
                B_s[nb][gc + 1][gv + r * 64] = bR[r].y;
                B_s[nb][gc + 2][gv + r * 64] = bR[r].z;
                B_s[nb][gc + 3][gv + r * 64] = bR[r].w;
            }
            __syncthreads();
            buf = nb;
        }
    }

    // ---- epilogue ----
    const int c0 = v0 + n0, c1 = v0 + n0 + 128;
    float4 ob0 = *(const float4*)&out_b[c0];
    float4 ob1 = *(const float4*)&out_b[c1];

#pragma unroll
    for (int i = 0; i < 8; i++) {
        int mb = m0 + i;
        float vals[8];
        vals[0] = acc[i][0] + ob0.x; vals[1] = acc[i][1] + ob0.y;
        vals[2] = acc[i][2] + ob0.z; vals[3] = acc[i][3] + ob0.w;
        vals[4] = acc[i][4] + ob1.x; vals[5] = acc[i][5] + ob1.y;
        vals[6] = acc[i][6] + ob1.z; vals[7] = acc[i][7] + ob1.w;

        // store raw logits
        float* orow = out + (size_t)mb * steps * VQ + (size_t)step * VQ;
        *(float4*)&orow[c0] = make_float4(vals[0], vals[1], vals[2], vals[3]);
        *(float4*)&orow[c1] = make_float4(vals[4], vals[5], vals[6], vals[7]);

        // thread-local max (ascending index order; strict > keeps first index)
        float vm = vals[0]; int vi = c0;
#pragma unroll
        for (int j = 1; j < 4; j++)
            if (vals[j] > vm) { vm = vals[j]; vi = c0 + j; }
#pragma unroll
        for (int j = 4; j < 8; j++)
            if (vals[j] > vm) { vm = vals[j]; vi = c1 + j - 4; }

        unsigned long long key =
            ((unsigned long long)fmono(vm) << 32) |
            (unsigned int)(~(unsigned int)vi);
#pragma unroll
        for (int ofs = 16; ofs >= 1; ofs >>= 1) {
            unsigned long long o = __shfl_xor_sync(0xFFFFFFFFu, key, ofs);
            if (o > key) key = o;
        }
        // warp/block max for this row (row fully inside this warp)
        float mrow = fmono_inv((unsigned int)(key >> 32));

        float s = 0.f;
#pragma unroll
        for (int j = 0; j < 8; j++) s += fexp(vals[j] - mrow);
#pragma unroll
        for (int ofs = 16; ofs >= 1; ofs >>= 1)
            s += __shfl_xor_sync(0xFFFFFFFFu, s, ofs);

        if (ln == 0) {
            atomicMax(&g_amax[mb], key);
            g_part[mb][blockIdx.x] = make_float2(mrow, s);
        }
    }
}

// ---------------- combine partials: lse + next token ----------------
__global__ void k_reduce(const int* __restrict__ qix) {
    int b = blockIdx.x;
    int t = threadIdx.x;  // 128 threads
    __shared__ float sm[4], ss[4];

    float m = -3.4e38f;
    float2 p = make_float2(-3.4e38f, 0.f);
    if (t < NBLK) { p = g_part[b][t]; m = p.x; }
#pragma unroll
    for (int o = 16; o >= 1; o >>= 1)
        m = fmaxf(m, __shfl_xor_sync(0xFFFFFFFFu, m, o));
    if ((t & 31) == 0) sm[t >> 5] = m;
    __syncthreads();
    float M = fmaxf(fmaxf(sm[0], sm[1]), fmaxf(sm[2], sm[3]));

    float s = (t < NBLK) ? p.y * fexp(p.x - M) : 0.f;
#pragma unroll
    for (int o = 16; o >= 1; o >>= 1)
        s += __shfl_xor_sync(0xFFFFFFFFu, s, o);
    if ((t & 31) == 0) ss[t >> 5] = s;
    __syncthreads();

    if (t == 0) {
        float S = ss[0] + ss[1] + ss[2] + ss[3];
        g_lse[b] = M + logf(S);
        unsigned long long key = g_amax[b];
        unsigned int vv = ~(unsigned int)(key & 0xFFFFFFFFull);
        g_idx[b]  = qix[vv];
        g_amax[b] = 0ull;
    }
}

// ---------------- logp = logits - lse (in place) ----------------
__global__ void k_fix(float* __restrict__ out, int step, int steps) {
    long i  = (long)blockIdx.x * blockDim.x + threadIdx.x;
    int  b  = (int)(i / (VQ / 4));
    int  v4 = (int)(i % (VQ / 4));
    float lse = g_lse[b];
    float4* p = (float4*)(out + (long)b * steps * VQ + (long)step * VQ) + v4;
    float4 x = *p;
    x.x -= lse; x.y -= lse; x.z -= lse; x.w -= lse;
    *p = x;
}

// ---------------- launch ----------------
extern "C" void kernel_launch(void* const* d_in, const int* in_sizes, int n_in,
                              void* d_out, int out_size) {
    (void)in_sizes; (void)n_in;
    const float* q_att = (const float*)d_in[1];
    const float* emb   = (const float*)d_in[2];
    const float* W_ih  = (const float*)d_in[3];
    const float* W_hh  = (const float*)d_in[4];
    const float* b_ih  = (const float*)d_in[5];
    const float* b_hh  = (const float*)d_in[6];
    const float* out_W = (const float*)d_in[7];
    const float* out_b = (const float*)d_in[8];
    const int*   qix   = (const int*)d_in[9];

    int steps = out_size / (BSZ * VQ);  // 33

    k_init<<<1, 256>>>(q_att, qix);
    for (int s = 0; s < steps; s++) {
        int par = s & 1;
        k_lstm<<<64, 256>>>(emb, W_ih, W_hh, b_ih, b_hh, par);
        k_logits<<<NBLK, 256>>>(out_W, out_b, (float*)d_out, par ^ 1, s, steps);
        k_reduce<<<BSZ, 128>>>(qix);
        k_fix<<<BSZ * (VQ / 4) / 256, 256>>>((float*)d_out, s, steps);
    }
}

// round 4
// speedup vs baseline: 1.4222x; 1.0143x over previous
#include <cuda_runtime.h>
#include <cuda_bf16.h>
#include <math.h>
#include <stdint.h>

#define BSZ 64
#define HID 512
#define EMB 300
#define VQ  32000
#define SOS 1
#define NBLK 125            // VQ / 256
#define NCHUNK 8            // K chunks of 64

// smem layout (relative to 1024-aligned base)
// A: buf b: hi @ b*16384, lo @ b*16384+8192        (32 KB total)
// B: buf b: hi @ 32768+b*65536, lo @ +32768        (128 KB total)
// bias @ 163840 (1 KB). dsm (epilogue) aliases offset 0 (67.6 KB).
#define OFF_B    32768
#define OFF_BIAS 163840
#define SMEM_REQ (164864 + 1024)
#define DP 264              // dsm row stride in floats

// ---------------- persistent device state ----------------
__device__ float g_hbuf[2][BSZ * HID];
__device__ float g_c[BSZ * HID];
__device__ unsigned long long g_amax[2][BSZ];   // ping-pong packed (max, ~argmax)
__device__ float2 g_part[BSZ][NBLK];
__device__ float g_scr[(size_t)BSZ * VQ];
__device__ __nv_bfloat16 g_Whi[(size_t)VQ * HID];
__device__ __nv_bfloat16 g_Wlo[(size_t)VQ * HID];

// ---------------- helpers ----------------
__device__ __forceinline__ unsigned int fmono(float f) {
    unsigned int u = __float_as_uint(f);
    return (u & 0x80000000u) ? ~u : (u | 0x80000000u);
}
__device__ __forceinline__ float fmono_inv(unsigned int u) {
    return (u & 0x80000000u) ? __uint_as_float(u & 0x7FFFFFFFu)
                             : __uint_as_float(~u);
}
__device__ __forceinline__ float fexp(float x) {
    x = fmaxf(x, -80.0f);
    float t = fmaf(x, 1.4426950408889634f, 12582912.0f);
    float i = t - 12582912.0f;
    float f = fmaf(x, 1.4426950408889634f, -i);
    float p = 1.3333558e-3f;
    p = fmaf(p, f, 9.6181291e-3f);
    p = fmaf(p, f, 5.5504110e-2f);
    p = fmaf(p, f, 2.4022651e-1f);
    p = fmaf(p, f, 6.9314718e-1f);
    p = fmaf(p, f, 1.0f);
    int ei = __float_as_int(t) - 0x4B400000;
    float sc = __int_as_float((ei + 127) << 23);
    return sc * p;
}
__device__ __forceinline__ uint32_t smem_u32(const void* p) {
    uint32_t a;
    asm("{ .reg .u64 t; cvta.to.shared.u64 t, %1; cvt.u32.u64 %0, t; }"
        : "=r"(a) : "l"(p));
    return a;
}
__device__ __forceinline__ uint32_t sw128(uint32_t o) { return o ^ ((o >> 3) & 0x70); }
__device__ __forceinline__ uint32_t pb2(float a, float b) {
    __nv_bfloat162 t = __floats2bfloat162_rn(a, b);
    return *reinterpret_cast<uint32_t*>(&t);
}

#define CP_ASYNC16(dst, src) \
    asm volatile("cp.async.cg.shared.global [%0], [%1], 16;" :: "r"(dst), "l"(src) : "memory")
#define CP_COMMIT() asm volatile("cp.async.commit_group;" ::: "memory")
#define CP_WAIT(n)  asm volatile("cp.async.wait_group %0;" :: "n"(n) : "memory")

__device__ __forceinline__ void ldsm4(uint32_t* r, uint32_t addr) {
    asm volatile("ldmatrix.sync.aligned.m8n8.x4.shared.b16 {%0,%1,%2,%3}, [%4];"
                 : "=r"(r[0]), "=r"(r[1]), "=r"(r[2]), "=r"(r[3]) : "r"(addr));
}
__device__ __forceinline__ void mma16816(float* d, const uint32_t* a, const uint32_t* b) {
    asm volatile(
        "mma.sync.aligned.m16n8k16.row.col.f32.bf16.bf16.f32 "
        "{%0,%1,%2,%3}, {%4,%5,%6,%7}, {%8,%9}, {%0,%1,%2,%3};"
        : "+f"(d[0]), "+f"(d[1]), "+f"(d[2]), "+f"(d[3])
        : "r"(a[0]), "r"(a[1]), "r"(a[2]), "r"(a[3]), "r"(b[0]), "r"(b[1]));
}

// ---------------- prep: split out_W into bf16 hi/lo ----------------
__global__ void k_prep(const float* __restrict__ W) {
    size_t n4 = (size_t)VQ * HID / 4;
    uint2* whi = (uint2*)g_Whi;
    uint2* wlo = (uint2*)g_Wlo;
    for (size_t i = (size_t)blockIdx.x * blockDim.x + threadIdx.x; i < n4;
         i += (size_t)gridDim.x * blockDim.x) {
        float4 x = ((const float4*)W)[i];
        float hx = __bfloat162float(__float2bfloat16_rn(x.x));
        float hy = __bfloat162float(__float2bfloat16_rn(x.y));
        float hz = __bfloat162float(__float2bfloat16_rn(x.z));
        float hw = __bfloat162float(__float2bfloat16_rn(x.w));
        whi[i] = make_uint2(pb2(hx, hy), pb2(hz, hw));
        wlo[i] = make_uint2(pb2(x.x - hx, x.y - hy), pb2(x.z - hz, x.w - hw));
    }
}

// ---------------- init ----------------
__global__ void k_init(const float* __restrict__ q_att) {
    int t = threadIdx.x;
    if (t < BSZ) {
        g_amax[1][t] = (unsigned long long)(unsigned int)(~(unsigned int)SOS);
        g_amax[0][t] = 0ull;
    }
    for (int i = t; i < BSZ * HID; i += blockDim.x) {
        g_hbuf[0][i] = q_att[i];
        g_c[i] = 0.f;
    }
}

// ---------------- fused LSTM step ----------------
__global__ void k_lstm(const float* __restrict__ emb,
                       const float* __restrict__ W_ih,
                       const float* __restrict__ W_hh,
                       const float* __restrict__ b_ih,
                       const float* __restrict__ b_hh,
                       const int*   __restrict__ qix,
                       int par) {
    __shared__ float xh_s[32][66];
    __shared__ float w_s[32][36];
    __shared__ float gates_s[32][66];
    __shared__ int   sidx[BSZ];

    const float* hin  = g_hbuf[par];
    float*       hout = g_hbuf[par ^ 1];

    int t  = threadIdx.x;
    int tx = t & 7, ty = t >> 3;
    int j0 = blockIdx.x * 8;
    int r0 = tx * 4, m0 = ty * 2;

    if (t < BSZ) {
        unsigned long long key = g_amax[par ^ 1][t];
        sidx[t] = qix[~(unsigned int)(key & 0xFFFFFFFFull)];
    } else if (t < 2 * BSZ) {
        g_amax[par][t - BSZ] = 0ull;
    }

    float acc[4][2];
#pragma unroll
    for (int i = 0; i < 4; i++)
#pragma unroll
        for (int j = 0; j < 2; j++) acc[i][j] = 0.f;
    __syncthreads();

    for (int k0 = 0; k0 < EMB; k0 += 32) {
        for (int i = t; i < 2048; i += 256) {
            int kk = i & 31, m = i >> 5;
            int k = k0 + kk;
            float v = 0.f;
            if (k < EMB) v = fmaxf(emb[(long)sidx[m] * EMB + k], 0.f);
            xh_s[kk][m] = v;
        }
        for (int i = t; i < 1024; i += 256) {
            int kk = i & 31, r = i >> 5;
            int k = k0 + kk;
            int gr = (r >> 3) * HID + j0 + (r & 7);
            w_s[kk][r] = (k < EMB) ? W_ih[(long)gr * EMB + k] : 0.f;
        }
        __syncthreads();
#pragma unroll
        for (int kk = 0; kk < 32; kk++) {
            float4 w4 = *(const float4*)&w_s[kk][r0];
            float2 a2 = *(const float2*)&xh_s[kk][m0];
            float w[4] = {w4.x, w4.y, w4.z, w4.w};
            float a[2] = {a2.x, a2.y};
#pragma unroll
            for (int i = 0; i < 4; i++)
#pragma unroll
                for (int j = 0; j < 2; j++)
                    acc[i][j] = fmaf(w[i], a[j], acc[i][j]);
        }
        __syncthreads();
    }

    for (int k0 = 0; k0 < HID; k0 += 32) {
        for (int i = t; i < 2048; i += 256) {
            int kk = i & 31, m = i >> 5;
            xh_s[kk][m] = hin[m * HID + k0 + kk];
        }
        for (int i = t; i < 1024; i += 256) {
            int kk = i & 31, r = i >> 5;
            int gr = (r >> 3) * HID + j0 + (r & 7);
            w_s[kk][r] = W_hh[(long)gr * HID + k0 + kk];
        }
        __syncthreads();
#pragma unroll
        for (int kk = 0; kk < 32; kk++) {
            float4 w4 = *(const float4*)&w_s[kk][r0];
            float2 a2 = *(const float2*)&xh_s[kk][m0];
            float w[4] = {w4.x, w4.y, w4.z, w4.w};
            float a[2] = {a2.x, a2.y};
#pragma unroll
            for (int i = 0; i < 4; i++)
#pragma unroll
                for (int j = 0; j < 2; j++)
                    acc[i][j] = fmaf(w[i], a[j], acc[i][j]);
        }
        __syncthreads();
    }

#pragma unroll
    for (int i = 0; i < 4; i++) {
        int r  = r0 + i;
        int gr = (r >> 3) * HID + j0 + (r & 7);
        float bs = b_ih[gr] + b_hh[gr];
        gates_s[r][m0]     = acc[i][0] + bs;
        gates_s[r][m0 + 1] = acc[i][1] + bs;
    }
    __syncthreads();

    for (int p = t; p < 512; p += 256) {
        int u = p >> 6, m = p & 63;
        float gi = gates_s[u][m];
        float gf = gates_s[8 + u][m];
        float gg = gates_s[16 + u][m];
        float go = gates_s[24 + u][m];
        int ci = m * HID + j0 + u;
        float c  = g_c[ci];
        float si = 1.f / (1.f + expf(-gi));
        float sf = 1.f / (1.f + expf(-gf));
        float so = 1.f / (1.f + expf(-go));
        float nc = sf * c + si * tanhf(gg);
        float nh = so * tanhf(nc);
        g_c[ci]  = nc;
        hout[ci] = nh;
    }
}

// ---------------- logits: mma.sync bf16 3-term split GEMM ----------------
__device__ __forceinline__ void issueB(uint32_t bbase, int c, int v0) {
    int t = threadIdx.x;
#pragma unroll
    for (int n = 0; n < 8; n++) {
        int i = t + n * 256;
        int r = i >> 3, j = i & 7;
        size_t g = (size_t)(v0 + r) * HID + (size_t)c * 64 + j * 8;
        uint32_t so = sw128((uint32_t)(r * 128 + j * 16));
        CP_ASYNC16(bbase + so, g_Whi + g);
        CP_ASYNC16(bbase + 32768 + so, g_Wlo + g);
    }
}
__device__ __forceinline__ void ldgA(const float* h, int c, float4* av) {
    int t = threadIdx.x;
#pragma unroll
    for (int n = 0; n < 4; n++) {
        int i = t + n * 256;
        int r = i >> 4, q = i & 15;
        av[n] = *(const float4*)&h[r * HID + c * 64 + q * 4];
    }
}
__device__ __forceinline__ void stsA(uint32_t abase, const float4* av) {
    int t = threadIdx.x;
#pragma unroll
    for (int n = 0; n < 4; n++) {
        int i = t + n * 256;
        int r = i >> 4, q = i & 15;
        float4 x = av[n];
        float hx = __bfloat162float(__float2bfloat16_rn(x.x));
        float hy = __bfloat162float(__float2bfloat16_rn(x.y));
        float hz = __bfloat162float(__float2bfloat16_rn(x.z));
        float hw = __bfloat162float(__float2bfloat16_rn(x.w));
        uint32_t so = sw128((uint32_t)(r * 128 + q * 8));
        uint32_t* phi = (uint32_t*)(size_t)0;  // placeholder (unused)
        (void)phi;
        // hi then lo (generic smem pointers via st.shared through address arithmetic)
        asm volatile("st.shared.v2.b32 [%0], {%1, %2};" ::
                     "r"(abase + so), "r"(pb2(hx, hy)), "r"(pb2(hz, hw)) : "memory");
        asm volatile("st.shared.v2.b32 [%0], {%1, %2};" ::
                     "r"(abase + 8192 + so),
                     "r"(pb2(x.x - hx, x.y - hy)), "r"(pb2(x.z - hz, x.w - hw)) : "memory");
    }
}

__global__ void __launch_bounds__(256)
k_logits(const float* __restrict__ out_b, int hpar, int apar) {
    extern __shared__ __align__(16) char smem_raw[];
    uint32_t raw  = smem_u32(smem_raw);
    uint32_t base = (raw + 1023) & ~1023u;
    char* smb = smem_raw + (base - raw);

    const int t  = threadIdx.x;
    const int wid = t >> 5, ln = t & 31;
    const int v0 = blockIdx.x * 256;
    const float* h = g_hbuf[hpar];
    float* bias_sm = (float*)(smb + OFF_BIAS);

    bias_sm[t] = out_b[v0 + t];

    float acc[4][4][4];
#pragma unroll
    for (int a = 0; a < 4; a++)
#pragma unroll
        for (int b = 0; b < 4; b++)
#pragma unroll
            for (int cc = 0; cc < 4; cc++) acc[a][b][cc] = 0.f;

    // prime chunk 0
    issueB(base + OFF_B, 0, v0);
    CP_COMMIT();
    {
        float4 av[4];
        ldgA(h, 0, av);
        stsA(base, av);
    }

    // per-lane ldmatrix geometry
    const int ti = ln >> 3, li = ln & 7;
    const int aml = (ti & 1) * 8 + li, ak = ti >> 1;
    const int bnl = (ti >> 1) * 8 + li, bk = ti & 1;
    const int nbase = wid * 32;

    float4 av[4];
    for (int c = 0; c < NCHUNK; c++) {
        int b = c & 1;
        if (c < NCHUNK - 1) {
            issueB(base + OFF_B + (b ^ 1) * 65536, c + 1, v0);
            CP_COMMIT();
            ldgA(h, c + 1, av);
            CP_WAIT(1);
        } else {
            CP_WAIT(0);
        }
        __syncthreads();

        uint32_t Ahi = base + b * 16384, Alo = Ahi + 8192;
        uint32_t Bhi = base + OFF_B + b * 65536, Blo = Bhi + 32768;
#pragma unroll
        for (int ks = 0; ks < 4; ks++) {
            uint32_t ah[4][4], al[4][4], bh[4][2], bl[4][2];
#pragma unroll
            for (int mt = 0; mt < 4; mt++) {
                uint32_t off = sw128((uint32_t)((mt * 16 + aml) * 128 + ks * 32 + ak * 16));
                ldsm4(ah[mt], Ahi + off);
                ldsm4(al[mt], Alo + off);
            }
#pragma unroll
            for (int ng = 0; ng < 2; ng++) {
                uint32_t off = sw128((uint32_t)((nbase + ng * 16 + bnl) * 128 + ks * 32 + bk * 16));
                uint32_t r4[4];
                ldsm4(r4, Bhi + off);
                bh[ng * 2][0] = r4[0]; bh[ng * 2][1] = r4[1];
                bh[ng * 2 + 1][0] = r4[2]; bh[ng * 2 + 1][1] = r4[3];
                ldsm4(r4, Blo + off);
                bl[ng * 2][0] = r4[0]; bl[ng * 2][1] = r4[1];
                bl[ng * 2 + 1][0] = r4[2]; bl[ng * 2 + 1][1] = r4[3];
            }
#pragma unroll
            for (int mt = 0; mt < 4; mt++)
#pragma unroll
                for (int nt = 0; nt < 4; nt++) {
                    mma16816(acc[mt][nt], ah[mt], bh[nt]);
                    mma16816(acc[mt][nt], ah[mt], bl[nt]);
                    mma16816(acc[mt][nt], al[mt], bh[nt]);
                }
        }
        if (c < NCHUNK - 1) stsA(base + (b ^ 1) * 16384, av);
        __syncthreads();
    }

    // ---- epilogue: frags + bias -> dsm (aliases k-loop buffers) ----
    float* dsm = (float*)smb;
    const int g = ln >> 2, tg2 = (ln & 3) * 2;
#pragma unroll
    for (int mt = 0; mt < 4; mt++)
#pragma unroll
        for (int nt = 0; nt < 4; nt++) {
            int row0 = mt * 16 + g;
            int col  = nbase + nt * 8 + tg2;
            float b0 = bias_sm[col], b1 = bias_sm[col + 1];
            dsm[row0 * DP + col]           = acc[mt][nt][0] + b0;
            dsm[row0 * DP + col + 1]       = acc[mt][nt][1] + b1;
            dsm[(row0 + 8) * DP + col]     = acc[mt][nt][2] + b0;
            dsm[(row0 + 8) * DP + col + 1] = acc[mt][nt][3] + b1;
        }
    __syncthreads();

    // ---- row scan: warp w handles rows w*8..w*8+7 ----
#pragma unroll 1
    for (int i8 = 0; i8 < 8; i8++) {
        int r = wid * 8 + i8;
        float4 va = *(const float4*)&dsm[r * DP + ln * 8];
        float4 vb = *(const float4*)&dsm[r * DP + ln * 8 + 4];
        float vals[8] = {va.x, va.y, va.z, va.w, vb.x, vb.y, vb.z, vb.w};
        int c0 = v0 + ln * 8;

        float vm = vals[0]; int vi = c0;
#pragma unroll
        for (int j = 1; j < 8; j++)
            if (vals[j] > vm) { vm = vals[j]; vi = c0 + j; }

        unsigned long long key =
            ((unsigned long long)fmono(vm) << 32) |
            (unsigned int)(~(unsigned int)vi);
#pragma unroll
        for (int o = 16; o >= 1; o >>= 1) {
            unsigned long long other = __shfl_xor_sync(0xFFFFFFFFu, key, o);
            if (other > key) key = other;
        }
        float mrow = fmono_inv((unsigned int)(key >> 32));

        float s = 0.f;
#pragma unroll
        for (int j = 0; j < 8; j++) s += fexp(vals[j] - mrow);
#pragma unroll
        for (int o = 16; o >= 1; o >>= 1)
            s += __shfl_xor_sync(0xFFFFFFFFu, s, o);

        float* orow = g_scr + (size_t)r * VQ + c0;
        *(float4*)orow       = va;
        *(float4*)(orow + 4) = vb;

        if (ln == 0) {
            atomicMax(&g_amax[apar][r], key);
            g_part[r][blockIdx.x] = make_float2(mrow, s);
        }
    }
}

// ---------------- post: combine partials -> lse; write logp ----------------
__global__ void k_post(float* __restrict__ out, int step, int steps) {
    int b = blockIdx.x;
    int t = threadIdx.x;   // 256
    __shared__ float sm_[8], sx[8], s_lse;

    float2 p = (t < NBLK) ? g_part[b][t] : make_float2(-3.4e38f, 0.f);
    float m = p.x;
#pragma unroll
    for (int o = 16; o >= 1; o >>= 1)
        m = fmaxf(m, __shfl_xor_sync(0xFFFFFFFFu, m, o));
    if ((t & 31) == 0) sm_[t >> 5] = m;
    __syncthreads();
    float M = sm_[0];
#pragma unroll
    for (int i = 1; i < 8; i++) M = fmaxf(M, sm_[i]);

    float s = (t < NBLK) ? p.y * fexp(p.x - M) : 0.f;
#pragma unroll
    for (int o = 16; o >= 1; o >>= 1)
        s += __shfl_xor_sync(0xFFFFFFFFu, s, o);
    if ((t & 31) == 0) sx[t >> 5] = s;
    __syncthreads();
    if (t == 0) {
        float S = 0.f;
#pragma unroll
        for (int i = 0; i < 8; i++) S += sx[i];
        s_lse = M + logf(S);
    }
    __syncthreads();
    float lse = s_lse;

    const float4* src = (const float4*)(g_scr + (size_t)b * VQ);
    float4* dst = (float4*)(out + ((size_t)b * steps + step) * VQ);
    for (int i = t; i < VQ / 4; i += 256) {
        float4 x = src[i];
        x.x -= lse; x.y -= lse; x.z -= lse; x.w -= lse;
        dst[i] = x;
    }
}

// ---------------- launch ----------------
extern "C" void kernel_launch(void* const* d_in, const int* in_sizes, int n_in,
                              void* d_out, int out_size) {
    (void)in_sizes; (void)n_in;
    const float* q_att = (const float*)d_in[1];
    const float* emb   = (const float*)d_in[2];
    const float* W_ih  = (const float*)d_in[3];
    const float* W_hh  = (const float*)d_in[4];
    const float* b_ih  = (const float*)d_in[5];
    const float* b_hh  = (const float*)d_in[6];
    const float* out_W = (const float*)d_in[7];
    const float* out_b = (const float*)d_in[8];
    const int*   qix   = (const int*)d_in[9];

    int steps = out_size / (BSZ * VQ);  // 33

    cudaFuncSetAttribute(k_logits, cudaFuncAttributeMaxDynamicSharedMemorySize,
                         SMEM_REQ);

    k_prep<<<2048, 256>>>(out_W);
    k_init<<<1, 256>>>(q_att);
    for (int s = 0; s < steps; s++) {
        int par = s & 1;
        k_lstm<<<64, 256>>>(emb, W_ih, W_hh, b_ih, b_hh, qix, par);
        k_logits<<<NBLK, 256, SMEM_REQ>>>(out_b, par ^ 1, par);
        k_post<<<BSZ, 256>>>((float*)d_out, s, steps);
    }
}

// round 5
// speedup vs baseline: 1.7083x; 1.2011x over previous
#include <cuda_runtime.h>
#include <cuda_bf16.h>
#include <math.h>
#include <stdint.h>

#define BSZ 64
#define HID 512
#define EMB 300
#define VQ  32000
#define SOS 1
#define NBLK 125            // VQ / 256 tiles == CTA count
#define NCTA 125
#define NCHUNK 8            // K chunks of 64

// dynamic smem layout (relative to 1024-aligned base)
#define OFF_B    32768      // B tiles: 2 bufs x (hi 32K + lo 32K)
#define OFF_BIAS 163840     // 256 floats
#define OFF_RED  164864     // 16 floats reduction scratch
#define SMEM_REQ 166912
#define DP 264              // dsm row stride (floats)
// lstm-phase aliases (low region)
#define LS_XH 0
#define LS_W  8448
#define LS_G  13056
#define LS_IDX 21504

// ---------------- persistent device state ----------------
__device__ float g_hbuf[2][BSZ * HID];
__device__ float g_c[BSZ * HID];
__device__ unsigned long long g_amax[2][BSZ];
__device__ float2 g_part[BSZ][NBLK];
__device__ float g_scr[2][(size_t)BSZ * VQ];    // ping-pong raw logits
__device__ __nv_bfloat16 g_Whi[(size_t)VQ * HID];
__device__ __nv_bfloat16 g_Wlo[(size_t)VQ * HID];
__device__ unsigned int g_cnt, g_gen;

// ---------------- helpers ----------------
__device__ __forceinline__ unsigned int fmono(float f) {
    unsigned int u = __float_as_uint(f);
    return (u & 0x80000000u) ? ~u : (u | 0x80000000u);
}
__device__ __forceinline__ float fmono_inv(unsigned int u) {
    return (u & 0x80000000u) ? __uint_as_float(u & 0x7FFFFFFFu)
                             : __uint_as_float(~u);
}
__device__ __forceinline__ float fexp(float x) {
    x = fmaxf(x, -80.0f);
    float t = fmaf(x, 1.4426950408889634f, 12582912.0f);
    float i = t - 12582912.0f;
    float f = fmaf(x, 1.4426950408889634f, -i);
    float p = 1.3333558e-3f;
    p = fmaf(p, f, 9.6181291e-3f);
    p = fmaf(p, f, 5.5504110e-2f);
    p = fmaf(p, f, 2.4022651e-1f);
    p = fmaf(p, f, 6.9314718e-1f);
    p = fmaf(p, f, 1.0f);
    int ei = __float_as_int(t) - 0x4B400000;
    float sc = __int_as_float((ei + 127) << 23);
    return sc * p;
}
__device__ __forceinline__ uint32_t smem_u32(const void* p) {
    uint32_t a;
    asm("{ .reg .u64 t; cvta.to.shared.u64 t, %1; cvt.u32.u64 %0, t; }"
        : "=r"(a) : "l"(p));
    return a;
}
__device__ __forceinline__ uint32_t sw128(uint32_t o) { return o ^ ((o >> 3) & 0x70); }
__device__ __forceinline__ uint32_t pb2(float a, float b) {
    __nv_bfloat162 t = __floats2bfloat162_rn(a, b);
    return *reinterpret_cast<uint32_t*>(&t);
}
__device__ __forceinline__ unsigned int ld_acq(const unsigned int* p) {
    unsigned int v;
    asm volatile("ld.global.acquire.gpu.b32 %0, [%1];" : "=r"(v) : "l"(p) : "memory");
    return v;
}

// grid-wide sense barrier (all NCTA CTAs resident -> safe)
__device__ __forceinline__ void gsync() {
    __threadfence();
    __syncthreads();
    if (threadIdx.x == 0) {
        unsigned int gen = ld_acq(&g_gen);
        unsigned int old = atomicAdd(&g_cnt, 1u);
        if (old == NCTA - 1) {
            g_cnt = 0;
            __threadfence();
            atomicAdd(&g_gen, 1u);
        } else {
            unsigned int cur;
            do { __nanosleep(64); cur = ld_acq(&g_gen); } while (cur == gen);
        }
    }
    __syncthreads();
}

#define CP_ASYNC16(dst, src) \
    asm volatile("cp.async.cg.shared.global [%0], [%1], 16;" :: "r"(dst), "l"(src) : "memory")
#define CP_COMMIT() asm volatile("cp.async.commit_group;" ::: "memory")
#define CP_WAIT(n)  asm volatile("cp.async.wait_group %0;" :: "n"(n) : "memory")

__device__ __forceinline__ void ldsm4(uint32_t* r, uint32_t addr) {
    asm volatile("ldmatrix.sync.aligned.m8n8.x4.shared.b16 {%0,%1,%2,%3}, [%4];"
                 : "=r"(r[0]), "=r"(r[1]), "=r"(r[2]), "=r"(r[3]) : "r"(addr));
}
__device__ __forceinline__ void mma16816(float* d, const uint32_t* a, const uint32_t* b) {
    asm volatile(
        "mma.sync.aligned.m16n8k16.row.col.f32.bf16.bf16.f32 "
        "{%0,%1,%2,%3}, {%4,%5,%6,%7}, {%8,%9}, {%0,%1,%2,%3};"
        : "+f"(d[0]), "+f"(d[1]), "+f"(d[2]), "+f"(d[3])
        : "r"(a[0]), "r"(a[1]), "r"(a[2]), "r"(a[3]), "r"(b[0]), "r"(b[1]));
}

// ---------------- prep: split out_W into bf16 hi/lo ----------------
__global__ void k_prep(const float* __restrict__ W) {
    size_t n4 = (size_t)VQ * HID / 4;
    uint2* whi = (uint2*)g_Whi;
    uint2* wlo = (uint2*)g_Wlo;
    for (size_t i = (size_t)blockIdx.x * blockDim.x + threadIdx.x; i < n4;
         i += (size_t)gridDim.x * blockDim.x) {
        float4 x = ((const float4*)W)[i];
        float hx = __bfloat162float(__float2bfloat16_rn(x.x));
        float hy = __bfloat162float(__float2bfloat16_rn(x.y));
        float hz = __bfloat162float(__float2bfloat16_rn(x.z));
        float hw = __bfloat162float(__float2bfloat16_rn(x.w));
        whi[i] = make_uint2(pb2(hx, hy), pb2(hz, hw));
        wlo[i] = make_uint2(pb2(x.x - hx, x.y - hy), pb2(x.z - hz, x.w - hw));
    }
}

__global__ void k_init(const float* __restrict__ q_att) {
    int t = threadIdx.x;
    if (t < BSZ) {
        g_amax[1][t] = (unsigned long long)(unsigned int)(~(unsigned int)SOS);
        g_amax[0][t] = 0ull;
    }
    for (int i = t; i < BSZ * HID; i += blockDim.x) {
        g_hbuf[0][i] = q_att[i];
        g_c[i] = 0.f;
    }
}

// ---------------- phase A1: LSTM (CTAs 0-63) ----------------
__device__ void lstm_phase(char* smb,
                           const float* __restrict__ emb,
                           const float* __restrict__ W_ih,
                           const float* __restrict__ W_hh,
                           const float* __restrict__ b_ih,
                           const float* __restrict__ b_hh,
                           const int*   __restrict__ qix,
                           int par) {
    float (*xh_s)[66]    = (float(*)[66])(smb + LS_XH);
    float (*w_s)[36]     = (float(*)[36])(smb + LS_W);
    float (*gates_s)[66] = (float(*)[66])(smb + LS_G);
    int* sidx = (int*)(smb + LS_IDX);

    const float* hin  = g_hbuf[par];
    float*       hout = g_hbuf[par ^ 1];

    int t  = threadIdx.x;
    int tx = t & 7, ty = t >> 3;
    int j0 = blockIdx.x * 8;
    int r0 = tx * 4, m0 = ty * 2;

    if (t < BSZ) {
        unsigned long long key = __ldcg(&g_amax[par ^ 1][t]);
        sidx[t] = qix[~(unsigned int)(key & 0xFFFFFFFFull)];
    }
    if (blockIdx.x == 0 && t >= BSZ && t < 2 * BSZ)
        g_amax[par][t - BSZ] = 0ull;

    float acc[4][2];
#pragma unroll
    for (int i = 0; i < 4; i++)
#pragma unroll
        for (int j = 0; j < 2; j++) acc[i][j] = 0.f;
    __syncthreads();

    for (int k0 = 0; k0 < EMB; k0 += 32) {
        for (int i = t; i < 2048; i += 256) {
            int kk = i & 31, m = i >> 5;
            int k = k0 + kk;
            float v = 0.f;
            if (k < EMB) v = fmaxf(emb[(long)sidx[m] * EMB + k], 0.f);
            xh_s[kk][m] = v;
        }
        for (int i = t; i < 1024; i += 256) {
            int kk = i & 31, r = i >> 5;
            int k = k0 + kk;
            int gr = (r >> 3) * HID + j0 + (r & 7);
            w_s[kk][r] = (k < EMB) ? W_ih[(long)gr * EMB + k] : 0.f;
        }
        __syncthreads();
#pragma unroll
        for (int kk = 0; kk < 32; kk++) {
            float4 w4 = *(const float4*)&w_s[kk][r0];
            float2 a2 = *(const float2*)&xh_s[kk][m0];
            float w[4] = {w4.x, w4.y, w4.z, w4.w};
            float a[2] = {a2.x, a2.y};
#pragma unroll
            for (int i = 0; i < 4; i++)
#pragma unroll
                for (int j = 0; j < 2; j++)
                    acc[i][j] = fmaf(w[i], a[j], acc[i][j]);
        }
        __syncthreads();
    }

    for (int k0 = 0; k0 < HID; k0 += 32) {
        for (int i = t; i < 2048; i += 256) {
            int kk = i & 31, m = i >> 5;
            xh_s[kk][m] = __ldcg(&hin[m * HID + k0 + kk]);
        }
        for (int i = t; i < 1024; i += 256) {
            int kk = i & 31, r = i >> 5;
            int gr = (r >> 3) * HID + j0 + (r & 7);
            w_s[kk][r] = W_hh[(long)gr * HID + k0 + kk];
        }
        __syncthreads();
#pragma unroll
        for (int kk = 0; kk < 32; kk++) {
            float4 w4 = *(const float4*)&w_s[kk][r0];
            float2 a2 = *(const float2*)&xh_s[kk][m0];
            float w[4] = {w4.x, w4.y, w4.z, w4.w};
            float a[2] = {a2.x, a2.y};
#pragma unroll
            for (int i = 0; i < 4; i++)
#pragma unroll
                for (int j = 0; j < 2; j++)
                    acc[i][j] = fmaf(w[i], a[j], acc[i][j]);
        }
        __syncthreads();
    }

#pragma unroll
    for (int i = 0; i < 4; i++) {
        int r  = r0 + i;
        int gr = (r >> 3) * HID + j0 + (r & 7);
        float bs = b_ih[gr] + b_hh[gr];
        gates_s[r][m0]     = acc[i][0] + bs;
        gates_s[r][m0 + 1] = acc[i][1] + bs;
    }
    __syncthreads();

    for (int p = t; p < 512; p += 256) {
        int u = p >> 6, m = p & 63;
        float gi = gates_s[u][m];
        float gf = gates_s[8 + u][m];
        float gg = gates_s[16 + u][m];
        float go = gates_s[24 + u][m];
        int ci = m * HID + j0 + u;
        float c  = g_c[ci];
        float si = 1.f / (1.f + expf(-gi));
        float sf = 1.f / (1.f + expf(-gf));
        float so = 1.f / (1.f + expf(-go));
        float nc = sf * c + si * tanhf(gg);
        float nh = so * tanhf(nc);
        g_c[ci]  = nc;
        hout[ci] = nh;
    }
}

// ---------------- phase A2: finalize one row of a finished step ----------------
__device__ void row_finalize(char* smb, float* __restrict__ out,
                             int sprev, int steps, int r) {
    int t = threadIdx.x;
    float* red = (float*)(smb + OFF_RED);   // 16 floats
    int pp = sprev & 1;

    float2 p = (t < NBLK) ? __ldcg(&g_part[r][t]) : make_float2(-3.4e38f, 0.f);
    float m = p.x;
#pragma unroll
    for (int o = 16; o >= 1; o >>= 1)
        m = fmaxf(m, __shfl_xor_sync(0xFFFFFFFFu, m, o));
    if ((t & 31) == 0) red[t >> 5] = m;
    __syncthreads();
    float M = red[0];
#pragma unroll
    for (int i = 1; i < 8; i++) M = fmaxf(M, red[i]);

    float s = (t < NBLK) ? p.y * fexp(p.x - M) : 0.f;
#pragma unroll
    for (int o = 16; o >= 1; o >>= 1)
        s += __shfl_xor_sync(0xFFFFFFFFu, s, o);
    __syncthreads();
    if ((t & 31) == 0) red[8 + (t >> 5)] = s;
    __syncthreads();
    float S = 0.f;
#pragma unroll
    for (int i = 0; i < 8; i++) S += red[8 + i];
    float lse = M + logf(S);

    const float4* src = (const float4*)(g_scr[pp] + (size_t)r * VQ);
    float4* dst = (float4*)(out + ((size_t)r * steps + sprev) * VQ);
    for (int i = t; i < VQ / 4; i += 256) {
        float4 x = __ldcg(&src[i]);
        x.x -= lse; x.y -= lse; x.z -= lse; x.w -= lse;
        dst[i] = x;
    }
    __syncthreads();
}

// ---------------- phase B: logits GEMM + fused epilogue ----------------
__device__ __forceinline__ void issueB(uint32_t bbase, int c, int v0) {
    int t = threadIdx.x;
#pragma unroll
    for (int n = 0; n < 8; n++) {
        int i = t + n * 256;
        int r = i >> 3, j = i & 7;
        size_t g = (size_t)(v0 + r) * HID + (size_t)c * 64 + j * 8;
        uint32_t so = sw128((uint32_t)(r * 128 + j * 16));
        CP_ASYNC16(bbase + so, g_Whi + g);
        CP_ASYNC16(bbase + 32768 + so, g_Wlo + g);
    }
}
__device__ __forceinline__ void ldgA(const float* h, int c, float4* av) {
    int t = threadIdx.x;
#pragma unroll
    for (int n = 0; n < 4; n++) {
        int i = t + n * 256;
        int r = i >> 4, q = i & 15;
        av[n] = __ldcg((const float4*)&h[r * HID + c * 64 + q * 4]);
    }
}
__device__ __forceinline__ void stsA(uint32_t abase, const float4* av) {
    int t = threadIdx.x;
#pragma unroll
    for (int n = 0; n < 4; n++) {
        int i = t + n * 256;
        int r = i >> 4, q = i & 15;
        float4 x = av[n];
        float hx = __bfloat162float(__float2bfloat16_rn(x.x));
        float hy = __bfloat162float(__float2bfloat16_rn(x.y));
        float hz = __bfloat162float(__float2bfloat16_rn(x.z));
        float hw = __bfloat162float(__float2bfloat16_rn(x.w));
        uint32_t so = sw128((uint32_t)(r * 128 + q * 8));
        asm volatile("st.shared.v2.b32 [%0], {%1, %2};" ::
                     "r"(abase + so), "r"(pb2(hx, hy)), "r"(pb2(hz, hw)) : "memory");
        asm volatile("st.shared.v2.b32 [%0], {%1, %2};" ::
                     "r"(abase + 8192 + so),
                     "r"(pb2(x.x - hx, x.y - hy)), "r"(pb2(x.z - hz, x.w - hw)) : "memory");
    }
}

__device__ void logits_phase(char* smb, uint32_t base, int par) {
    const int t  = threadIdx.x;
    const int wid = t >> 5, ln = t & 31;
    const int v0 = blockIdx.x * 256;
    const float* h = g_hbuf[par ^ 1];
    float* bias_sm = (float*)(smb + OFF_BIAS);

    float acc[4][4][4];
#pragma unroll
    for (int a = 0; a < 4; a++)
#pragma unroll
        for (int b = 0; b < 4; b++)
#pragma unroll
            for (int cc = 0; cc < 4; cc++) acc[a][b][cc] = 0.f;

    issueB(base + OFF_B, 0, v0);
    CP_COMMIT();
    {
        float4 av[4];
        ldgA(h, 0, av);
        stsA(base, av);
    }

    const int ti = ln >> 3, li = ln & 7;
    const int aml = (ti & 1) * 8 + li, ak = ti >> 1;
    const int bnl = (ti >> 1) * 8 + li, bk = ti & 1;
    const int nbase = wid * 32;

    float4 av[4];
    for (int c = 0; c < NCHUNK; c++) {
        int b = c & 1;
        if (c < NCHUNK - 1) {
            issueB(base + OFF_B + (b ^ 1) * 65536, c + 1, v0);
            CP_COMMIT();
            ldgA(h, c + 1, av);
            CP_WAIT(1);
        } else {
            CP_WAIT(0);
        }
        __syncthreads();

        uint32_t Ahi = base + b * 16384, Alo = Ahi + 8192;
        uint32_t Bhi = base + OFF_B + b * 65536, Blo = Bhi + 32768;
#pragma unroll
        for (int ks = 0; ks < 4; ks++) {
            uint32_t ah[4][4], al[4][4], bh[4][2], bl[4][2];
#pragma unroll
            for (int mt = 0; mt < 4; mt++) {
                uint32_t off = sw128((uint32_t)((mt * 16 + aml) * 128 + ks * 32 + ak * 16));
                ldsm4(ah[mt], Ahi + off);
                ldsm4(al[mt], Alo + off);
            }
#pragma unroll
            for (int ng = 0; ng < 2; ng++) {
                uint32_t off = sw128((uint32_t)((nbase + ng * 16 + bnl) * 128 + ks * 32 + bk * 16));
                uint32_t r4[4];
                ldsm4(r4, Bhi + off);
                bh[ng * 2][0] = r4[0]; bh[ng * 2][1] = r4[1];
                bh[ng * 2 + 1][0] = r4[2]; bh[ng * 2 + 1][1] = r4[3];
                ldsm4(r4, Blo + off);
                bl[ng * 2][0] = r4[0]; bl[ng * 2][1] = r4[1];
                bl[ng * 2 + 1][0] = r4[2]; bl[ng * 2 + 1][1] = r4[3];
            }
#pragma unroll
            for (int mt = 0; mt < 4; mt++)
#pragma unroll
                for (int nt = 0; nt < 4; nt++) {
                    mma16816(acc[mt][nt], ah[mt], bh[nt]);
                    mma16816(acc[mt][nt], ah[mt], bl[nt]);
                    mma16816(acc[mt][nt], al[mt], bh[nt]);
                }
        }
        if (c < NCHUNK - 1) stsA(base + (b ^ 1) * 16384, av);
        __syncthreads();
    }

    // epilogue: frags + bias -> dsm
    float* dsm = (float*)smb;
    const int g = ln >> 2, tg2 = (ln & 3) * 2;
#pragma unroll
    for (int mt = 0; mt < 4; mt++)
#pragma unroll
        for (int nt = 0; nt < 4; nt++) {
            int row0 = mt * 16 + g;
            int col  = nbase + nt * 8 + tg2;
            float b0 = bias_sm[col], b1 = bias_sm[col + 1];
            dsm[row0 * DP + col]           = acc[mt][nt][0] + b0;
            dsm[row0 * DP + col + 1]       = acc[mt][nt][1] + b1;
            dsm[(row0 + 8) * DP + col]     = acc[mt][nt][2] + b0;
            dsm[(row0 + 8) * DP + col + 1] = acc[mt][nt][3] + b1;
        }
    __syncthreads();

    // row scan: warp w -> rows w*8..w*8+7
    float* scr = g_scr[par];
#pragma unroll 1
    for (int i8 = 0; i8 < 8; i8++) {
        int r = wid * 8 + i8;
        float4 va = *(const float4*)&dsm[r * DP + ln * 8];
        float4 vb = *(const float4*)&dsm[r * DP + ln * 8 + 4];
        float vals[8] = {va.x, va.y, va.z, va.w, vb.x, vb.y, vb.z, vb.w};
        int c0 = v0 + ln * 8;

        float vm = vals[0]; int vi = c0;
#pragma unroll
        for (int j = 1; j < 8; j++)
            if (vals[j] > vm) { vm = vals[j]; vi = c0 + j; }

        unsigned long long key =
            ((unsigned long long)fmono(vm) << 32) |
            (unsigned int)(~(unsigned int)vi);
#pragma unroll
        for (int o = 16; o >= 1; o >>= 1) {
            unsigned long long other = __shfl_xor_sync(0xFFFFFFFFu, key, o);
            if (other > key) key = other;
        }
        float mrow = fmono_inv((unsigned int)(key >> 32));

        float s = 0.f;
#pragma unroll
        for (int j = 0; j < 8; j++) s += fexp(vals[j] - mrow);
#pragma unroll
        for (int o = 16; o >= 1; o >>= 1)
            s += __shfl_xor_sync(0xFFFFFFFFu, s, o);

        float* orow = scr + (size_t)r * VQ + c0;
        *(float4*)orow       = va;
        *(float4*)(orow + 4) = vb;

        if (ln == 0) {
            atomicMax(&g_amax[par][r], key);
            g_part[r][blockIdx.x] = make_float2(mrow, s);
        }
    }
    __syncthreads();
}

// ---------------- the persistent decode kernel ----------------
__global__ void __launch_bounds__(256, 1)
k_main(const float* __restrict__ emb,
       const float* __restrict__ W_ih,
       const float* __restrict__ W_hh,
       const float* __restrict__ b_ih,
       const float* __restrict__ b_hh,
       const float* __restrict__ out_b,
       const int*   __restrict__ qix,
       float* __restrict__ out, int steps) {
    extern __shared__ __align__(16) char smem_raw[];
    uint32_t raw  = smem_u32(smem_raw);
    uint32_t base = (raw + 1023) & ~1023u;
    char* smb = smem_raw + (base - raw);

    // bias for this CTA's fixed vocab tile, loaded once
    ((float*)(smb + OFF_BIAS))[threadIdx.x] = out_b[blockIdx.x * 256 + threadIdx.x];

    for (int s = 0; s < steps; s++) {
        int par = s & 1;

        // phase A: lstm (CTAs 0-63) || finalize prev step (CTAs 64-124)
        if (blockIdx.x < 64) {
            lstm_phase(smb, emb, W_ih, W_hh, b_ih, b_hh, qix, par);
        } else if (s > 0) {
            int j = blockIdx.x - 64;                  // 0..60
            int rlo = (j * BSZ) / (NCTA - 64);
            int rhi = ((j + 1) * BSZ) / (NCTA - 64);
            for (int r = rlo; r < rhi; r++)
                row_finalize(smb, out, s - 1, steps, r);
        }
        gsync();

        // phase B: logits GEMM + epilogue (all CTAs)
        logits_phase(smb, base, par);
        gsync();
    }

    // finalize last step (rows spread over all CTAs)
    {
        int j = blockIdx.x;
        int rlo = (j * BSZ) / NCTA;
        int rhi = ((j + 1) * BSZ) / NCTA;
        for (int r = rlo; r < rhi; r++)
            row_finalize(smb, out, steps - 1, steps, r);
    }
}

// ---------------- launch ----------------
extern "C" void kernel_launch(void* const* d_in, const int* in_sizes, int n_in,
                              void* d_out, int out_size) {
    (void)in_sizes; (void)n_in;
    const float* q_att = (const float*)d_in[1];
    const float* emb   = (const float*)d_in[2];
    const float* W_ih  = (const float*)d_in[3];
    const float* W_hh  = (const float*)d_in[4];
    const float* b_ih  = (const float*)d_in[5];
    const float* b_hh  = (const float*)d_in[6];
    const float* out_W = (const float*)d_in[7];
    const float* out_b = (const float*)d_in[8];
    const int*   qix   = (const int*)d_in[9];

    int steps = out_size / (BSZ * VQ);  // 33

    cudaFuncSetAttribute(k_main, cudaFuncAttributeMaxDynamicSharedMemorySize,
                         SMEM_REQ);

    k_prep<<<2048, 256>>>(out_W);
    k_init<<<1, 256>>>(q_att);
    k_main<<<NCTA, 256, SMEM_REQ>>>(emb, W_ih, W_hh, b_ih, b_hh, out_b, qix,
                                    (float*)d_out, steps);
}

// round 6
// speedup vs baseline: 1.9021x; 1.1134x over previous
#include <cuda_runtime.h>
#include <cuda_bf16.h>
#include <math.h>
#include <stdint.h>

#define BSZ 64
#define HID 512
#define EMB 300
#define VQ  32000
#define SOS 1
#define NBLK 125
#define NCTA 125
#define NCHUNK 8

// dynamic smem layout (relative to 1024-aligned base)
#define OFF_B    32768      // B tiles: 2 bufs x (hi 32K + lo 32K)
#define OFF_BIAS 163840     // 256 floats
#define OFF_RED  164864     // reduction scratch
#define SMEM_REQ 166912
#define DP 264
// lstm-phase aliases (low region, < 17 KB)
#define LS_XH  0            // float[32][68]  = 8704 B
#define LS_W   8704         // float[32][20]  = 2560 B
#define LS_G   11264        // float[20][68]  = 5440 B
#define LS_BS  16704        // float[20]
#define LS_IDX 16800        // int[64]

// ---------------- persistent device state ----------------
__device__ float g_hbuf[2][BSZ * HID];
__device__ float g_c[BSZ * HID];
__device__ unsigned long long g_amax[2][BSZ];
__device__ float2 g_part[2][BSZ][NBLK];
__device__ float g_scr[2][(size_t)BSZ * VQ];
__device__ __nv_bfloat16 g_Whi[(size_t)VQ * HID];
__device__ __nv_bfloat16 g_Wlo[(size_t)VQ * HID];
__device__ unsigned int g_cnt, g_gen;

// ---------------- helpers ----------------
__device__ __forceinline__ unsigned int fmono(float f) {
    unsigned int u = __float_as_uint(f);
    return (u & 0x80000000u) ? ~u : (u | 0x80000000u);
}
__device__ __forceinline__ float fmono_inv(unsigned int u) {
    return (u & 0x80000000u) ? __uint_as_float(u & 0x7FFFFFFFu)
                             : __uint_as_float(~u);
}
__device__ __forceinline__ float fexp(float x) {
    x = fmaxf(x, -80.0f);
    float t = fmaf(x, 1.4426950408889634f, 12582912.0f);
    float i = t - 12582912.0f;
    float f = fmaf(x, 1.4426950408889634f, -i);
    float p = 1.3333558e-3f;
    p = fmaf(p, f, 9.6181291e-3f);
    p = fmaf(p, f, 5.5504110e-2f);
    p = fmaf(p, f, 2.4022651e-1f);
    p = fmaf(p, f, 6.9314718e-1f);
    p = fmaf(p, f, 1.0f);
    int ei = __float_as_int(t) - 0x4B400000;
    float sc = __int_as_float((ei + 127) << 23);
    return sc * p;
}
__device__ __forceinline__ uint32_t smem_u32(const void* p) {
    uint32_t a;
    asm("{ .reg .u64 t; cvta.to.shared.u64 t, %1; cvt.u32.u64 %0, t; }"
        : "=r"(a) : "l"(p));
    return a;
}
__device__ __forceinline__ uint32_t sw128(uint32_t o) { return o ^ ((o >> 3) & 0x70); }
__device__ __forceinline__ uint32_t pb2(float a, float b) {
    __nv_bfloat162 t = __floats2bfloat162_rn(a, b);
    return *reinterpret_cast<uint32_t*>(&t);
}
__device__ __forceinline__ unsigned int ld_acq(const unsigned int* p) {
    unsigned int v;
    asm volatile("ld.global.acquire.gpu.b32 %0, [%1];" : "=r"(v) : "l"(p) : "memory");
    return v;
}

__device__ __forceinline__ void gsync() {
    __threadfence();
    __syncthreads();
    if (threadIdx.x == 0) {
        unsigned int gen = ld_acq(&g_gen);
        unsigned int old = atomicAdd(&g_cnt, 1u);
        if (old == NCTA - 1) {
            g_cnt = 0;
            __threadfence();
            atomicAdd(&g_gen, 1u);
        } else {
            unsigned int cur;
            do { __nanosleep(32); cur = ld_acq(&g_gen); } while (cur == gen);
        }
    }
    __syncthreads();
}

#define CP_ASYNC16(dst, src) \
    asm volatile("cp.async.cg.shared.global [%0], [%1], 16;" :: "r"(dst), "l"(src) : "memory")
#define CP_COMMIT() asm volatile("cp.async.commit_group;" ::: "memory")
#define CP_WAIT(n)  asm volatile("cp.async.wait_group %0;" :: "n"(n) : "memory")

__device__ __forceinline__ void ldsm4(uint32_t* r, uint32_t addr) {
    asm volatile("ldmatrix.sync.aligned.m8n8.x4.shared.b16 {%0,%1,%2,%3}, [%4];"
                 : "=r"(r[0]), "=r"(r[1]), "=r"(r[2]), "=r"(r[3]) : "r"(addr));
}
__device__ __forceinline__ void mma16816(float* d, const uint32_t* a, const uint32_t* b) {
    asm volatile(
        "mma.sync.aligned.m16n8k16.row.col.f32.bf16.bf16.f32 "
        "{%0,%1,%2,%3}, {%4,%5,%6,%7}, {%8,%9}, {%0,%1,%2,%3};"
        : "+f"(d[0]), "+f"(d[1]), "+f"(d[2]), "+f"(d[3])
        : "r"(a[0]), "r"(a[1]), "r"(a[2]), "r"(a[3]), "r"(b[0]), "r"(b[1]));
}

// ---------------- prep / init ----------------
__global__ void k_prep(const float* __restrict__ W) {
    size_t n4 = (size_t)VQ * HID / 4;
    uint2* whi = (uint2*)g_Whi;
    uint2* wlo = (uint2*)g_Wlo;
    for (size_t i = (size_t)blockIdx.x * blockDim.x + threadIdx.x; i < n4;
         i += (size_t)gridDim.x * blockDim.x) {
        float4 x = ((const float4*)W)[i];
        float hx = __bfloat162float(__float2bfloat16_rn(x.x));
        float hy = __bfloat162float(__float2bfloat16_rn(x.y));
        float hz = __bfloat162float(__float2bfloat16_rn(x.z));
        float hw = __bfloat162float(__float2bfloat16_rn(x.w));
        whi[i] = make_uint2(pb2(hx, hy), pb2(hz, hw));
        wlo[i] = make_uint2(pb2(x.x - hx, x.y - hy), pb2(x.z - hz, x.w - hw));
    }
}

__global__ void k_init(const float* __restrict__ q_att) {
    int t = threadIdx.x;
    if (t < BSZ) {
        g_amax[1][t] = (unsigned long long)(unsigned int)(~(unsigned int)SOS);
        g_amax[0][t] = 0ull;
    }
    for (int i = t; i < BSZ * HID; i += blockDim.x) {
        g_hbuf[0][i] = q_att[i];
        g_c[i] = 0.f;
    }
}

// ---------------- phase A1: LSTM on all 125 CTAs ----------------
// CTA i owns units {i, 125+i, 250+i, 375+i} (+ 500+i for i<12).
__device__ void lstm_phase(char* smb,
                           const float* __restrict__ emb,
                           const float* __restrict__ W_ih,
                           const float* __restrict__ W_hh,
                           const float* __restrict__ b_ih,
                           const float* __restrict__ b_hh,
                           const int*   __restrict__ qix,
                           int par) {
    float (*xh)[68] = (float(*)[68])(smb + LS_XH);
    float (*ws)[20] = (float(*)[20])(smb + LS_W);
    float (*gs)[68] = (float(*)[68])(smb + LS_G);
    float* bs  = (float*)(smb + LS_BS);
    int* sidx  = (int*)(smb + LS_IDX);

    const int t  = threadIdx.x;
    const int i0 = blockIdx.x;
    const int NU = (i0 < 12) ? 5 : 4;
    const int NR = NU * 4;
    int u[5];
    u[0] = i0; u[1] = 125 + i0; u[2] = 250 + i0; u[3] = 375 + i0; u[4] = 500 + i0;

    const float* hin  = g_hbuf[par];
    float*       hout = g_hbuf[par ^ 1];

    if (t < BSZ) {
        unsigned long long key = __ldcg(&g_amax[par ^ 1][t]);
        sidx[t] = qix[~(unsigned int)(key & 0xFFFFFFFFull)];
    }
    if (i0 == 0 && t >= 64 && t < 128) g_amax[par][t - 64] = 0ull;
    if (t < NR) {
        int gr = (t & 3) * 512 + u[t >> 2];
        bs[t] = b_ih[gr] + b_hh[gr];
    }

    const int tx = t & 15, ty = t >> 4;
    const int m0 = ty * 4;
    const bool xt = (NR == 20) && (tx < 4);
    float acc[4]  = {0.f, 0.f, 0.f, 0.f};
    float acc2[4] = {0.f, 0.f, 0.f, 0.f};
    __syncthreads();

    // phase 1: x = relu(emb[idx]) vs W_ih, K = 300 (ragged)
    for (int k0 = 0; k0 < 320; k0 += 32) {
        for (int i = t; i < 2048; i += 256) {
            int kk = i & 31, m = i >> 5;
            int k = k0 + kk;
            float v = 0.f;
            if (k < EMB) v = fmaxf(__ldg(&emb[(size_t)sidx[m] * EMB + k]), 0.f);
            xh[kk][m] = v;
        }
        for (int i = t; i < NR * 32; i += 256) {
            int r = i >> 5, kk = i & 31;
            int k = k0 + kk;
            int gr = (r & 3) * 512 + u[r >> 2];
            ws[kk][r] = (k < EMB) ? W_ih[(size_t)gr * EMB + k] : 0.f;
        }
        __syncthreads();
#pragma unroll
        for (int kk = 0; kk < 32; kk++) {
            float4 a = *(const float4*)&xh[kk][m0];
            float w = ws[kk][tx];
            acc[0] = fmaf(w, a.x, acc[0]);
            acc[1] = fmaf(w, a.y, acc[1]);
            acc[2] = fmaf(w, a.z, acc[2]);
            acc[3] = fmaf(w, a.w, acc[3]);
            if (xt) {
                float w2 = ws[kk][16 + tx];
                acc2[0] = fmaf(w2, a.x, acc2[0]);
                acc2[1] = fmaf(w2, a.y, acc2[1]);
                acc2[2] = fmaf(w2, a.z, acc2[2]);
                acc2[3] = fmaf(w2, a.w, acc2[3]);
            }
        }
        __syncthreads();
    }

    // phase 2: h vs W_hh, K = 512
    for (int k0 = 0; k0 < HID; k0 += 32) {
        for (int i = t; i < 2048; i += 256) {
            int kk = i & 31, m = i >> 5;
            xh[kk][m] = __ldcg(&hin[m * HID + k0 + kk]);
        }
        for (int i = t; i < NR * 32; i += 256) {
            int r = i >> 5, kk = i & 31;
            int gr = (r & 3) * 512 + u[r >> 2];
            ws[kk][r] = W_hh[(size_t)gr * HID + k0 + kk];
        }
        __syncthreads();
#pragma unroll
        for (int kk = 0; kk < 32; kk++) {
            float4 a = *(const float4*)&xh[kk][m0];
            float w = ws[kk][tx];
            acc[0] = fmaf(w, a.x, acc[0]);
            acc[1] = fmaf(w, a.y, acc[1]);
            acc[2] = fmaf(w, a.z, acc[2]);
            acc[3] = fmaf(w, a.w, acc[3]);
            if (xt) {
                float w2 = ws[kk][16 + tx];
                acc2[0] = fmaf(w2, a.x, acc2[0]);
                acc2[1] = fmaf(w2, a.y, acc2[1]);
                acc2[2] = fmaf(w2, a.z, acc2[2]);
                acc2[3] = fmaf(w2, a.w, acc2[3]);
            }
        }
        __syncthreads();
    }

    // gates -> smem (+bias)
    {
        float bb = bs[tx];
        gs[tx][m0]     = acc[0] + bb;
        gs[tx][m0 + 1] = acc[1] + bb;
        gs[tx][m0 + 2] = acc[2] + bb;
        gs[tx][m0 + 3] = acc[3] + bb;
        if (xt) {
            float b2 = bs[16 + tx];
            gs[16 + tx][m0]     = acc2[0] + b2;
            gs[16 + tx][m0 + 1] = acc2[1] + b2;
            gs[16 + tx][m0 + 2] = acc2[2] + b2;
            gs[16 + tx][m0 + 3] = acc2[3] + b2;
        }
    }
    __syncthreads();

    // cell update
    for (int p = t; p < NU * 64; p += 256) {
        int uu = p >> 6, m = p & 63;
        float gi = gs[uu * 4 + 0][m];
        float gf = gs[uu * 4 + 1][m];
        float gg = gs[uu * 4 + 2][m];
        float go = gs[uu * 4 + 3][m];
        int ci = m * HID + u[uu];
        float c  = __ldcg(&g_c[ci]);
        float si = 1.f / (1.f + expf(-gi));
        float sf = 1.f / (1.f + expf(-gf));
        float so = 1.f / (1.f + expf(-go));
        float nc = sf * c + si * tanhf(gg);
        float nh = so * tanhf(nc);
        g_c[ci]  = nc;
        hout[ci] = nh;
    }
    __syncthreads();
}

// ---------------- phase A2: finalize one half-row of a finished step ----------------
__device__ void finalize_half(char* smb, float* __restrict__ out,
                              int sprev, int steps, int hr) {
    int r = hr >> 1, half = hr & 1;
    int pp = sprev & 1;
    int t = threadIdx.x;
    float* red = (float*)(smb + OFF_RED);
    __syncthreads();

    float2 p = (t < NBLK) ? __ldcg(&g_part[pp][r][t]) : make_float2(-3.4e38f, 0.f);
    float m = p.x;
#pragma unroll
    for (int o = 16; o >= 1; o >>= 1)
        m = fmaxf(m, __shfl_xor_sync(0xFFFFFFFFu, m, o));
    if ((t & 31) == 0) red[t >> 5] = m;
    __syncthreads();
    float M = red[0];
#pragma unroll
    for (int i = 1; i < 8; i++) M = fmaxf(M, red[i]);

    float s = (t < NBLK) ? p.y * fexp(p.x - M) : 0.f;
#pragma unroll
    for (int o = 16; o >= 1; o >>= 1)
        s += __shfl_xor_sync(0xFFFFFFFFu, s, o);
    __syncthreads();
    if ((t & 31) == 0) red[8 + (t >> 5)] = s;
    __syncthreads();
    float S = 0.f;
#pragma unroll
    for (int i = 0; i < 8; i++) S += red[8 + i];
    float lse = M + logf(S);

    const float4* src = (const float4*)(g_scr[pp] + (size_t)r * VQ) + half * (VQ / 8);
    float4* dst = (float4*)(out + ((size_t)r * steps + sprev) * VQ) + half * (VQ / 8);
    for (int i = t; i < VQ / 8; i += 256) {
        float4 x = __ldcg(&src[i]);
        x.x -= lse; x.y -= lse; x.z -= lse; x.w -= lse;
        dst[i] = x;
    }
    __syncthreads();
}

// ---------------- phase B: logits GEMM + fused epilogue ----------------
__device__ __forceinline__ void issueB(uint32_t bbase, int c, int v0) {
    int t = threadIdx.x;
#pragma unroll
    for (int n = 0; n < 8; n++) {
        int i = t + n * 256;
        int r = i >> 3, j = i & 7;
        size_t g = (size_t)(v0 + r) * HID + (size_t)c * 64 + j * 8;
        uint32_t so = sw128((uint32_t)(r * 128 + j * 16));
        CP_ASYNC16(bbase + so, g_Whi + g);
        CP_ASYNC16(bbase + 32768 + so, g_Wlo + g);
    }
}
__device__ __forceinline__ void ldgA(const float* h, int c, float4* av) {
    int t = threadIdx.x;
#pragma unroll
    for (int n = 0; n < 4; n++) {
        int i = t + n * 256;
        int r = i >> 4, q = i & 15;
        av[n] = __ldcg((const float4*)&h[r * HID + c * 64 + q * 4]);
    }
}
__device__ __forceinline__ void stsA(uint32_t abase, const float4* av) {
    int t = threadIdx.x;
#pragma unroll
    for (int n = 0; n < 4; n++) {
        int i = t + n * 256;
        int r = i >> 4, q = i & 15;
        float4 x = av[n];
        float hx = __bfloat162float(__float2bfloat16_rn(x.x));
        float hy = __bfloat162float(__float2bfloat16_rn(x.y));
        float hz = __bfloat162float(__float2bfloat16_rn(x.z));
        float hw = __bfloat162float(__float2bfloat16_rn(x.w));
        uint32_t so = sw128((uint32_t)(r * 128 + q * 8));
        asm volatile("st.shared.v2.b32 [%0], {%1, %2};" ::
                     "r"(abase + so), "r"(pb2(hx, hy)), "r"(pb2(hz, hw)) : "memory");
        asm volatile("st.shared.v2.b32 [%0], {%1, %2};" ::
                     "r"(abase + 8192 + so),
                     "r"(pb2(x.x - hx, x.y - hy)), "r"(pb2(x.z - hz, x.w - hw)) : "memory");
    }
}

__device__ void logits_phase(char* smb, uint32_t base, int par) {
    const int t  = threadIdx.x;
    const int wid = t >> 5, ln = t & 31;
    const int v0 = blockIdx.x * 256;
    const float* h = g_hbuf[par ^ 1];
    float* bias_sm = (float*)(smb + OFF_BIAS);

    float acc[4][4][4];
#pragma unroll
    for (int a = 0; a < 4; a++)
#pragma unroll
        for (int b = 0; b < 4; b++)
#pragma unroll
            for (int cc = 0; cc < 4; cc++) acc[a][b][cc] = 0.f;

    issueB(base + OFF_B, 0, v0);
    CP_COMMIT();
    {
        float4 av[4];
        ldgA(h, 0, av);
        stsA(base, av);
    }

    const int ti = ln >> 3, li = ln & 7;
    const int aml = (ti & 1) * 8 + li, ak = ti >> 1;
    const int bnl = (ti >> 1) * 8 + li, bk = ti & 1;
    const int nbase = wid * 32;

    float4 av[4];
    for (int c = 0; c < NCHUNK; c++) {
        int b = c & 1;
        if (c < NCHUNK - 1) {
            issueB(base + OFF_B + (b ^ 1) * 65536, c + 1, v0);
            CP_COMMIT();
            ldgA(h, c + 1, av);
            CP_WAIT(1);
        } else {
            CP_WAIT(0);
        }
        __syncthreads();

        uint32_t Ahi = base + b * 16384, Alo = Ahi + 8192;
        uint32_t Bhi = base + OFF_B + b * 65536, Blo = Bhi + 32768;
#pragma unroll
        for (int ks = 0; ks < 4; ks++) {
            uint32_t ah[4][4], al[4][4], bh[4][2], bl[4][2];
#pragma unroll
            for (int mt = 0; mt < 4; mt++) {
                uint32_t off = sw128((uint32_t)((mt * 16 + aml) * 128 + ks * 32 + ak * 16));
                ldsm4(ah[mt], Ahi + off);
                ldsm4(al[mt], Alo + off);
            }
#pragma unroll
            for (int ng = 0; ng < 2; ng++) {
                uint32_t off = sw128((uint32_t)((nbase + ng * 16 + bnl) * 128 + ks * 32 + bk * 16));
                uint32_t r4[4];
                ldsm4(r4, Bhi + off);
                bh[ng * 2][0] = r4[0]; bh[ng * 2][1] = r4[1];
                bh[ng * 2 + 1][0] = r4[2]; bh[ng * 2 + 1][1] = r4[3];
                ldsm4(r4, Blo + off);
                bl[ng * 2][0] = r4[0]; bl[ng * 2][1] = r4[1];
                bl[ng * 2 + 1][0] = r4[2]; bl[ng * 2 + 1][1] = r4[3];
            }
#pragma unroll
            for (int mt = 0; mt < 4; mt++)
#pragma unroll
                for (int nt = 0; nt < 4; nt++) {
                    mma16816(acc[mt][nt], ah[mt], bh[nt]);
                    mma16816(acc[mt][nt], ah[mt], bl[nt]);
                    mma16816(acc[mt][nt], al[mt], bh[nt]);
                }
        }
        if (c < NCHUNK - 1) stsA(base + (b ^ 1) * 16384, av);
        __syncthreads();
    }

    float* dsm = (float*)smb;
    const int g = ln >> 2, tg2 = (ln & 3) * 2;
#pragma unroll
    for (int mt = 0; mt < 4; mt++)
#pragma unroll
        for (int nt = 0; nt < 4; nt++) {
            int row0 = mt * 16 + g;
            int col  = nbase + nt * 8 + tg2;
            float b0 = bias_sm[col], b1 = bias_sm[col + 1];
            dsm[row0 * DP + col]           = acc[mt][nt][0] + b0;
            dsm[row0 * DP + col + 1]       = acc[mt][nt][1] + b1;
            dsm[(row0 + 8) * DP + col]     = acc[mt][nt][2] + b0;
            dsm[(row0 + 8) * DP + col + 1] = acc[mt][nt][3] + b1;
        }
    __syncthreads();

    float* scr = g_scr[par];
#pragma unroll 1
    for (int i8 = 0; i8 < 8; i8++) {
        int r = wid * 8 + i8;
        float4 va = *(const float4*)&dsm[r * DP + ln * 8];
        float4 vb = *(const float4*)&dsm[r * DP + ln * 8 + 4];
        float vals[8] = {va.x, va.y, va.z, va.w, vb.x, vb.y, vb.z, vb.w};
        int c0 = v0 + ln * 8;

        float vm = vals[0]; int vi = c0;
#pragma unroll
        for (int j = 1; j < 8; j++)
            if (vals[j] > vm) { vm = vals[j]; vi = c0 + j; }

        unsigned long long key =
            ((unsigned long long)fmono(vm) << 32) |
            (unsigned int)(~(unsigned int)vi);
#pragma unroll
        for (int o = 16; o >= 1; o >>= 1) {
            unsigned long long other = __shfl_xor_sync(0xFFFFFFFFu, key, o);
            if (other > key) key = other;
        }
        float mrow = fmono_inv((unsigned int)(key >> 32));

        float s = 0.f;
#pragma unroll
        for (int j = 0; j < 8; j++) s += fexp(vals[j] - mrow);
#pragma unroll
        for (int o = 16; o >= 1; o >>= 1)
            s += __shfl_xor_sync(0xFFFFFFFFu, s, o);

        float* orow = scr + (size_t)r * VQ + c0;
        *(float4*)orow       = va;
        *(float4*)(orow + 4) = vb;

        if (ln == 0) {
            atomicMax(&g_amax[par][r], key);
            g_part[par][r][blockIdx.x] = make_float2(mrow, s);
        }
    }
    __syncthreads();
}

// ---------------- the persistent decode kernel ----------------
__global__ void __launch_bounds__(256, 1)
k_main(const float* __restrict__ emb,
       const float* __restrict__ W_ih,
       const float* __restrict__ W_hh,
       const float* __restrict__ b_ih,
       const float* __restrict__ b_hh,
       const float* __restrict__ out_b,
       const int*   __restrict__ qix,
       float* __restrict__ out, int steps) {
    extern __shared__ __align__(16) char smem_raw[];
    uint32_t raw  = smem_u32(smem_raw);
    uint32_t base = (raw + 1023) & ~1023u;
    char* smb = smem_raw + (base - raw);

    ((float*)(smb + OFF_BIAS))[threadIdx.x] = out_b[blockIdx.x * 256 + threadIdx.x];

    for (int s = 0; s < steps; s++) {
        int par = s & 1;

        // phase A: lstm on all CTAs, then finalize prev step (half-row per CTA)
        lstm_phase(smb, emb, W_ih, W_hh, b_ih, b_hh, qix, par);
        if (s > 0) {
            finalize_half(smb, out, s - 1, steps, blockIdx.x);
            if (blockIdx.x < 3)
                finalize_half(smb, out, s - 1, steps, 125 + blockIdx.x);
        }
        gsync();

        // phase B: logits GEMM + epilogue (all CTAs)
        logits_phase(smb, base, par);
        gsync();
    }

    // finalize last step
    finalize_half(smb, out, steps - 1, steps, blockIdx.x);
    if (blockIdx.x < 3)
        finalize_half(smb, out, steps - 1, steps, 125 + blockIdx.x);
}

// ---------------- launch ----------------
extern "C" void kernel_launch(void* const* d_in, const int* in_sizes, int n_in,
                              void* d_out, int out_size) {
    (void)in_sizes; (void)n_in;
    const float* q_att = (const float*)d_in[1];
    const float* emb   = (const float*)d_in[2];
    const float* W_ih  = (const float*)d_in[3];
    const float* W_hh  = (const float*)d_in[4];
    const float* b_ih  = (const float*)d_in[5];
    const float* b_hh  = (const float*)d_in[6];
    const float* out_W = (const float*)d_in[7];
    const float* out_b = (const float*)d_in[8];
    const int*   qix   = (const int*)d_in[9];

    int steps = out_size / (BSZ * VQ);  // 33

    cudaFuncSetAttribute(k_main, cudaFuncAttributeMaxDynamicSharedMemorySize,
                         SMEM_REQ);

    k_prep<<<2048, 256>>>(out_W);
    k_init<<<1, 256>>>(q_att);
    k_main<<<NCTA, 256, SMEM_REQ>>>(emb, W_ih, W_hh, b_ih, b_hh, out_b, qix,
                                    (float*)d_out, steps);
}

// round 7
// speedup vs baseline: 2.5406x; 1.3357x over previous
#include <cuda_runtime.h>
#include <cuda_bf16.h>
#include <math.h>
#include <stdint.h>

#define BSZ 64
#define HID 512
#define EMB 300
#define VQ  32000
#define SOS 1
#define NBLK 125
#define NCTA 125
#define NCHUNK 8

// dynamic smem layout (relative to 1024-aligned base)
#define OFF_B    32768      // B tiles: 2 bufs x (hi 32K + lo 32K)
#define OFF_BIAS 163840     // 256 floats
#define OFF_RED  164864     // reduction scratch
#define SMEM_REQ 166912
#define DP 264
// lstm-phase aliases (low region, < 17 KB)
#define LS_XH  0
#define LS_W   8704
#define LS_G   11264
#define LS_BS  16704
#define LS_IDX 16800

// ---------------- persistent device state ----------------
__device__ float g_hbuf[2][BSZ * HID];
__device__ float g_c[BSZ * HID];
__device__ unsigned long long g_amax[2][BSZ];
__device__ float2 g_part[2][BSZ][NBLK];
__device__ float g_scr[2][(size_t)BSZ * VQ];
__device__ __nv_bfloat16 g_Whi[(size_t)VQ * HID];
__device__ __nv_bfloat16 g_Wlo[(size_t)VQ * HID];
__device__ unsigned int g_cnt, g_gen;

// ---------------- helpers ----------------
__device__ __forceinline__ unsigned int fmono(float f) {
    unsigned int u = __float_as_uint(f);
    return (u & 0x80000000u) ? ~u : (u | 0x80000000u);
}
__device__ __forceinline__ float fmono_inv(unsigned int u) {
    return (u & 0x80000000u) ? __uint_as_float(u & 0x7FFFFFFFu)
                             : __uint_as_float(~u);
}
__device__ __forceinline__ float fexp(float x) {
    x = fmaxf(x, -80.0f);
    float t = fmaf(x, 1.4426950408889634f, 12582912.0f);
    float i = t - 12582912.0f;
    float f = fmaf(x, 1.4426950408889634f, -i);
    float p = 1.3333558e-3f;
    p = fmaf(p, f, 9.6181291e-3f);
    p = fmaf(p, f, 5.5504110e-2f);
    p = fmaf(p, f, 2.4022651e-1f);
    p = fmaf(p, f, 6.9314718e-1f);
    p = fmaf(p, f, 1.0f);
    int ei = __float_as_int(t) - 0x4B400000;
    float sc = __int_as_float((ei + 127) << 23);
    return sc * p;
}
__device__ __forceinline__ uint32_t smem_u32(const void* p) {
    uint32_t a;
    asm("{ .reg .u64 t; cvta.to.shared.u64 t, %1; cvt.u32.u64 %0, t; }"
        : "=r"(a) : "l"(p));
    return a;
}
__device__ __forceinline__ uint32_t sw128(uint32_t o) { return o ^ ((o >> 3) & 0x70); }
__device__ __forceinline__ uint32_t pb2(float a, float b) {
    __nv_bfloat162 t = __floats2bfloat162_rn(a, b);
    return *reinterpret_cast<uint32_t*>(&t);
}
__device__ __forceinline__ unsigned int ld_acq(const unsigned int* p) {
    unsigned int v;
    asm volatile("ld.global.acquire.gpu.b32 %0, [%1];" : "=r"(v) : "l"(p) : "memory");
    return v;
}
__device__ __forceinline__ void st_cs4(float* p, float4 x) {
    asm volatile("st.global.cs.v4.f32 [%0], {%1, %2, %3, %4};"
                 :: "l"(p), "f"(x.x), "f"(x.y), "f"(x.z), "f"(x.w) : "memory");
}
__device__ __forceinline__ float4 ld_cs4(const float* p) {
    float4 x;
    asm volatile("ld.global.cs.v4.f32 {%0, %1, %2, %3}, [%4];"
                 : "=f"(x.x), "=f"(x.y), "=f"(x.z), "=f"(x.w) : "l"(p));
    return x;
}

__device__ __forceinline__ void gsync() {
    __threadfence();
    __syncthreads();
    if (threadIdx.x == 0) {
        unsigned int gen = ld_acq(&g_gen);
        unsigned int old = atomicAdd(&g_cnt, 1u);
        if (old == NCTA - 1) {
            g_cnt = 0;
            __threadfence();
            atomicAdd(&g_gen, 1u);
        } else {
            unsigned int cur;
            do { __nanosleep(32); cur = ld_acq(&g_gen); } while (cur == gen);
        }
    }
    __syncthreads();
}

#define CP_ASYNC16(dst, src) \
    asm volatile("cp.async.cg.shared.global [%0], [%1], 16;" :: "r"(dst), "l"(src) : "memory")
#define CP_COMMIT() asm volatile("cp.async.commit_group;" ::: "memory")
#define CP_WAIT(n)  asm volatile("cp.async.wait_group %0;" :: "n"(n) : "memory")

__device__ __forceinline__ void ldsm4(uint32_t* r, uint32_t addr) {
    asm volatile("ldmatrix.sync.aligned.m8n8.x4.shared.b16 {%0,%1,%2,%3}, [%4];"
                 : "=r"(r[0]), "=r"(r[1]), "=r"(r[2]), "=r"(r[3]) : "r"(addr));
}
__device__ __forceinline__ void mma16816(float* d, const uint32_t* a, const uint32_t* b) {
    asm volatile(
        "mma.sync.aligned.m16n8k16.row.col.f32.bf16.bf16.f32 "
        "{%0,%1,%2,%3}, {%4,%5,%6,%7}, {%8,%9}, {%0,%1,%2,%3};"
        : "+f"(d[0]), "+f"(d[1]), "+f"(d[2]), "+f"(d[3])
        : "r"(a[0]), "r"(a[1]), "r"(a[2]), "r"(a[3]), "r"(b[0]), "r"(b[1]));
}

// ---------------- phase A1: LSTM on all 125 CTAs ----------------
__device__ void lstm_phase(char* smb,
                           const float* __restrict__ emb,
                           const float* __restrict__ W_ih,
                           const float* __restrict__ W_hh,
                           const float* __restrict__ b_ih,
                           const float* __restrict__ b_hh,
                           const int*   __restrict__ qix,
                           int par) {
    float (*xh)[68] = (float(*)[68])(smb + LS_XH);
    float (*ws)[20] = (float(*)[20])(smb + LS_W);
    float (*gs)[68] = (float(*)[68])(smb + LS_G);
    float* bs  = (float*)(smb + LS_BS);
    int* sidx  = (int*)(smb + LS_IDX);

    const int t  = threadIdx.x;
    const int i0 = blockIdx.x;
    const int NU = (i0 < 12) ? 5 : 4;
    const int NR = NU * 4;
    int u[5];
    u[0] = i0; u[1] = 125 + i0; u[2] = 250 + i0; u[3] = 375 + i0; u[4] = 500 + i0;

    const float* hin  = g_hbuf[par];
    float*       hout = g_hbuf[par ^ 1];

    if (t < BSZ) {
        unsigned long long key = __ldcg(&g_amax[par ^ 1][t]);
        sidx[t] = qix[~(unsigned int)(key & 0xFFFFFFFFull)];
    }
    if (i0 == 0 && t >= 64 && t < 128) g_amax[par][t - 64] = 0ull;
    if (t < NR) {
        int gr = (t & 3) * 512 + u[t >> 2];
        bs[t] = b_ih[gr] + b_hh[gr];
    }

    const int tx = t & 15, ty = t >> 4;
    const int m0 = ty * 4;
    const bool xt = (NR == 20) && (tx < 4);
    float acc[4]  = {0.f, 0.f, 0.f, 0.f};
    float acc2[4] = {0.f, 0.f, 0.f, 0.f};

    float xr[8], wr[3];
    const int lm = t >> 5, lk = t & 31;       // xh load: row m stride 8
    const int wrr = t >> 5, wkk = t & 31;     // ws load geometry (r = i>>5)
    __syncthreads();   // sidx ready

    // ---- phase 1: x = relu(emb[idx]) vs W_ih, K=300 ragged (10 iters) ----
    {
        // preload iter 0
#pragma unroll
        for (int n = 0; n < 8; n++) {
            int m = lm + n * 8, k = lk;
            xr[n] = (k < EMB) ? fmaxf(__ldg(&emb[(size_t)sidx[m] * EMB + k]), 0.f) : 0.f;
        }
#pragma unroll
        for (int n = 0; n < 3; n++) {
            int i = t + n * 256;
            if (i < NR * 32) {
                int r = i >> 5, kk = i & 31;
                int gr = (r & 3) * 512 + u[r >> 2];
                wr[n] = (kk < EMB) ? W_ih[(size_t)gr * EMB + kk] : 0.f;
            }
        }
        for (int k0 = 0; k0 < 320; k0 += 32) {
#pragma unroll
            for (int n = 0; n < 8; n++) xh[lk][lm + n * 8] = xr[n];
#pragma unroll
            for (int n = 0; n < 3; n++) {
                int i = t + n * 256;
                if (i < NR * 32) ws[i & 31][i >> 5] = wr[n];
            }
            __syncthreads();
            if (k0 + 32 < 320) {
                int k0n = k0 + 32;
#pragma unroll
                for (int n = 0; n < 8; n++) {
                    int m = lm + n * 8, k = k0n + lk;
                    xr[n] = (k < EMB) ? fmaxf(__ldg(&emb[(size_t)sidx[m] * EMB + k]), 0.f) : 0.f;
                }
#pragma unroll
                for (int n = 0; n < 3; n++) {
                    int i = t + n * 256;
                    if (i < NR * 32) {
                        int r = i >> 5, kk = i & 31;
                        int k = k0n + kk;
                        int gr = (r & 3) * 512 + u[r >> 2];
                        wr[n] = (k < EMB) ? W_ih[(size_t)gr * EMB + k] : 0.f;
                    }
                }
            }
#pragma unroll
            for (int kk = 0; kk < 32; kk++) {
                float4 a = *(const float4*)&xh[kk][m0];
                float w = ws[kk][tx];
                acc[0] = fmaf(w, a.x, acc[0]);
                acc[1] = fmaf(w, a.y, acc[1]);
                acc[2] = fmaf(w, a.z, acc[2]);
                acc[3] = fmaf(w, a.w, acc[3]);
                if (xt) {
                    float w2 = ws[kk][16 + tx];
                    acc2[0] = fmaf(w2, a.x, acc2[0]);
                    acc2[1] = fmaf(w2, a.y, acc2[1]);
                    acc2[2] = fmaf(w2, a.z, acc2[2]);
                    acc2[3] = fmaf(w2, a.w, acc2[3]);
                }
            }
            __syncthreads();
        }
    }

    // ---- phase 2: h vs W_hh, K=512 (16 iters) ----
    {
#pragma unroll
        for (int n = 0; n < 8; n++)
            xr[n] = __ldcg(&hin[(lm + n * 8) * HID + lk]);
#pragma unroll
        for (int n = 0; n < 3; n++) {
            int i = t + n * 256;
            if (i < NR * 32) {
                int r = i >> 5, kk = i & 31;
                int gr = (r & 3) * 512 + u[r >> 2];
                wr[n] = W_hh[(size_t)gr * HID + kk];
            }
        }
        for (int k0 = 0; k0 < HID; k0 += 32) {
#pragma unroll
            for (int n = 0; n < 8; n++) xh[lk][lm + n * 8] = xr[n];
#pragma unroll
            for (int n = 0; n < 3; n++) {
                int i = t + n * 256;
                if (i < NR * 32) ws[i & 31][i >> 5] = wr[n];
            }
            __syncthreads();
            if (k0 + 32 < HID) {
                int k0n = k0 + 32;
#pragma unroll
                for (int n = 0; n < 8; n++)
                    xr[n] = __ldcg(&hin[(lm + n * 8) * HID + k0n + lk]);
#pragma unroll
                for (int n = 0; n < 3; n++) {
                    int i = t + n * 256;
                    if (i < NR * 32) {
                        int r = i >> 5, kk = i & 31;
                        int gr = (r & 3) * 512 + u[r >> 2];
                        wr[n] = W_hh[(size_t)gr * HID + k0n + kk];
                    }
                }
            }
#pragma unroll
            for (int kk = 0; kk < 32; kk++) {
                float4 a = *(const float4*)&xh[kk][m0];
                float w = ws[kk][tx];
                acc[0] = fmaf(w, a.x, acc[0]);
                acc[1] = fmaf(w, a.y, acc[1]);
                acc[2] = fmaf(w, a.z, acc[2]);
                acc[3] = fmaf(w, a.w, acc[3]);
                if (xt) {
                    float w2 = ws[kk][16 + tx];
                    acc2[0] = fmaf(w2, a.x, acc2[0]);
                    acc2[1] = fmaf(w2, a.y, acc2[1]);
                    acc2[2] = fmaf(w2, a.z, acc2[2]);
                    acc2[3] = fmaf(w2, a.w, acc2[3]);
                }
            }
            __syncthreads();
        }
    }

    // gates -> smem (+bias)
    {
        float bb = bs[tx];
        gs[tx][m0]     = acc[0] + bb;
        gs[tx][m0 + 1] = acc[1] + bb;
        gs[tx][m0 + 2] = acc[2] + bb;
        gs[tx][m0 + 3] = acc[3] + bb;
        if (xt) {
            float b2 = bs[16 + tx];
            gs[16 + tx][m0]     = acc2[0] + b2;
            gs[16 + tx][m0 + 1] = acc2[1] + b2;
            gs[16 + tx][m0 + 2] = acc2[2] + b2;
            gs[16 + tx][m0 + 3] = acc2[3] + b2;
        }
    }
    __syncthreads();

    for (int p = t; p < NU * 64; p += 256) {
        int uu = p >> 6, m = p & 63;
        float gi = gs[uu * 4 + 0][m];
        float gf = gs[uu * 4 + 1][m];
        float gg = gs[uu * 4 + 2][m];
        float go = gs[uu * 4 + 3][m];
        int ci = m * HID + u[uu];
        float c  = __ldcg(&g_c[ci]);
        float si = 1.f / (1.f + expf(-gi));
        float sf = 1.f / (1.f + expf(-gf));
        float so = 1.f / (1.f + expf(-go));
        float nc = sf * c + si * tanhf(gg);
        float nh = so * tanhf(nc);
        g_c[ci]  = nc;
        hout[ci] = nh;
    }
    __syncthreads();
}

// ---------------- phase A2: finalize one half-row of a finished step ----------------
__device__ void finalize_half(char* smb, float* __restrict__ out,
                              int sprev, int steps, int hr) {
    int r = hr >> 1, half = hr & 1;
    int pp = sprev & 1;
    int t = threadIdx.x;
    float* red = (float*)(smb + OFF_RED);
    __syncthreads();

    float2 p = (t < NBLK) ? __ldcg(&g_part[pp][r][t]) : make_float2(-3.4e38f, 0.f);
    float m = p.x;
#pragma unroll
    for (int o = 16; o >= 1; o >>= 1)
        m = fmaxf(m, __shfl_xor_sync(0xFFFFFFFFu, m, o));
    if ((t & 31) == 0) red[t >> 5] = m;
    __syncthreads();
    float M = red[0];
#pragma unroll
    for (int i = 1; i < 8; i++) M = fmaxf(M, red[i]);

    float s = (t < NBLK) ? p.y * fexp(p.x - M) : 0.f;
#pragma unroll
    for (int o = 16; o >= 1; o >>= 1)
        s += __shfl_xor_sync(0xFFFFFFFFu, s, o);
    __syncthreads();
    if ((t & 31) == 0) red[8 + (t >> 5)] = s;
    __syncthreads();
    float S = 0.f;
#pragma unroll
    for (int i = 0; i < 8; i++) S += red[8 + i];
    float lse = M + logf(S);

    const float* src = g_scr[pp] + (size_t)r * VQ + half * (VQ / 2);
    float* dst = out + ((size_t)r * steps + sprev) * VQ + half * (VQ / 2);
    for (int i = t; i < VQ / 8; i += 256) {
        float4 x = ld_cs4(src + i * 4);
        x.x -= lse; x.y -= lse; x.z -= lse; x.w -= lse;
        st_cs4(dst + i * 4, x);
    }
    __syncthreads();
}

// ---------------- phase B: logits GEMM + fused epilogue ----------------
__device__ __forceinline__ void issueB(uint32_t bbase, int c, int v0) {
    int t = threadIdx.x;
#pragma unroll
    for (int n = 0; n < 8; n++) {
        int i = t + n * 256;
        int r = i >> 3, j = i & 7;
        size_t g = (size_t)(v0 + r) * HID + (size_t)c * 64 + j * 8;
        uint32_t so = sw128((uint32_t)(r * 128 + j * 16));
        CP_ASYNC16(bbase + so, g_Whi + g);
        CP_ASYNC16(bbase + 32768 + so, g_Wlo + g);
    }
}
__device__ __forceinline__ void ldgA(const float* h, int c, float4* av) {
    int t = threadIdx.x;
#pragma unroll
    for (int n = 0; n < 4; n++) {
        int i = t + n * 256;
        int r = i >> 4, q = i & 15;
        av[n] = __ldcg((const float4*)&h[r * HID + c * 64 + q * 4]);
    }
}
__device__ __forceinline__ void stsA(uint32_t abase, const float4* av) {
    int t = threadIdx.x;
#pragma unroll
    for (int n = 0; n < 4; n++) {
        int i = t + n * 256;
        int r = i >> 4, q = i & 15;
        float4 x = av[n];
        float hx = __bfloat162float(__float2bfloat16_rn(x.x));
        float hy = __bfloat162float(__float2bfloat16_rn(x.y));
        float hz = __bfloat162float(__float2bfloat16_rn(x.z));
        float hw = __bfloat162float(__float2bfloat16_rn(x.w));
        uint32_t so = sw128((uint32_t)(r * 128 + q * 8));
        asm volatile("st.shared.v2.b32 [%0], {%1, %2};" ::
                     "r"(abase + so), "r"(pb2(hx, hy)), "r"(pb2(hz, hw)) : "memory");
        asm volatile("st.shared.v2.b32 [%0], {%1, %2};" ::
                     "r"(abase + 8192 + so),
                     "r"(pb2(x.x - hx, x.y - hy)), "r"(pb2(x.z - hz, x.w - hw)) : "memory");
    }
}

// NOTE: B chunk 0 is prefetched into buf0 during phase A (cp.async group already
// committed when this is called).
__device__ void logits_phase(char* smb, uint32_t base, int par) {
    const int t  = threadIdx.x;
    const int wid = t >> 5, ln = t & 31;
    const int v0 = blockIdx.x * 256;
    const float* h = g_hbuf[par ^ 1];
    float* bias_sm = (float*)(smb + OFF_BIAS);

    float acc[4][4][4];
#pragma unroll
    for (int a = 0; a < 4; a++)
#pragma unroll
        for (int b = 0; b < 4; b++)
#pragma unroll
            for (int cc = 0; cc < 4; cc++) acc[a][b][cc] = 0.f;

    {
        float4 av[4];
        ldgA(h, 0, av);
        stsA(base, av);
    }

    const int ti = ln >> 3, li = ln & 7;
    const int aml = (ti & 1) * 8 + li, ak = ti >> 1;
    const int bnl = (ti >> 1) * 8 + li, bk = ti & 1;
    const int nbase = wid * 32;

    float4 av[4];
    for (int c = 0; c < NCHUNK; c++) {
        int b = c & 1;
        if (c < NCHUNK - 1) {
            issueB(base + OFF_B + (b ^ 1) * 65536, c + 1, v0);
            CP_COMMIT();
            ldgA(h, c + 1, av);
            CP_WAIT(1);
        } else {
            CP_WAIT(0);
        }
        __syncthreads();

        uint32_t Ahi = base + b * 16384, Alo = Ahi + 8192;
        uint32_t Bhi = base + OFF_B + b * 65536, Blo = Bhi + 32768;
#pragma unroll
        for (int ks = 0; ks < 4; ks++) {
            uint32_t ah[4][4], al[4][4], bh[4][2], bl[4][2];
#pragma unroll
            for (int mt = 0; mt < 4; mt++) {
                uint32_t off = sw128((uint32_t)((mt * 16 + aml) * 128 + ks * 32 + ak * 16));
                ldsm4(ah[mt], Ahi + off);
                ldsm4(al[mt], Alo + off);
            }
#pragma unroll
            for (int ng = 0; ng < 2; ng++) {
                uint32_t off = sw128((uint32_t)((nbase + ng * 16 + bnl) * 128 + ks * 32 + bk * 16));
                uint32_t r4[4];
                ldsm4(r4, Bhi + off);
                bh[ng * 2][0] = r4[0]; bh[ng * 2][1] = r4[1];
                bh[ng * 2 + 1][0] = r4[2]; bh[ng * 2 + 1][1] = r4[3];
                ldsm4(r4, Blo + off);
                bl[ng * 2][0] = r4[0]; bl[ng * 2][1] = r4[1];
                bl[ng * 2 + 1][0] = r4[2]; bl[ng * 2 + 1][1] = r4[3];
            }
#pragma unroll
            for (int mt = 0; mt < 4; mt++)
#pragma unroll
                for (int nt = 0; nt < 4; nt++) {
                    mma16816(acc[mt][nt], ah[mt], bh[nt]);
                    mma16816(acc[mt][nt], ah[mt], bl[nt]);
                    mma16816(acc[mt][nt], al[mt], bh[nt]);
                }
        }
        if (c < NCHUNK - 1) stsA(base + (b ^ 1) * 16384, av);
        __syncthreads();
    }

    float* dsm = (float*)smb;
    const int g = ln >> 2, tg2 = (ln & 3) * 2;
#pragma unroll
    for (int mt = 0; mt < 4; mt++)
#pragma unroll
        for (int nt = 0; nt < 4; nt++) {
            int row0 = mt * 16 + g;
            int col  = nbase + nt * 8 + tg2;
            float b0 = bias_sm[col], b1 = bias_sm[col + 1];
            dsm[row0 * DP + col]           = acc[mt][nt][0] + b0;
            dsm[row0 * DP + col + 1]       = acc[mt][nt][1] + b1;
            dsm[(row0 + 8) * DP + col]     = acc[mt][nt][2] + b0;
            dsm[(row0 + 8) * DP + col + 1] = acc[mt][nt][3] + b1;
        }
    __syncthreads();

    float* scr = g_scr[par];
#pragma unroll 1
    for (int i8 = 0; i8 < 8; i8++) {
        int r = wid * 8 + i8;
        float4 va = *(const float4*)&dsm[r * DP + ln * 8];
        float4 vb = *(const float4*)&dsm[r * DP + ln * 8 + 4];
        float vals[8] = {va.x, va.y, va.z, va.w, vb.x, vb.y, vb.z, vb.w};
        int c0 = v0 + ln * 8;

        float vm = vals[0]; int vi = c0;
#pragma unroll
        for (int j = 1; j < 8; j++)
            if (vals[j] > vm) { vm = vals[j]; vi = c0 + j; }

        unsigned long long key =
            ((unsigned long long)fmono(vm) << 32) |
            (unsigned int)(~(unsigned int)vi);
#pragma unroll
        for (int o = 16; o >= 1; o >>= 1) {
            unsigned long long other = __shfl_xor_sync(0xFFFFFFFFu, key, o);
            if (other > key) key = other;
        }
        float mrow = fmono_inv((unsigned int)(key >> 32));

        float s = 0.f;
#pragma unroll
        for (int j = 0; j < 8; j++) s += fexp(vals[j] - mrow);
#pragma unroll
        for (int o = 16; o >= 1; o >>= 1)
            s += __shfl_xor_sync(0xFFFFFFFFu, s, o);

        float* orow = scr + (size_t)r * VQ + c0;
        *(float4*)orow       = va;
        *(float4*)(orow + 4) = vb;

        if (ln == 0) {
            atomicMax(&g_amax[par][r], key);
            g_part[par][r][blockIdx.x] = make_float2(mrow, s);
        }
    }
    __syncthreads();
}

// ---------------- the persistent decode kernel (single launch) ----------------
__global__ void __launch_bounds__(256, 1)
k_main(const float* __restrict__ q_att,
       const float* __restrict__ emb,
       const float* __restrict__ W_ih,
       const float* __restrict__ W_hh,
       const float* __restrict__ b_ih,
       const float* __restrict__ b_hh,
       const float* __restrict__ out_W,
       const float* __restrict__ out_b,
       const int*   __restrict__ qix,
       float* __restrict__ out, int steps) {
    extern __shared__ __align__(16) char smem_raw[];
    uint32_t raw  = smem_u32(smem_raw);
    uint32_t base = (raw + 1023) & ~1023u;
    char* smb = smem_raw + (base - raw);
    const int t = threadIdx.x;

    // ---- prologue: W split (all CTAs) + state init (CTA 0) ----
    {
        size_t n4 = (size_t)VQ * HID / 4;
        uint2* whi = (uint2*)g_Whi;
        uint2* wlo = (uint2*)g_Wlo;
        for (size_t i = (size_t)blockIdx.x * 256 + t; i < n4; i += (size_t)NCTA * 256) {
            float4 x = ((const float4*)out_W)[i];
            float hx = __bfloat162float(__float2bfloat16_rn(x.x));
            float hy = __bfloat162float(__float2bfloat16_rn(x.y));
            float hz = __bfloat162float(__float2bfloat16_rn(x.z));
            float hw = __bfloat162float(__float2bfloat16_rn(x.w));
            whi[i] = make_uint2(pb2(hx, hy), pb2(hz, hw));
            wlo[i] = make_uint2(pb2(x.x - hx, x.y - hy), pb2(x.z - hz, x.w - hw));
        }
        if (blockIdx.x == 0) {
            if (t < BSZ) {
                g_amax[1][t] = (unsigned long long)(unsigned int)(~(unsigned int)SOS);
                g_amax[0][t] = 0ull;
            }
            for (int i = t; i < BSZ * HID; i += 256) {
                g_hbuf[0][i] = q_att[i];
                g_c[i] = 0.f;
            }
        }
        ((float*)(smb + OFF_BIAS))[t] = out_b[blockIdx.x * 256 + t];
    }
    gsync();

    for (int s = 0; s < steps; s++) {
        int par = s & 1;

        // prefetch B chunk 0 for phase B (OFF_B region unused during phase A)
        issueB(base + OFF_B, 0, blockIdx.x * 256);
        CP_COMMIT();

        lstm_phase(smb, emb, W_ih, W_hh, b_ih, b_hh, qix, par);
        if (s > 0) {
            finalize_half(smb, out, s - 1, steps, blockIdx.x);
            if (blockIdx.x < 3)
                finalize_half(smb, out, s - 1, steps, 125 + blockIdx.x);
        }
        gsync();

        logits_phase(smb, base, par);
        gsync();
    }

    finalize_half(smb, out, steps - 1, steps, blockIdx.x);
    if (blockIdx.x < 3)
        finalize_half(smb, out, steps - 1, steps, 125 + blockIdx.x);
}

// ---------------- launch ----------------
extern "C" void kernel_launch(void* const* d_in, const int* in_sizes, int n_in,
                              void* d_out, int out_size) {
    (void)in_sizes; (void)n_in;
    const float* q_att = (const float*)d_in[1];
    const float* emb   = (const float*)d_in[2];
    const float* W_ih  = (const float*)d_in[3];
    const float* W_hh  = (const float*)d_in[4];
    const float* b_ih  = (const float*)d_in[5];
    const float* b_hh  = (const float*)d_in[6];
    const float* out_W = (const float*)d_in[7];
    const float* out_b = (const float*)d_in[8];
    const int*   qix   = (const int*)d_in[9];

    int steps = out_size / (BSZ * VQ);  // 33

    cudaFuncSetAttribute(k_main, cudaFuncAttributeMaxDynamicSharedMemorySize,
                         SMEM_REQ);

    k_main<<<NCTA, 256, SMEM_REQ>>>(q_att, emb, W_ih, W_hh, b_ih, b_hh,
                                    out_W, out_b, qix, (float*)d_out, steps);
}

// round 8
// speedup vs baseline: 2.7875x; 1.0972x over previous
#include <cuda_runtime.h>
#include <cuda_bf16.h>
#include <math.h>
#include <stdint.h>

#define BSZ 64
#define HID 512
#define EMB 300
#define VQ  32000
#define SOS 1
#define NBLK 125
#define NCTA 125
#define NCHUNK 8

// dynamic smem layout (relative to 1024-aligned base)
// A bufs: 0..32K ; B bufs: 32K..160K (buf0 hi 32K..64K, buf0 lo 64K..96K,
//                                     buf1 hi 96K..128K... see below)
// NOTE actual B layout: buf b at OFF_B + b*65536 (hi), +32768 (lo).
//   buf0: 32768..98304   buf1: 98304..163840
// TILE aliases buf1 (98304..163840): 64 rows x 256 floats, written by the
// phase-B epilogue AFTER the mainloop (buf1 dead), consumed by finalize_tile
// in the NEXT step's phase A (before buf1 is reloaded at chunk 1).
#define OFF_B    32768
#define OFF_TILE 98304
#define OFF_BIAS 163840
#define OFF_RED  164864     // 64 lse floats + scratch
#define SMEM_REQ 166912
// lstm-phase aliases (low region, < 17 KB)
#define LS_XH  0
#define LS_W   8704
#define LS_G   11264
#define LS_BS  16704
#define LS_IDX 16800

// ---------------- persistent device state ----------------
__device__ float g_hbuf[2][BSZ * HID];
__device__ float g_c[BSZ * HID];
__device__ unsigned long long g_amax[2][BSZ];
__device__ float2 g_part[2][BSZ][NBLK];
__device__ __nv_bfloat16 g_Whi[(size_t)VQ * HID];
__device__ __nv_bfloat16 g_Wlo[(size_t)VQ * HID];
__device__ unsigned int g_cnt, g_gen;

// ---------------- helpers ----------------
__device__ __forceinline__ unsigned int fmono(float f) {
    unsigned int u = __float_as_uint(f);
    return (u & 0x80000000u) ? ~u : (u | 0x80000000u);
}
__device__ __forceinline__ float fmono_inv(unsigned int u) {
    return (u & 0x80000000u) ? __uint_as_float(u & 0x7FFFFFFFu)
                             : __uint_as_float(~u);
}
__device__ __forceinline__ float fexp(float x) {
    x = fmaxf(x, -80.0f);
    float t = fmaf(x, 1.4426950408889634f, 12582912.0f);
    float i = t - 12582912.0f;
    float f = fmaf(x, 1.4426950408889634f, -i);
    float p = 1.3333558e-3f;
    p = fmaf(p, f, 9.6181291e-3f);
    p = fmaf(p, f, 5.5504110e-2f);
    p = fmaf(p, f, 2.4022651e-1f);
    p = fmaf(p, f, 6.9314718e-1f);
    p = fmaf(p, f, 1.0f);
    int ei = __float_as_int(t) - 0x4B400000;
    float sc = __int_as_float((ei + 127) << 23);
    return sc * p;
}
__device__ __forceinline__ uint32_t smem_u32(const void* p) {
    uint32_t a;
    asm("{ .reg .u64 t; cvta.to.shared.u64 t, %1; cvt.u32.u64 %0, t; }"
        : "=r"(a) : "l"(p));
    return a;
}
__device__ __forceinline__ uint32_t sw128(uint32_t o) { return o ^ ((o >> 3) & 0x70); }
__device__ __forceinline__ uint32_t pb2(float a, float b) {
    __nv_bfloat162 t = __floats2bfloat162_rn(a, b);
    return *reinterpret_cast<uint32_t*>(&t);
}
__device__ __forceinline__ unsigned int ld_acq(const unsigned int* p) {
    unsigned int v;
    asm volatile("ld.global.acquire.gpu.b32 %0, [%1];" : "=r"(v) : "l"(p) : "memory");
    return v;
}
__device__ __forceinline__ void st_cs4(float* p, float4 x) {
    asm volatile("st.global.cs.v4.f32 [%0], {%1, %2, %3, %4};"
                 :: "l"(p), "f"(x.x), "f"(x.y), "f"(x.z), "f"(x.w) : "memory");
}

__device__ __forceinline__ void gsync() {
    __threadfence();
    __syncthreads();
    if (threadIdx.x == 0) {
        unsigned int gen = ld_acq(&g_gen);
        unsigned int old = atomicAdd(&g_cnt, 1u);
        if (old == NCTA - 1) {
            g_cnt = 0;
            __threadfence();
            atomicAdd(&g_gen, 1u);
        } else {
            unsigned int cur;
            do { __nanosleep(32); cur = ld_acq(&g_gen); } while (cur == gen);
        }
    }
    __syncthreads();
}

#define CP_ASYNC16(dst, src) \
    asm volatile("cp.async.cg.shared.global [%0], [%1], 16;" :: "r"(dst), "l"(src) : "memory")
#define CP_COMMIT() asm volatile("cp.async.commit_group;" ::: "memory")
#define CP_WAIT(n)  asm volatile("cp.async.wait_group %0;" :: "n"(n) : "memory")

__device__ __forceinline__ void ldsm4(uint32_t* r, uint32_t addr) {
    asm volatile("ldmatrix.sync.aligned.m8n8.x4.shared.b16 {%0,%1,%2,%3}, [%4];"
                 : "=r"(r[0]), "=r"(r[1]), "=r"(r[2]), "=r"(r[3]) : "r"(addr));
}
__device__ __forceinline__ void mma16816(float* d, const uint32_t* a, const uint32_t* b) {
    asm volatile(
        "mma.sync.aligned.m16n8k16.row.col.f32.bf16.bf16.f32 "
        "{%0,%1,%2,%3}, {%4,%5,%6,%7}, {%8,%9}, {%0,%1,%2,%3};"
        : "+f"(d[0]), "+f"(d[1]), "+f"(d[2]), "+f"(d[3])
        : "r"(a[0]), "r"(a[1]), "r"(a[2]), "r"(a[3]), "r"(b[0]), "r"(b[1]));
}

// ---------------- phase A1: LSTM on all 125 CTAs ----------------
__device__ void lstm_phase(char* smb,
                           const float* __restrict__ emb,
                           const float* __restrict__ W_ih,
                           const float* __restrict__ W_hh,
                           const float* __restrict__ b_ih,
                           const float* __restrict__ b_hh,
                           const int*   __restrict__ qix,
                           int par) {
    float (*xh)[68] = (float(*)[68])(smb + LS_XH);
    float (*ws)[20] = (float(*)[20])(smb + LS_W);
    float (*gs)[68] = (float(*)[68])(smb + LS_G);
    float* bs  = (float*)(smb + LS_BS);
    int* sidx  = (int*)(smb + LS_IDX);

    const int t  = threadIdx.x;
    const int i0 = blockIdx.x;
    const int NU = (i0 < 12) ? 5 : 4;
    const int NR = NU * 4;
    int u[5];
    u[0] = i0; u[1] = 125 + i0; u[2] = 250 + i0; u[3] = 375 + i0; u[4] = 500 + i0;

    const float* hin  = g_hbuf[par];
    float*       hout = g_hbuf[par ^ 1];

    if (t < BSZ) {
        unsigned long long key = __ldcg(&g_amax[par ^ 1][t]);
        sidx[t] = qix[~(unsigned int)(key & 0xFFFFFFFFull)];
    }
    if (i0 == 0 && t >= 64 && t < 128) g_amax[par][t - 64] = 0ull;
    if (t < NR) {
        int gr = (t & 3) * 512 + u[t >> 2];
        bs[t] = b_ih[gr] + b_hh[gr];
    }

    const int tx = t & 15, ty = t >> 4;
    const int m0 = ty * 4;
    const bool xt = (NR == 20) && (tx < 4);
    float acc[4]  = {0.f, 0.f, 0.f, 0.f};
    float acc2[4] = {0.f, 0.f, 0.f, 0.f};

    float xr[8], wr[3];
    const int lm = t >> 5, lk = t & 31;
    __syncthreads();

    // ---- phase 1: x = relu(emb[idx]) vs W_ih, K=300 ragged ----
    {
#pragma unroll
        for (int n = 0; n < 8; n++) {
            int m = lm + n * 8, k = lk;
            xr[n] = (k < EMB) ? fmaxf(__ldg(&emb[(size_t)sidx[m] * EMB + k]), 0.f) : 0.f;
        }
#pragma unroll
        for (int n = 0; n < 3; n++) {
            int i = t + n * 256;
            if (i < NR * 32) {
                int r = i >> 5, kk = i & 31;
                int gr = (r & 3) * 512 + u[r >> 2];
                wr[n] = (kk < EMB) ? W_ih[(size_t)gr * EMB + kk] : 0.f;
            }
        }
        for (int k0 = 0; k0 < 320; k0 += 32) {
#pragma unroll
            for (int n = 0; n < 8; n++) xh[lk][lm + n * 8] = xr[n];
#pragma unroll
            for (int n = 0; n < 3; n++) {
                int i = t + n * 256;
                if (i < NR * 32) ws[i & 31][i >> 5] = wr[n];
            }
            __syncthreads();
            if (k0 + 32 < 320) {
                int k0n = k0 + 32;
#pragma unroll
                for (int n = 0; n < 8; n++) {
                    int m = lm + n * 8, k = k0n + lk;
                    xr[n] = (k < EMB) ? fmaxf(__ldg(&emb[(size_t)sidx[m] * EMB + k]), 0.f) : 0.f;
                }
#pragma unroll
                for (int n = 0; n < 3; n++) {
                    int i = t + n * 256;
                    if (i < NR * 32) {
                        int r = i >> 5, kk = i & 31;
                        int k = k0n + kk;
                        int gr = (r & 3) * 512 + u[r >> 2];
                        wr[n] = (k < EMB) ? W_ih[(size_t)gr * EMB + k] : 0.f;
                    }
                }
            }
#pragma unroll
            for (int kk = 0; kk < 32; kk++) {
                float4 a = *(const float4*)&xh[kk][m0];
                float w = ws[kk][tx];
                acc[0] = fmaf(w, a.x, acc[0]);
                acc[1] = fmaf(w, a.y, acc[1]);
                acc[2] = fmaf(w, a.z, acc[2]);
                acc[3] = fmaf(w, a.w, acc[3]);
                if (xt) {
                    float w2 = ws[kk][16 + tx];
                    acc2[0] = fmaf(w2, a.x, acc2[0]);
                    acc2[1] = fmaf(w2, a.y, acc2[1]);
                    acc2[2] = fmaf(w2, a.z, acc2[2]);
                    acc2[3] = fmaf(w2, a.w, acc2[3]);
                }
            }
            __syncthreads();
        }
    }

    // ---- phase 2: h vs W_hh, K=512 ----
    {
#pragma unroll
        for (int n = 0; n < 8; n++)
            xr[n] = __ldcg(&hin[(lm + n * 8) * HID + lk]);
#pragma unroll
        for (int n = 0; n < 3; n++) {
            int i = t + n * 256;
            if (i < NR * 32) {
                int r = i >> 5, kk = i & 31;
                int gr = (r & 3) * 512 + u[r >> 2];
                wr[n] = W_hh[(size_t)gr * HID + kk];
            }
        }
        for (int k0 = 0; k0 < HID; k0 += 32) {
#pragma unroll
            for (int n = 0; n < 8; n++) xh[lk][lm + n * 8] = xr[n];
#pragma unroll
            for (int n = 0; n < 3; n++) {
                int i = t + n * 256;
                if (i < NR * 32) ws[i & 31][i >> 5] = wr[n];
            }
            __syncthreads();
            if (k0 + 32 < HID) {
                int k0n = k0 + 32;
#pragma unroll
                for (int n = 0; n < 8; n++)
                    xr[n] = __ldcg(&hin[(lm + n * 8) * HID + k0n + lk]);
#pragma unroll
                for (int n = 0; n < 3; n++) {
                    int i = t + n * 256;
                    if (i < NR * 32) {
                        int r = i >> 5, kk = i & 31;
                        int gr = (r & 3) * 512 + u[r >> 2];
                        wr[n] = W_hh[(size_t)gr * HID + k0n + kk];
                    }
                }
            }
#pragma unroll
            for (int kk = 0; kk < 32; kk++) {
                float4 a = *(const float4*)&xh[kk][m0];
                float w = ws[kk][tx];
                acc[0] = fmaf(w, a.x, acc[0]);
                acc[1] = fmaf(w, a.y, acc[1]);
                acc[2] = fmaf(w, a.z, acc[2]);
                acc[3] = fmaf(w, a.w, acc[3]);
                if (xt) {
                    float w2 = ws[kk][16 + tx];
                    acc2[0] = fmaf(w2, a.x, acc2[0]);
                    acc2[1] = fmaf(w2, a.y, acc2[1]);
                    acc2[2] = fmaf(w2, a.z, acc2[2]);
                    acc2[3] = fmaf(w2, a.w, acc2[3]);
                }
            }
            __syncthreads();
        }
    }

    // gates -> smem (+bias)
    {
        float bb = bs[tx];
        gs[tx][m0]     = acc[0] + bb;
        gs[tx][m0 + 1] = acc[1] + bb;
        gs[tx][m0 + 2] = acc[2] + bb;
        gs[tx][m0 + 3] = acc[3] + bb;
        if (xt) {
            float b2 = bs[16 + tx];
            gs[16 + tx][m0]     = acc2[0] + b2;
            gs[16 + tx][m0 + 1] = acc2[1] + b2;
            gs[16 + tx][m0 + 2] = acc2[2] + b2;
            gs[16 + tx][m0 + 3] = acc2[3] + b2;
        }
    }
    __syncthreads();

    for (int p = t; p < NU * 64; p += 256) {
        int uu = p >> 6, m = p & 63;
        float gi = gs[uu * 4 + 0][m];
        float gf = gs[uu * 4 + 1][m];
        float gg = gs[uu * 4 + 2][m];
        float go = gs[uu * 4 + 3][m];
        int ci = m * HID + u[uu];
        float c  = __ldcg(&g_c[ci]);
        float si = 1.f / (1.f + expf(-gi));
        float sf = 1.f / (1.f + expf(-gf));
        float so = 1.f / (1.f + expf(-go));
        float nc = sf * c + si * tanhf(gg);
        float nh = so * tanhf(nc);
        g_c[ci]  = nc;
        hout[ci] = nh;
    }
    __syncthreads();
}

// ---------------- phase A2: finalize tile in smem -> out ----------------
// Tile (64 x 256 raw logits for cols [v0, v0+256)) is resident at OFF_TILE
// from the previous step's phase-B epilogue. Compute all 64 row-lse's from
// g_part, subtract, stream to out. Uniform work per CTA, coalesced stores.
__device__ void finalize_tile(char* smb, float* __restrict__ out,
                              int sprev, int steps) {
    const int t = threadIdx.x;
    const int w = t >> 5, ln = t & 31;
    const int pp = sprev & 1;
    const int v0 = blockIdx.x * 256;
    float* tile = (float*)(smb + OFF_TILE);
    float* lse_sm = (float*)(smb + OFF_RED);
    __syncthreads();

    // each warp computes lse for rows w, w+8, ..., w+56
    for (int r = w; r < BSZ; r += 8) {
        float2 pv[4];
#pragma unroll
        for (int i = 0; i < 4; i++) {
            int idx = ln + i * 32;
            pv[i] = (idx < NBLK) ? __ldcg(&g_part[pp][r][idx])
                                 : make_float2(-3.4e38f, 0.f);
        }
        float m = fmaxf(fmaxf(pv[0].x, pv[1].x), fmaxf(pv[2].x, pv[3].x));
#pragma unroll
        for (int o = 16; o >= 1; o >>= 1)
            m = fmaxf(m, __shfl_xor_sync(0xFFFFFFFFu, m, o));
        float s = pv[0].y * fexp(pv[0].x - m) + pv[1].y * fexp(pv[1].x - m)
                + pv[2].y * fexp(pv[2].x - m) + pv[3].y * fexp(pv[3].x - m);
#pragma unroll
        for (int o = 16; o >= 1; o >>= 1)
            s += __shfl_xor_sync(0xFFFFFFFFu, s, o);
        if (ln == 0) lse_sm[r] = m + logf(s);
    }
    __syncthreads();

    // stream tile - lse -> out
#pragma unroll 4
    for (int it = 0; it < 16; it++) {
        int idx = t + it * 256;          // 0..4095 float4s
        int r  = idx >> 6;
        int c4 = idx & 63;
        float4 x = *(const float4*)&tile[r * 256 + c4 * 4];
        float lse = lse_sm[r];
        x.x -= lse; x.y -= lse; x.z -= lse; x.w -= lse;
        st_cs4(out + ((size_t)r * steps + sprev) * VQ + v0 + c4 * 4, x);
    }
    __syncthreads();
}

// ---------------- phase B: logits GEMM + fused epilogue ----------------
__device__ __forceinline__ void issueB(uint32_t bbase, int c, int v0) {
    int t = threadIdx.x;
#pragma unroll
    for (int n = 0; n < 8; n++) {
        int i = t + n * 256;
        int r = i >> 3, j = i & 7;
        size_t g = (size_t)(v0 + r) * HID + (size_t)c * 64 + j * 8;
        uint32_t so = sw128((uint32_t)(r * 128 + j * 16));
        CP_ASYNC16(bbase + so, g_Whi + g);
        CP_ASYNC16(bbase + 32768 + so, g_Wlo + g);
    }
}
__device__ __forceinline__ void ldgA(const float* h, int c, float4* av) {
    int t = threadIdx.x;
#pragma unroll
    for (int n = 0; n < 4; n++) {
        int i = t + n * 256;
        int r = i >> 4, q = i & 15;
        av[n] = __ldcg((const float4*)&h[r * HID + c * 64 + q * 4]);
    }
}
__device__ __forceinline__ void stsA(uint32_t abase, const float4* av) {
    int t = threadIdx.x;
#pragma unroll
    for (int n = 0; n < 4; n++) {
        int i = t + n * 256;
        int r = i >> 4, q = i & 15;
        float4 x = av[n];
        float hx = __bfloat162float(__float2bfloat16_rn(x.x));
        float hy = __bfloat162float(__float2bfloat16_rn(x.y));
        float hz = __bfloat162float(__float2bfloat16_rn(x.z));
        float hw = __bfloat162float(__float2bfloat16_rn(x.w));
        uint32_t so = sw128((uint32_t)(r * 128 + q * 8));
        asm volatile("st.shared.v2.b32 [%0], {%1, %2};" ::
                     "r"(abase + so), "r"(pb2(hx, hy)), "r"(pb2(hz, hw)) : "memory");
        asm volatile("st.shared.v2.b32 [%0], {%1, %2};" ::
                     "r"(abase + 8192 + so),
                     "r"(pb2(x.x - hx, x.y - hy)), "r"(pb2(x.z - hz, x.w - hw)) : "memory");
    }
}

// B chunk 0 already prefetched into buf0 during phase A.
__device__ void logits_phase(char* smb, uint32_t base, int par) {
    const int t  = threadIdx.x;
    const int wid = t >> 5, ln = t & 31;
    const int v0 = blockIdx.x * 256;
    const float* h = g_hbuf[par ^ 1];
    float* bias_sm = (float*)(smb + OFF_BIAS);

    float acc[4][4][4];
#pragma unroll
    for (int a = 0; a < 4; a++)
#pragma unroll
        for (int b = 0; b < 4; b++)
#pragma unroll
            for (int cc = 0; cc < 4; cc++) acc[a][b][cc] = 0.f;

    {
        float4 av[4];
        ldgA(h, 0, av);
        stsA(base, av);
    }

    const int ti = ln >> 3, li = ln & 7;
    const int aml = (ti & 1) * 8 + li, ak = ti >> 1;
    const int bnl = (ti >> 1) * 8 + li, bk = ti & 1;
    const int nbase = wid * 32;

    float4 av[4];
    for (int c = 0; c < NCHUNK; c++) {
        int b = c & 1;
        if (c < NCHUNK - 1) {
            issueB(base + OFF_B + (b ^ 1) * 65536, c + 1, v0);
            CP_COMMIT();
            ldgA(h, c + 1, av);
            CP_WAIT(1);
        } else {
            CP_WAIT(0);
        }
        __syncthreads();

        uint32_t Ahi = base + b * 16384, Alo = Ahi + 8192;
        uint32_t Bhi = base + OFF_B + b * 65536, Blo = Bhi + 32768;
#pragma unroll
        for (int ks = 0; ks < 4; ks++) {
            uint32_t ah[4][4], al[4][4], bh[4][2], bl[4][2];
#pragma unroll
            for (int mt = 0; mt < 4; mt++) {
                uint32_t off = sw128((uint32_t)((mt * 16 + aml) * 128 + ks * 32 + ak * 16));
                ldsm4(ah[mt], Ahi + off);
                ldsm4(al[mt], Alo + off);
            }
#pragma unroll
            for (int ng = 0; ng < 2; ng++) {
                uint32_t off = sw128((uint32_t)((nbase + ng * 16 + bnl) * 128 + ks * 32 + bk * 16));
                uint32_t r4[4];
                ldsm4(r4, Bhi + off);
                bh[ng * 2][0] = r4[0]; bh[ng * 2][1] = r4[1];
                bh[ng * 2 + 1][0] = r4[2]; bh[ng * 2 + 1][1] = r4[3];
                ldsm4(r4, Blo + off);
                bl[ng * 2][0] = r4[0]; bl[ng * 2][1] = r4[1];
                bl[ng * 2 + 1][0] = r4[2]; bl[ng * 2 + 1][1] = r4[3];
            }
#pragma unroll
            for (int mt = 0; mt < 4; mt++)
#pragma unroll
                for (int nt = 0; nt < 4; nt++) {
                    mma16816(acc[mt][nt], ah[mt], bh[nt]);
                    mma16816(acc[mt][nt], ah[mt], bl[nt]);
                    mma16816(acc[mt][nt], al[mt], bh[nt]);
                }
        }
        if (c < NCHUNK - 1) stsA(base + (b ^ 1) * 16384, av);
        __syncthreads();
    }

    // epilogue: frags + bias -> TILE (buf1 region, dead after mainloop)
    float* tile = (float*)(smb + OFF_TILE);
    const int g = ln >> 2, tg2 = (ln & 3) * 2;
#pragma unroll
    for (int mt = 0; mt < 4; mt++)
#pragma unroll
        for (int nt = 0; nt < 4; nt++) {
            int row0 = mt * 16 + g;
            int col  = nbase + nt * 8 + tg2;
            float b0 = bias_sm[col], b1 = bias_sm[col + 1];
            tile[row0 * 256 + col]           = acc[mt][nt][0] + b0;
            tile[row0 * 256 + col + 1]       = acc[mt][nt][1] + b1;
            tile[(row0 + 8) * 256 + col]     = acc[mt][nt][2] + b0;
            tile[(row0 + 8) * 256 + col + 1] = acc[mt][nt][3] + b1;
        }
    __syncthreads();

    // row scan (argmax + softmax partials); tile stays in smem for finalize
#pragma unroll 1
    for (int i8 = 0; i8 < 8; i8++) {
        int r = wid * 8 + i8;
        float4 va = *(const float4*)&tile[r * 256 + ln * 8];
        float4 vb = *(const float4*)&tile[r * 256 + ln * 8 + 4];
        float vals[8] = {va.x, va.y, va.z, va.w, vb.x, vb.y, vb.z, vb.w};
        int c0 = v0 + ln * 8;

        float vm = vals[0]; int vi = c0;
#pragma unroll
        for (int j = 1; j < 8; j++)
            if (vals[j] > vm) { vm = vals[j]; vi = c0 + j; }

        unsigned long long key =
            ((unsigned long long)fmono(vm) << 32) |
            (unsigned int)(~(unsigned int)vi);
#pragma unroll
        for (int o = 16; o >= 1; o >>= 1) {
            unsigned long long other = __shfl_xor_sync(0xFFFFFFFFu, key, o);
            if (other > key) key = other;
        }
        float mrow = fmono_inv((unsigned int)(key >> 32));

        float s = 0.f;
#pragma unroll
        for (int j = 0; j < 8; j++) s += fexp(vals[j] - mrow);
#pragma unroll
        for (int o = 16; o >= 1; o >>= 1)
            s += __shfl_xor_sync(0xFFFFFFFFu, s, o);

        if (ln == 0) {
            atomicMax(&g_amax[par][r], key);
            g_part[par][r][blockIdx.x] = make_float2(mrow, s);
        }
    }
    __syncthreads();
}

// ---------------- the persistent decode kernel (single launch) ----------------
__global__ void __launch_bounds__(256, 1)
k_main(const float* __restrict__ q_att,
       const float* __restrict__ emb,
       const float* __restrict__ W_ih,
       const float* __restrict__ W_hh,
       const float* __restrict__ b_ih,
       const float* __restrict__ b_hh,
       const float* __restrict__ out_W,
       const float* __restrict__ out_b,
       const int*   __restrict__ qix,
       float* __restrict__ out, int steps) {
    extern __shared__ __align__(16) char smem_raw[];
    uint32_t raw  = smem_u32(smem_raw);
    uint32_t base = (raw + 1023) & ~1023u;
    char* smb = smem_raw + (base - raw);
    const int t = threadIdx.x;

    // ---- prologue: W split (all CTAs) + state init (CTA 0) ----
    {
        size_t n4 = (size_t)VQ * HID / 4;
        uint2* whi = (uint2*)g_Whi;
        uint2* wlo = (uint2*)g_Wlo;
        for (size_t i = (size_t)blockIdx.x * 256 + t; i < n4; i += (size_t)NCTA * 256) {
            float4 x = ((const float4*)out_W)[i];
            float hx = __bfloat162float(__float2bfloat16_rn(x.x));
            float hy = __bfloat162float(__float2bfloat16_rn(x.y));
            float hz = __bfloat162float(__float2bfloat16_rn(x.z));
            float hw = __bfloat162float(__float2bfloat16_rn(x.w));
            whi[i] = make_uint2(pb2(hx, hy), pb2(hz, hw));
            wlo[i] = make_uint2(pb2(x.x - hx, x.y - hy), pb2(x.z - hz, x.w - hw));
        }
        if (blockIdx.x == 0) {
            if (t < BSZ) {
                g_amax[1][t] = (unsigned long long)(unsigned int)(~(unsigned int)SOS);
                g_amax[0][t] = 0ull;
            }
            for (int i = t; i < BSZ * HID; i += 256) {
                g_hbuf[0][i] = q_att[i];
                g_c[i] = 0.f;
            }
        }
        ((float*)(smb + OFF_BIAS))[t] = out_b[blockIdx.x * 256 + t];
    }
    gsync();

    for (int s = 0; s < steps; s++) {
        int par = s & 1;

        // prefetch B chunk 0 into buf0 (doesn't touch TILE in buf1)
        issueB(base + OFF_B, 0, blockIdx.x * 256);
        CP_COMMIT();

        lstm_phase(smb, emb, W_ih, W_hh, b_ih, b_hh, qix, par);
        if (s > 0) finalize_tile(smb, out, s - 1, steps);
        gsync();

        logits_phase(smb, base, par);
        gsync();
    }

    finalize_tile(smb, out, steps - 1, steps);
}

// ---------------- launch ----------------
extern "C" void kernel_launch(void* const* d_in, const int* in_sizes, int n_in,
                              void* d_out, int out_size) {
    (void)in_sizes; (void)n_in;
    const float* q_att = (const float*)d_in[1];
    const float* emb   = (const float*)d_in[2];
    const float* W_ih  = (const float*)d_in[3];
    const float* W_hh  = (const float*)d_in[4];
    const float* b_ih  = (const float*)d_in[5];
    const float* b_hh  = (const float*)d_in[6];
    const float* out_W = (const float*)d_in[7];
    const float* out_b = (const float*)d_in[8];
    const int*   qix   = (const int*)d_in[9];

    int steps = out_size / (BSZ * VQ);  // 33

    cudaFuncSetAttribute(k_main, cudaFuncAttributeMaxDynamicSharedMemorySize,
                         SMEM_REQ);

    k_main<<<NCTA, 256, SMEM_REQ>>>(q_att, emb, W_ih, W_hh, b_ih, b_hh,
                                    out_W, out_b, qix, (float*)d_out, steps);
}

// round 9
// speedup vs baseline: 2.8263x; 1.0139x over previous
#include <cuda_runtime.h>
#include <cuda_bf16.h>
#include <math.h>
#include <stdint.h>

#define BSZ 64
#define HID 512
#define EMB 300
#define VQ  32000
#define SOS 1
#define NBLK 125
#define NCTA 125
#define NCHUNK 8

// dynamic smem layout (relative to 1024-aligned base)
//   A bufs: 0..32K ; B buf b at OFF_B + b*65536 (hi), +32768 (lo)
//   buf0: 32768..98304   buf1: 98304..163840
//   TILE aliases buf1; written by phase-B epilogue (buf1 dead after mainloop),
//   read by finalize_tile next step, then overwritten by chunk-1 prefetch.
#define OFF_B    32768
#define OFF_TILE 98304
#define OFF_BIAS 163840
#define OFF_RED  164864
#define SMEM_REQ 166912
// lstm-phase aliases (low region, < 17 KB)
#define LS_XH  0
#define LS_W   8704
#define LS_G   11264
#define LS_BS  16704
#define LS_IDX 16800

// ---------------- persistent device state ----------------
__device__ float g_hbuf[2][BSZ * HID];
__device__ float g_c[BSZ * HID];
__device__ unsigned long long g_amax[2][BSZ];
__device__ float2 g_part[2][BSZ][NBLK];
__device__ __nv_bfloat16 g_Whi[(size_t)VQ * HID];
__device__ __nv_bfloat16 g_Wlo[(size_t)VQ * HID];
__device__ unsigned int g_bcnt;    // monotonic barrier arrival counter
__device__ unsigned int g_epoch;   // launches completed (CTA0 bumps at end)

// ---------------- helpers ----------------
__device__ __forceinline__ unsigned int fmono(float f) {
    unsigned int u = __float_as_uint(f);
    return (u & 0x80000000u) ? ~u : (u | 0x80000000u);
}
__device__ __forceinline__ float fmono_inv(unsigned int u) {
    return (u & 0x80000000u) ? __uint_as_float(u & 0x7FFFFFFFu)
                             : __uint_as_float(~u);
}
__device__ __forceinline__ float fexp(float x) {
    x = fmaxf(x, -80.0f);
    float t = fmaf(x, 1.4426950408889634f, 12582912.0f);
    float i = t - 12582912.0f;
    float f = fmaf(x, 1.4426950408889634f, -i);
    float p = 1.3333558e-3f;
    p = fmaf(p, f, 9.6181291e-3f);
    p = fmaf(p, f, 5.5504110e-2f);
    p = fmaf(p, f, 2.4022651e-1f);
    p = fmaf(p, f, 6.9314718e-1f);
    p = fmaf(p, f, 1.0f);
    int ei = __float_as_int(t) - 0x4B400000;
    float sc = __int_as_float((ei + 127) << 23);
    return sc * p;
}
__device__ __forceinline__ uint32_t smem_u32(const void* p) {
    uint32_t a;
    asm("{ .reg .u64 t; cvta.to.shared.u64 t, %1; cvt.u32.u64 %0, t; }"
        : "=r"(a) : "l"(p));
    return a;
}
__device__ __forceinline__ uint32_t sw128(uint32_t o) { return o ^ ((o >> 3) & 0x70); }
__device__ __forceinline__ uint32_t pb2(float a, float b) {
    __nv_bfloat162 t = __floats2bfloat162_rn(a, b);
    return *reinterpret_cast<uint32_t*>(&t);
}
__device__ __forceinline__ void st_cs4(float* p, float4 x) {
    asm volatile("st.global.cs.v4.f32 [%0], {%1, %2, %3, %4};"
                 :: "l"(p), "f"(x.x), "f"(x.y), "f"(x.z), "f"(x.w) : "memory");
}

// grid barrier: fire-and-forget red + monotonic target (replay-safe, no reset)
__device__ __forceinline__ void gsync(unsigned int target) {
    __syncthreads();
    if (threadIdx.x == 0) {
        asm volatile("red.release.gpu.global.add.u32 [%0], 1;"
                     :: "l"(&g_bcnt) : "memory");
        unsigned int v;
        do {
            __nanosleep(32);
            asm volatile("ld.global.acquire.gpu.b32 %0, [%1];"
                         : "=r"(v) : "l"(&g_bcnt) : "memory");
        } while ((int)(v - target) < 0);
    }
    __syncthreads();
}

#define CP_ASYNC16(dst, src) \
    asm volatile("cp.async.cg.shared.global [%0], [%1], 16;" :: "r"(dst), "l"(src) : "memory")
#define CP_COMMIT() asm volatile("cp.async.commit_group;" ::: "memory")
#define CP_WAIT(n)  asm volatile("cp.async.wait_group %0;" :: "n"(n) : "memory")

__device__ __forceinline__ void ldsm4(uint32_t* r, uint32_t addr) {
    asm volatile("ldmatrix.sync.aligned.m8n8.x4.shared.b16 {%0,%1,%2,%3}, [%4];"
                 : "=r"(r[0]), "=r"(r[1]), "=r"(r[2]), "=r"(r[3]) : "r"(addr));
}
__device__ __forceinline__ void mma16816(float* d, const uint32_t* a, const uint32_t* b) {
    asm volatile(
        "mma.sync.aligned.m16n8k16.row.col.f32.bf16.bf16.f32 "
        "{%0,%1,%2,%3}, {%4,%5,%6,%7}, {%8,%9}, {%0,%1,%2,%3};"
        : "+f"(d[0]), "+f"(d[1]), "+f"(d[2]), "+f"(d[3])
        : "r"(a[0]), "r"(a[1]), "r"(a[2]), "r"(a[3]), "r"(b[0]), "r"(b[1]));
}

// ---------------- phase A1: LSTM on all 125 CTAs ----------------
__device__ void lstm_phase(char* smb,
                           const float* __restrict__ emb,
                           const float* __restrict__ W_ih,
                           const float* __restrict__ W_hh,
                           const float* __restrict__ b_ih,
                           const float* __restrict__ b_hh,
                           const int*   __restrict__ qix,
                           int par) {
    float (*xh)[68] = (float(*)[68])(smb + LS_XH);
    float (*ws)[20] = (float(*)[20])(smb + LS_W);
    float (*gs)[68] = (float(*)[68])(smb + LS_G);
    float* bs  = (float*)(smb + LS_BS);
    int* sidx  = (int*)(smb + LS_IDX);

    const int t  = threadIdx.x;
    const int i0 = blockIdx.x;
    const int NU = (i0 < 12) ? 5 : 4;
    const int NR = NU * 4;
    int u[5];
    u[0] = i0; u[1] = 125 + i0; u[2] = 250 + i0; u[3] = 375 + i0; u[4] = 500 + i0;

    const float* hin  = g_hbuf[par];
    float*       hout = g_hbuf[par ^ 1];

    if (t < BSZ) {
        unsigned long long key = __ldcg(&g_amax[par ^ 1][t]);
        sidx[t] = qix[~(unsigned int)(key & 0xFFFFFFFFull)];
    }
    if (i0 == 0 && t >= 64 && t < 128) g_amax[par][t - 64] = 0ull;
    if (t < NR) {
        int gr = (t & 3) * 512 + u[t >> 2];
        bs[t] = b_ih[gr] + b_hh[gr];
    }

    const int tx = t & 15, ty = t >> 4;
    const int m0 = ty * 4;
    const bool xt = (NR == 20) && (tx < 4);
    float acc[4]  = {0.f, 0.f, 0.f, 0.f};
    float acc2[4] = {0.f, 0.f, 0.f, 0.f};

    float xr[8], wr[3];
    const int lm = t >> 5, lk = t & 31;
    __syncthreads();

    // ---- phase 1: x = relu(emb[idx]) vs W_ih, K=300 ragged ----
    {
#pragma unroll
        for (int n = 0; n < 8; n++) {
            int m = lm + n * 8, k = lk;
            xr[n] = (k < EMB) ? fmaxf(__ldg(&emb[(size_t)sidx[m] * EMB + k]), 0.f) : 0.f;
        }
#pragma unroll
        for (int n = 0; n < 3; n++) {
            int i = t + n * 256;
            if (i < NR * 32) {
                int r = i >> 5, kk = i & 31;
                int gr = (r & 3) * 512 + u[r >> 2];
                wr[n] = (kk < EMB) ? W_ih[(size_t)gr * EMB + kk] : 0.f;
            }
        }
        for (int k0 = 0; k0 < 320; k0 += 32) {
#pragma unroll
            for (int n = 0; n < 8; n++) xh[lk][lm + n * 8] = xr[n];
#pragma unroll
            for (int n = 0; n < 3; n++) {
                int i = t + n * 256;
                if (i < NR * 32) ws[i & 31][i >> 5] = wr[n];
            }
            __syncthreads();
            if (k0 + 32 < 320) {
                int k0n = k0 + 32;
#pragma unroll
                for (int n = 0; n < 8; n++) {
                    int m = lm + n * 8, k = k0n + lk;
                    xr[n] = (k < EMB) ? fmaxf(__ldg(&emb[(size_t)sidx[m] * EMB + k]), 0.f) : 0.f;
                }
#pragma unroll
                for (int n = 0; n < 3; n++) {
                    int i = t + n * 256;
                    if (i < NR * 32) {
                        int r = i >> 5, kk = i & 31;
                        int k = k0n + kk;
                        int gr = (r & 3) * 512 + u[r >> 2];
                        wr[n] = (k < EMB) ? W_ih[(size_t)gr * EMB + k] : 0.f;
                    }
                }
            }
#pragma unroll
            for (int kk = 0; kk < 32; kk++) {
                float4 a = *(const float4*)&xh[kk][m0];
                float w = ws[kk][tx];
                acc[0] = fmaf(w, a.x, acc[0]);
                acc[1] = fmaf(w, a.y, acc[1]);
                acc[2] = fmaf(w, a.z, acc[2]);
                acc[3] = fmaf(w, a.w, acc[3]);
                if (xt) {
                    float w2 = ws[kk][16 + tx];
                    acc2[0] = fmaf(w2, a.x, acc2[0]);
                    acc2[1] = fmaf(w2, a.y, acc2[1]);
                    acc2[2] = fmaf(w2, a.z, acc2[2]);
                    acc2[3] = fmaf(w2, a.w, acc2[3]);
                }
            }
            __syncthreads();
        }
    }

    // ---- phase 2: h vs W_hh, K=512 ----
    {
#pragma unroll
        for (int n = 0; n < 8; n++)
            xr[n] = __ldcg(&hin[(lm + n * 8) * HID + lk]);
#pragma unroll
        for (int n = 0; n < 3; n++) {
            int i = t + n * 256;
            if (i < NR * 32) {
                int r = i >> 5, kk = i & 31;
                int gr = (r & 3) * 512 + u[r >> 2];
                wr[n] = W_hh[(size_t)gr * HID + kk];
            }
        }
        for (int k0 = 0; k0 < HID; k0 += 32) {
#pragma unroll
            for (int n = 0; n < 8; n++) xh[lk][lm + n * 8] = xr[n];
#pragma unroll
            for (int n = 0; n < 3; n++) {
                int i = t + n * 256;
                if (i < NR * 32) ws[i & 31][i >> 5] = wr[n];
            }
            __syncthreads();
            if (k0 + 32 < HID) {
                int k0n = k0 + 32;
#pragma unroll
                for (int n = 0; n < 8; n++)
                    xr[n] = __ldcg(&hin[(lm + n * 8) * HID + k0n + lk]);
#pragma unroll
                for (int n = 0; n < 3; n++) {
                    int i = t + n * 256;
                    if (i < NR * 32) {
                        int r = i >> 5, kk = i & 31;
                        int gr = (r & 3) * 512 + u[r >> 2];
                        wr[n] = W_hh[(size_t)gr * HID + k0n + kk];
                    }
                }
            }
#pragma unroll
            for (int kk = 0; kk < 32; kk++) {
                float4 a = *(const float4*)&xh[kk][m0];
                float w = ws[kk][tx];
                acc[0] = fmaf(w, a.x, acc[0]);
                acc[1] = fmaf(w, a.y, acc[1]);
                acc[2] = fmaf(w, a.z, acc[2]);
                acc[3] = fmaf(w, a.w, acc[3]);
                if (xt) {
                    float w2 = ws[kk][16 + tx];
                    acc2[0] = fmaf(w2, a.x, acc2[0]);
                    acc2[1] = fmaf(w2, a.y, acc2[1]);
                    acc2[2] = fmaf(w2, a.z, acc2[2]);
                    acc2[3] = fmaf(w2, a.w, acc2[3]);
                }
            }
            __syncthreads();
        }
    }

    // gates -> smem (+bias)
    {
        float bb = bs[tx];
        gs[tx][m0]     = acc[0] + bb;
        gs[tx][m0 + 1] = acc[1] + bb;
        gs[tx][m0 + 2] = acc[2] + bb;
        gs[tx][m0 + 3] = acc[3] + bb;
        if (xt) {
            float b2 = bs[16 + tx];
            gs[16 + tx][m0]     = acc2[0] + b2;
            gs[16 + tx][m0 + 1] = acc2[1] + b2;
            gs[16 + tx][m0 + 2] = acc2[2] + b2;
            gs[16 + tx][m0 + 3] = acc2[3] + b2;
        }
    }
    __syncthreads();

    for (int p = t; p < NU * 64; p += 256) {
        int uu = p >> 6, m = p & 63;
        float gi = gs[uu * 4 + 0][m];
        float gf = gs[uu * 4 + 1][m];
        float gg = gs[uu * 4 + 2][m];
        float go = gs[uu * 4 + 3][m];
        int ci = m * HID + u[uu];
        float c  = __ldcg(&g_c[ci]);
        float si = 1.f / (1.f + expf(-gi));
        float sf = 1.f / (1.f + expf(-gf));
        float so = 1.f / (1.f + expf(-go));
        float nc = sf * c + si * tanhf(gg);
        float nh = so * tanhf(nc);
        g_c[ci]  = nc;
        hout[ci] = nh;
    }
    __syncthreads();
}

// ---------------- phase A2: finalize tile in smem -> out ----------------
__device__ void finalize_tile(char* smb, float* __restrict__ out,
                              int sprev, int steps) {
    const int t = threadIdx.x;
    const int w = t >> 5, ln = t & 31;
    const int pp = sprev & 1;
    const int v0 = blockIdx.x * 256;
    float* tile = (float*)(smb + OFF_TILE);
    float* lse_sm = (float*)(smb + OFF_RED);
    __syncthreads();

    for (int r = w; r < BSZ; r += 8) {
        float2 pv[4];
#pragma unroll
        for (int i = 0; i < 4; i++) {
            int idx = ln + i * 32;
            pv[i] = (idx < NBLK) ? __ldcg(&g_part[pp][r][idx])
                                 : make_float2(-3.4e38f, 0.f);
        }
        float m = fmaxf(fmaxf(pv[0].x, pv[1].x), fmaxf(pv[2].x, pv[3].x));
#pragma unroll
        for (int o = 16; o >= 1; o >>= 1)
            m = fmaxf(m, __shfl_xor_sync(0xFFFFFFFFu, m, o));
        float s = pv[0].y * fexp(pv[0].x - m) + pv[1].y * fexp(pv[1].x - m)
                + pv[2].y * fexp(pv[2].x - m) + pv[3].y * fexp(pv[3].x - m);
#pragma unroll
        for (int o = 16; o >= 1; o >>= 1)
            s += __shfl_xor_sync(0xFFFFFFFFu, s, o);
        if (ln == 0) lse_sm[r] = m + logf(s);
    }
    __syncthreads();

#pragma unroll 4
    for (int it = 0; it < 16; it++) {
        int idx = t + it * 256;
        int r  = idx >> 6;
        int c4 = idx & 63;
        float4 x = *(const float4*)&tile[r * 256 + c4 * 4];
        float lse = lse_sm[r];
        x.x -= lse; x.y -= lse; x.z -= lse; x.w -= lse;
        st_cs4(out + ((size_t)r * steps + sprev) * VQ + v0 + c4 * 4, x);
    }
    __syncthreads();
}

// ---------------- phase B: logits GEMM + fused epilogue ----------------
__device__ __forceinline__ void issueB(uint32_t bbase, int c, int v0) {
    int t = threadIdx.x;
#pragma unroll
    for (int n = 0; n < 8; n++) {
        int i = t + n * 256;
        int r = i >> 3, j = i & 7;
        size_t g = (size_t)(v0 + r) * HID + (size_t)c * 64 + j * 8;
        uint32_t so = sw128((uint32_t)(r * 128 + j * 16));
        CP_ASYNC16(bbase + so, g_Whi + g);
        CP_ASYNC16(bbase + 32768 + so, g_Wlo + g);
    }
}
__device__ __forceinline__ void ldgA(const float* h, int c, float4* av) {
    int t = threadIdx.x;
#pragma unroll
    for (int n = 0; n < 4; n++) {
        int i = t + n * 256;
        int r = i >> 4, q = i & 15;
        av[n] = __ldcg((const float4*)&h[r * HID + c * 64 + q * 4]);
    }
}
__device__ __forceinline__ void stsA(uint32_t abase, const float4* av) {
    int t = threadIdx.x;
#pragma unroll
    for (int n = 0; n < 4; n++) {
        int i = t + n * 256;
        int r = i >> 4, q = i & 15;
        float4 x = av[n];
        float hx = __bfloat162float(__float2bfloat16_rn(x.x));
        float hy = __bfloat162float(__float2bfloat16_rn(x.y));
        float hz = __bfloat162float(__float2bfloat16_rn(x.z));
        float hw = __bfloat162float(__float2bfloat16_rn(x.w));
        uint32_t so = sw128((uint32_t)(r * 128 + q * 8));
        asm volatile("st.shared.v2.b32 [%0], {%1, %2};" ::
                     "r"(abase + so), "r"(pb2(hx, hy)), "r"(pb2(hz, hw)) : "memory");
        asm volatile("st.shared.v2.b32 [%0], {%1, %2};" ::
                     "r"(abase + 8192 + so),
                     "r"(pb2(x.x - hx, x.y - hy)), "r"(pb2(x.z - hz, x.w - hw)) : "memory");
    }
}

// B chunks 0 AND 1 already prefetched (two cp.async groups pending).
__device__ void logits_phase(char* smb, uint32_t base, int par) {
    const int t  = threadIdx.x;
    const int wid = t >> 5, ln = t & 31;
    const int v0 = blockIdx.x * 256;
    const float* h = g_hbuf[par ^ 1];
    float* bias_sm = (float*)(smb + OFF_BIAS);

    float acc[4][4][4];
#pragma unroll
    for (int a = 0; a < 4; a++)
#pragma unroll
        for (int b = 0; b < 4; b++)
#pragma unroll
            for (int cc = 0; cc < 4; cc++) acc[a][b][cc] = 0.f;

    {
        float4 av[4];
        ldgA(h, 0, av);
        stsA(base, av);
    }

    const int ti = ln >> 3, li = ln & 7;
    const int aml = (ti & 1) * 8 + li, ak = ti >> 1;
    const int bnl = (ti >> 1) * 8 + li, bk = ti & 1;
    const int nbase = wid * 32;

    float4 av[4];
    for (int c = 0; c < NCHUNK; c++) {
        int b = c & 1;
        if (c >= 1 && c < NCHUNK - 1) {
            issueB(base + OFF_B + (b ^ 1) * 65536, c + 1, v0);
            CP_COMMIT();
        }
        if (c < NCHUNK - 1) {
            ldgA(h, c + 1, av);
            CP_WAIT(1);
        } else {
            CP_WAIT(0);
        }
        __syncthreads();

        uint32_t Ahi = base + b * 16384, Alo = Ahi + 8192;
        uint32_t Bhi = base + OFF_B + b * 65536, Blo = Bhi + 32768;
#pragma unroll
        for (int ks = 0; ks < 4; ks++) {
            uint32_t ah[4][4], al[4][4], bh[4][2], bl[4][2];
#pragma unroll
            for (int mt = 0; mt < 4; mt++) {
                uint32_t off = sw128((uint32_t)((mt * 16 + aml) * 128 + ks * 32 + ak * 16));
                ldsm4(ah[mt], Ahi + off);
                ldsm4(al[mt], Alo + off);
            }
#pragma unroll
            for (int ng = 0; ng < 2; ng++) {
                uint32_t off = sw128((uint32_t)((nbase + ng * 16 + bnl) * 128 + ks * 32 + bk * 16));
                uint32_t r4[4];
                ldsm4(r4, Bhi + off);
                bh[ng * 2][0] = r4[0]; bh[ng * 2][1] = r4[1];
                bh[ng * 2 + 1][0] = r4[2]; bh[ng * 2 + 1][1] = r4[3];
                ldsm4(r4, Blo + off);
                bl[ng * 2][0] = r4[0]; bl[ng * 2][1] = r4[1];
                bl[ng * 2 + 1][0] = r4[2]; bl[ng * 2 + 1][1] = r4[3];
            }
#pragma unroll
            for (int mt = 0; mt < 4; mt++)
#pragma unroll
                for (int nt = 0; nt < 4; nt++) {
                    mma16816(acc[mt][nt], ah[mt], bh[nt]);
                    mma16816(acc[mt][nt], ah[mt], bl[nt]);
                    mma16816(acc[mt][nt], al[mt], bh[nt]);
                }
        }
        if (c < NCHUNK - 1) stsA(base + (b ^ 1) * 16384, av);
        __syncthreads();
    }

    // epilogue: frags + bias -> TILE (buf1 region, dead after mainloop)
    float* tile = (float*)(smb + OFF_TILE);
    const int g = ln >> 2, tg2 = (ln & 3) * 2;
#pragma unroll
    for (int mt = 0; mt < 4; mt++)
#pragma unroll
        for (int nt = 0; nt < 4; nt++) {
            int row0 = mt * 16 + g;
            int col  = nbase + nt * 8 + tg2;
            float b0 = bias_sm[col], b1 = bias_sm[col + 1];
            tile[row0 * 256 + col]           = acc[mt][nt][0] + b0;
            tile[row0 * 256 + col + 1]       = acc[mt][nt][1] + b1;
            tile[(row0 + 8) * 256 + col]     = acc[mt][nt][2] + b0;
            tile[(row0 + 8) * 256 + col + 1] = acc[mt][nt][3] + b1;
        }
    __syncthreads();

    // row scan (argmax + softmax partials); tile stays resident for finalize
#pragma unroll 1
    for (int i8 = 0; i8 < 8; i8++) {
        int r = wid * 8 + i8;
        float4 va = *(const float4*)&tile[r * 256 + ln * 8];
        float4 vb = *(const float4*)&tile[r * 256 + ln * 8 + 4];
        float vals[8] = {va.x, va.y, va.z, va.w, vb.x, vb.y, vb.z, vb.w};
        int c0 = v0 + ln * 8;

        float vm = vals[0]; int vi = c0;
#pragma unroll
        for (int j = 1; j < 8; j++)
            if (vals[j] > vm) { vm = vals[j]; vi = c0 + j; }

        unsigned long long key =
            ((unsigned long long)fmono(vm) << 32) |
            (unsigned int)(~(unsigned int)vi);
#pragma unroll
        for (int o = 16; o >= 1; o >>= 1) {
            unsigned long long other = __shfl_xor_sync(0xFFFFFFFFu, key, o);
            if (other > key) key = other;
        }
        float mrow = fmono_inv((unsigned int)(key >> 32));

        float s = 0.f;
#pragma unroll
        for (int j = 0; j < 8; j++) s += fexp(vals[j] - mrow);
#pragma unroll
        for (int o = 16; o >= 1; o >>= 1)
            s += __shfl_xor_sync(0xFFFFFFFFu, s, o);

        if (ln == 0) {
            atomicMax(&g_amax[par][r], key);
            g_part[par][r][blockIdx.x] = make_float2(mrow, s);
        }
    }
    __syncthreads();
}

// ---------------- the persistent decode kernel (single launch) ----------------
__global__ void __launch_bounds__(256, 1)
k_main(const float* __restrict__ q_att,
       const float* __restrict__ emb,
       const float* __restrict__ W_ih,
       const float* __restrict__ W_hh,
       const float* __restrict__ b_ih,
       const float* __restrict__ b_hh,
       const float* __restrict__ out_W,
       const float* __restrict__ out_b,
       const int*   __restrict__ qix,
       float* __restrict__ out, int steps) {
    extern __shared__ __align__(16) char smem_raw[];
    uint32_t raw  = smem_u32(smem_raw);
    uint32_t base = (raw + 1023) & ~1023u;
    char* smb = smem_raw + (base - raw);
    const int t = threadIdx.x;
    const int v0cta = blockIdx.x * 256;

    // epoch base for monotonic barrier targets (t0 only; others pass 0)
    unsigned int Eval = 0, ebase = 0;
    int nb = 0;
    const unsigned int NBAR = (unsigned int)(1 + 2 * steps);
    if (t == 0) {
        asm volatile("ld.global.acquire.gpu.b32 %0, [%1];"
                     : "=r"(Eval) : "l"(&g_epoch));
        ebase = Eval * NBAR * NCTA;
    }

    // ---- prologue: W split (all CTAs) + state init (CTA 0) ----
    {
        size_t n4 = (size_t)VQ * HID / 4;
        uint2* whi = (uint2*)g_Whi;
        uint2* wlo = (uint2*)g_Wlo;
        for (size_t i = (size_t)blockIdx.x * 256 + t; i < n4; i += (size_t)NCTA * 256) {
            float4 x = ((const float4*)out_W)[i];
            float hx = __bfloat162float(__float2bfloat16_rn(x.x));
            float hy = __bfloat162float(__float2bfloat16_rn(x.y));
            float hz = __bfloat162float(__float2bfloat16_rn(x.z));
            float hw = __bfloat162float(__float2bfloat16_rn(x.w));
            whi[i] = make_uint2(pb2(hx, hy), pb2(hz, hw));
            wlo[i] = make_uint2(pb2(x.x - hx, x.y - hy), pb2(x.z - hz, x.w - hw));
        }
        if (blockIdx.x == 0) {
            if (t < BSZ) {
                g_amax[1][t] = (unsigned long long)(unsigned int)(~(unsigned int)SOS);
                g_amax[0][t] = 0ull;
            }
            for (int i = t; i < BSZ * HID; i += 256) {
                g_hbuf[0][i] = q_att[i];
                g_c[i] = 0.f;
            }
        }
        ((float*)(smb + OFF_BIAS))[t] = out_b[v0cta + t];
    }
    ++nb; gsync(ebase + nb * NCTA);

    for (int s = 0; s < steps; s++) {
        int par = s & 1;

        // prefetch B chunk 0 into buf0 (TILE in buf1 untouched)
        issueB(base + OFF_B, 0, v0cta);
        CP_COMMIT();

        lstm_phase(smb, emb, W_ih, W_hh, b_ih, b_hh, qix, par);
        if (s > 0) finalize_tile(smb, out, s - 1, steps);

        // TILE consumed -> prefetch B chunk 1 into buf1
        issueB(base + OFF_B + 65536, 1, v0cta);
        CP_COMMIT();

        ++nb; gsync(ebase + nb * NCTA);

        logits_phase(smb, base, par);
        ++nb; gsync(ebase + nb * NCTA);
    }

    // bump epoch for the next launch (after the last barrier; pollers use counts only)
    if (blockIdx.x == 0 && t == 0)
        *((volatile unsigned int*)&g_epoch) = Eval + 1;

    finalize_tile(smb, out, steps - 1, steps);
}

// ---------------- launch ----------------
extern "C" void kernel_launch(void* const* d_in, const int* in_sizes, int n_in,
                              void* d_out, int out_size) {
    (void)in_sizes; (void)n_in;
    const float* q_att = (const float*)d_in[1];
    const float* emb   = (const float*)d_in[2];
    const float* W_ih  = (const float*)d_in[3];
    const float* W_hh  = (const float*)d_in[4];
    const float* b_ih  = (const float*)d_in[5];
    const float* b_hh  = (const float*)d_in[6];
    const float* out_W = (const float*)d_in[7];
    const float* out_b = (const float*)d_in[8];
    const int*   qix   = (const int*)d_in[9];

    int steps = out_size / (BSZ * VQ);  // 33

    cudaFuncSetAttribute(k_main, cudaFuncAttributeMaxDynamicSharedMemorySize,
                         SMEM_REQ);

    k_main<<<NCTA, 256, SMEM_REQ>>>(q_att, emb, W_ih, W_hh, b_ih, b_hh,
                                    out_W, out_b, qix, (float*)d_out, steps);
}

// round 10
// speedup vs baseline: 2.8441x; 1.0063x over previous
#include <cuda_runtime.h>
#include <cuda_bf16.h>
#include <math.h>
#include <stdint.h>

#define BSZ 64
#define HID 512
#define EMB 300
#define VQ  32000
#define SOS 1
#define NBLK 125
#define NCTA 125
#define NCHUNK 8

// dynamic smem layout (relative to 1024-aligned base)
//   A bufs: 0..32K ; B buf b at OFF_B + b*65536 (hi), +32768 (lo)
//   buf0: 32768..98304   buf1: 98304..163840
//   TILE aliases buf1; written by phase-B epilogue (buf1 dead after mainloop),
//   read by finalize_tile next step, then overwritten by chunk-1 prefetch.
#define OFF_B    32768
#define OFF_TILE 98304
#define OFF_BIAS 163840
#define OFF_RED  164864
#define SMEM_REQ 166912
// lstm-phase aliases (low region, < 17 KB)
#define LS_XH  0
#define LS_W   8704
#define LS_G   11264
#define LS_BS  16704
#define LS_IDX 16800

// ---------------- persistent device state ----------------
__device__ float g_hbuf[2][BSZ * HID];
__device__ float g_c[BSZ * HID];
__device__ unsigned long long g_amax[2][BSZ];
__device__ float2 g_part[2][BSZ][NBLK];
__device__ __nv_bfloat16 g_Whi[(size_t)VQ * HID];
__device__ __nv_bfloat16 g_Wlo[(size_t)VQ * HID];
__device__ unsigned int g_bcnt;    // monotonic barrier arrival counter
__device__ unsigned int g_epoch;   // launches completed (CTA0 bumps at end)

// ---------------- helpers ----------------
__device__ __forceinline__ unsigned int fmono(float f) {
    unsigned int u = __float_as_uint(f);
    return (u & 0x80000000u) ? ~u : (u | 0x80000000u);
}
__device__ __forceinline__ float fmono_inv(unsigned int u) {
    return (u & 0x80000000u) ? __uint_as_float(u & 0x7FFFFFFFu)
                             : __uint_as_float(~u);
}
__device__ __forceinline__ float fexp(float x) {
    x = fmaxf(x, -80.0f);
    float t = fmaf(x, 1.4426950408889634f, 12582912.0f);
    float i = t - 12582912.0f;
    float f = fmaf(x, 1.4426950408889634f, -i);
    float p = 1.3333558e-3f;
    p = fmaf(p, f, 9.6181291e-3f);
    p = fmaf(p, f, 5.5504110e-2f);
    p = fmaf(p, f, 2.4022651e-1f);
    p = fmaf(p, f, 6.9314718e-1f);
    p = fmaf(p, f, 1.0f);
    int ei = __float_as_int(t) - 0x4B400000;
    float sc = __int_as_float((ei + 127) << 23);
    return sc * p;
}
__device__ __forceinline__ uint32_t smem_u32(const void* p) {
    uint32_t a;
    asm("{ .reg .u64 t; cvta.to.shared.u64 t, %1; cvt.u32.u64 %0, t; }"
        : "=r"(a) : "l"(p));
    return a;
}
__device__ __forceinline__ uint32_t sw128(uint32_t o) { return o ^ ((o >> 3) & 0x70); }
__device__ __forceinline__ uint32_t pb2(float a, float b) {
    __nv_bfloat162 t = __floats2bfloat162_rn(a, b);
    return *reinterpret_cast<uint32_t*>(&t);
}
__device__ __forceinline__ void st_cs4(float* p, float4 x) {
    asm volatile("st.global.cs.v4.f32 [%0], {%1, %2, %3, %4};"
                 :: "l"(p), "f"(x.x), "f"(x.y), "f"(x.z), "f"(x.w) : "memory");
}

// grid barrier: fire-and-forget red + monotonic target (replay-safe, no reset)
__device__ __forceinline__ void gsync(unsigned int target) {
    __syncthreads();
    if (threadIdx.x == 0) {
        asm volatile("red.release.gpu.global.add.u32 [%0], 1;"
                     :: "l"(&g_bcnt) : "memory");
        unsigned int v;
        do {
            __nanosleep(32);
            asm volatile("ld.global.acquire.gpu.b32 %0, [%1];"
                         : "=r"(v) : "l"(&g_bcnt) : "memory");
        } while ((int)(v - target) < 0);
    }
    __syncthreads();
}

#define CP_ASYNC16(dst, src) \
    asm volatile("cp.async.cg.shared.global [%0], [%1], 16;" :: "r"(dst), "l"(src) : "memory")
#define CP_COMMIT() asm volatile("cp.async.commit_group;" ::: "memory")
#define CP_WAIT(n)  asm volatile("cp.async.wait_group %0;" :: "n"(n) : "memory")

__device__ __forceinline__ void ldsm4(uint32_t* r, uint32_t addr) {
    asm volatile("ldmatrix.sync.aligned.m8n8.x4.shared.b16 {%0,%1,%2,%3}, [%4];"
                 : "=r"(r[0]), "=r"(r[1]), "=r"(r[2]), "=r"(r[3]) : "r"(addr));
}
__device__ __forceinline__ void mma16816(float* d, const uint32_t* a, const uint32_t* b) {
    asm volatile(
        "mma.sync.aligned.m16n8k16.row.col.f32.bf16.bf16.f32 "
        "{%0,%1,%2,%3}, {%4,%5,%6,%7}, {%8,%9}, {%0,%1,%2,%3};"
        : "+f"(d[0]), "+f"(d[1]), "+f"(d[2]), "+f"(d[3])
        : "r"(a[0]), "r"(a[1]), "r"(a[2]), "r"(a[3]), "r"(b[0]), "r"(b[1]));
}

// ---------------- phase A1: LSTM on all 125 CTAs ----------------
__device__ void lstm_phase(char* smb,
                           const float* __restrict__ emb,
                           const float* __restrict__ W_ih,
                           const float* __restrict__ W_hh,
                           const float* __restrict__ b_ih,
                           const float* __restrict__ b_hh,
                           const int*   __restrict__ qix,
                           int par) {
    float (*xh)[68] = (float(*)[68])(smb + LS_XH);
    float (*ws)[20] = (float(*)[20])(smb + LS_W);
    float (*gs)[68] = (float(*)[68])(smb + LS_G);
    float* bs  = (float*)(smb + LS_BS);
    int* sidx  = (int*)(smb + LS_IDX);

    const int t  = threadIdx.x;
    const int i0 = blockIdx.x;
    const int NU = (i0 < 12) ? 5 : 4;
    const int NR = NU * 4;
    int u[5];
    u[0] = i0; u[1] = 125 + i0; u[2] = 250 + i0; u[3] = 375 + i0; u[4] = 500 + i0;

    const float* hin  = g_hbuf[par];
    float*       hout = g_hbuf[par ^ 1];

    if (t < BSZ) {
        unsigned long long key = __ldcg(&g_amax[par ^ 1][t]);
        sidx[t] = qix[~(unsigned int)(key & 0xFFFFFFFFull)];
    }
    if (i0 == 0 && t >= 64 && t < 128) g_amax[par][t - 64] = 0ull;
    if (t < NR) {
        int gr = (t & 3) * 512 + u[t >> 2];
        bs[t] = b_ih[gr] + b_hh[gr];
    }

    const int tx = t & 15, ty = t >> 4;
    const int m0 = ty * 4;
    const bool xt = (NR == 20) && (tx < 4);
    float acc[4]  = {0.f, 0.f, 0.f, 0.f};
    float acc2[4] = {0.f, 0.f, 0.f, 0.f};

    float xr[8], wr[3];
    const int lm = t >> 5, lk = t & 31;
    __syncthreads();

    // ---- phase 1: x = relu(emb[idx]) vs W_ih, K=300 ragged ----
    {
#pragma unroll
        for (int n = 0; n < 8; n++) {
            int m = lm + n * 8, k = lk;
            xr[n] = (k < EMB) ? fmaxf(__ldg(&emb[(size_t)sidx[m] * EMB + k]), 0.f) : 0.f;
        }
#pragma unroll
        for (int n = 0; n < 3; n++) {
            int i = t + n * 256;
            if (i < NR * 32) {
                int r = i >> 5, kk = i & 31;
                int gr = (r & 3) * 512 + u[r >> 2];
                wr[n] = (kk < EMB) ? W_ih[(size_t)gr * EMB + kk] : 0.f;
            }
        }
        for (int k0 = 0; k0 < 320; k0 += 32) {
#pragma unroll
            for (int n = 0; n < 8; n++) xh[lk][lm + n * 8] = xr[n];
#pragma unroll
            for (int n = 0; n < 3; n++) {
                int i = t + n * 256;
                if (i < NR * 32) ws[i & 31][i >> 5] = wr[n];
            }
            __syncthreads();
            if (k0 + 32 < 320) {
                int k0n = k0 + 32;
#pragma unroll
                for (int n = 0; n < 8; n++) {
                    int m = lm + n * 8, k = k0n + lk;
                    xr[n] = (k < EMB) ? fmaxf(__ldg(&emb[(size_t)sidx[m] * EMB + k]), 0.f) : 0.f;
                }
#pragma unroll
                for (int n = 0; n < 3; n++) {
                    int i = t + n * 256;
                    if (i < NR * 32) {
                        int r = i >> 5, kk = i & 31;
                        int k = k0n + kk;
                        int gr = (r & 3) * 512 + u[r >> 2];
                        wr[n] = (k < EMB) ? W_ih[(size_t)gr * EMB + k] : 0.f;
                    }
                }
            }
#pragma unroll
            for (int kk = 0; kk < 32; kk++) {
                float4 a = *(const float4*)&xh[kk][m0];
                float w = ws[kk][tx];
                acc[0] = fmaf(w, a.x, acc[0]);
                acc[1] = fmaf(w, a.y, acc[1]);
                acc[2] = fmaf(w, a.z, acc[2]);
                acc[3] = fmaf(w, a.w, acc[3]);
                if (xt) {
                    float w2 = ws[kk][16 + tx];
                    acc2[0] = fmaf(w2, a.x, acc2[0]);
                    acc2[1] = fmaf(w2, a.y, acc2[1]);
                    acc2[2] = fmaf(w2, a.z, acc2[2]);
                    acc2[3] = fmaf(w2, a.w, acc2[3]);
                }
            }
            __syncthreads();
        }
    }

    // ---- phase 2: h vs W_hh, K=512 ----
    {
#pragma unroll
        for (int n = 0; n < 8; n++)
            xr[n] = __ldcg(&hin[(lm + n * 8) * HID + lk]);
#pragma unroll
        for (int n = 0; n < 3; n++) {
            int i = t + n * 256;
            if (i < NR * 32) {
                int r = i >> 5, kk = i & 31;
                int gr = (r & 3) * 512 + u[r >> 2];
                wr[n] = W_hh[(size_t)gr * HID + kk];
            }
        }
        for (int k0 = 0; k0 < HID; k0 += 32) {
#pragma unroll
            for (int n = 0; n < 8; n++) xh[lk][lm + n * 8] = xr[n];
#pragma unroll
            for (int n = 0; n < 3; n++) {
                int i = t + n * 256;
                if (i < NR * 32) ws[i & 31][i >> 5] = wr[n];
            }
            __syncthreads();
            if (k0 + 32 < HID) {
                int k0n = k0 + 32;
#pragma unroll
                for (int n = 0; n < 8; n++)
                    xr[n] = __ldcg(&hin[(lm + n * 8) * HID + k0n + lk]);
#pragma unroll
                for (int n = 0; n < 3; n++) {
                    int i = t + n * 256;
                    if (i < NR * 32) {
                        int r = i >> 5, kk = i & 31;
                        int gr = (r & 3) * 512 + u[r >> 2];
                        wr[n] = W_hh[(size_t)gr * HID + k0n + kk];
                    }
                }
            }
#pragma unroll
            for (int kk = 0; kk < 32; kk++) {
                float4 a = *(const float4*)&xh[kk][m0];
                float w = ws[kk][tx];
                acc[0] = fmaf(w, a.x, acc[0]);
                acc[1] = fmaf(w, a.y, acc[1]);
                acc[2] = fmaf(w, a.z, acc[2]);
                acc[3] = fmaf(w, a.w, acc[3]);
                if (xt) {
                    float w2 = ws[kk][16 + tx];
                    acc2[0] = fmaf(w2, a.x, acc2[0]);
                    acc2[1] = fmaf(w2, a.y, acc2[1]);
                    acc2[2] = fmaf(w2, a.z, acc2[2]);
                    acc2[3] = fmaf(w2, a.w, acc2[3]);
                }
            }
            __syncthreads();
        }
    }

    // gates -> smem (+bias)
    {
        float bb = bs[tx];
        gs[tx][m0]     = acc[0] + bb;
        gs[tx][m0 + 1] = acc[1] + bb;
        gs[tx][m0 + 2] = acc[2] + bb;
        gs[tx][m0 + 3] = acc[3] + bb;
        if (xt) {
            float b2 = bs[16 + tx];
            gs[16 + tx][m0]     = acc2[0] + b2;
            gs[16 + tx][m0 + 1] = acc2[1] + b2;
            gs[16 + tx][m0 + 2] = acc2[2] + b2;
            gs[16 + tx][m0 + 3] = acc2[3] + b2;
        }
    }
    __syncthreads();

    for (int p = t; p < NU * 64; p += 256) {
        int uu = p >> 6, m = p & 63;
        float gi = gs[uu * 4 + 0][m];
        float gf = gs[uu * 4 + 1][m];
        float gg = gs[uu * 4 + 2][m];
        float go = gs[uu * 4 + 3][m];
        int ci = m * HID + u[uu];
        float c  = __ldcg(&g_c[ci]);
        float si = 1.f / (1.f + expf(-gi));
        float sf = 1.f / (1.f + expf(-gf));
        float so = 1.f / (1.f + expf(-go));
        float nc = sf * c + si * tanhf(gg);
        float nh = so * tanhf(nc);
        g_c[ci]  = nc;
        hout[ci] = nh;
    }
    __syncthreads();
}

// ---------------- phase A2: finalize tile in smem -> out ----------------
__device__ void finalize_tile(char* smb, float* __restrict__ out,
                              int sprev, int steps) {
    const int t = threadIdx.x;
    const int w = t >> 5, ln = t & 31;
    const int pp = sprev & 1;
    const int v0 = blockIdx.x * 256;
    float* tile = (float*)(smb + OFF_TILE);
    float* lse_sm = (float*)(smb + OFF_RED);
    __syncthreads();

    for (int r = w; r < BSZ; r += 8) {
        float2 pv[4];
#pragma unroll
        for (int i = 0; i < 4; i++) {
            int idx = ln + i * 32;
            pv[i] = (idx < NBLK) ? __ldcg(&g_part[pp][r][idx])
                                 : make_float2(-3.4e38f, 0.f);
        }
        float m = fmaxf(fmaxf(pv[0].x, pv[1].x), fmaxf(pv[2].x, pv[3].x));
#pragma unroll
        for (int o = 16; o >= 1; o >>= 1)
            m = fmaxf(m, __shfl_xor_sync(0xFFFFFFFFu, m, o));
        float s = pv[0].y * fexp(pv[0].x - m) + pv[1].y * fexp(pv[1].x - m)
                + pv[2].y * fexp(pv[2].x - m) + pv[3].y * fexp(pv[3].x - m);
#pragma unroll
        for (int o = 16; o >= 1; o >>= 1)
            s += __shfl_xor_sync(0xFFFFFFFFu, s, o);
        if (ln == 0) lse_sm[r] = m + logf(s);
    }
    __syncthreads();

#pragma unroll 4
    for (int it = 0; it < 16; it++) {
        int idx = t + it * 256;
        int r  = idx >> 6;
        int c4 = idx & 63;
        float4 x = *(const float4*)&tile[r * 256 + c4 * 4];
        float lse = lse_sm[r];
        x.x -= lse; x.y -= lse; x.z -= lse; x.w -= lse;
        st_cs4(out + ((size_t)r * steps + sprev) * VQ + v0 + c4 * 4, x);
    }
    __syncthreads();
}

// ---------------- phase B: logits GEMM + fused epilogue ----------------
__device__ __forceinline__ void issueB(uint32_t bbase, int c, int v0) {
    int t = threadIdx.x;
#pragma unroll
    for (int n = 0; n < 8; n++) {
        int i = t + n * 256;
        int r = i >> 3, j = i & 7;
        size_t g = (size_t)(v0 + r) * HID + (size_t)c * 64 + j * 8;
        uint32_t so = sw128((uint32_t)(r * 128 + j * 16));
        CP_ASYNC16(bbase + so, g_Whi + g);
        CP_ASYNC16(bbase + 32768 + so, g_Wlo + g);
    }
}
__device__ __forceinline__ void ldgA(const float* h, int c, float4* av) {
    int t = threadIdx.x;
#pragma unroll
    for (int n = 0; n < 4; n++) {
        int i = t + n * 256;
        int r = i >> 4, q = i & 15;
        av[n] = __ldcg((const float4*)&h[r * HID + c * 64 + q * 4]);
    }
}
__device__ __forceinline__ void stsA(uint32_t abase, const float4* av) {
    int t = threadIdx.x;
#pragma unroll
    for (int n = 0; n < 4; n++) {
        int i = t + n * 256;
        int r = i >> 4, q = i & 15;
        float4 x = av[n];
        float hx = __bfloat162float(__float2bfloat16_rn(x.x));
        float hy = __bfloat162float(__float2bfloat16_rn(x.y));
        float hz = __bfloat162float(__float2bfloat16_rn(x.z));
        float hw = __bfloat162float(__float2bfloat16_rn(x.w));
        uint32_t so = sw128((uint32_t)(r * 128 + q * 8));
        asm volatile("st.shared.v2.b32 [%0], {%1, %2};" ::
                     "r"(abase + so), "r"(pb2(hx, hy)), "r"(pb2(hz, hw)) : "memory");
        asm volatile("st.shared.v2.b32 [%0], {%1, %2};" ::
                     "r"(abase + 8192 + so),
                     "r"(pb2(x.x - hx, x.y - hy)), "r"(pb2(x.z - hz, x.w - hw)) : "memory");
    }
}

// B chunks 0 AND 1 already prefetched (two cp.async groups pending).
__device__ void logits_phase(char* smb, uint32_t base, int par) {
    const int t  = threadIdx.x;
    const int wid = t >> 5, ln = t & 31;
    const int v0 = blockIdx.x * 256;
    const float* h = g_hbuf[par ^ 1];
    float* bias_sm = (float*)(smb + OFF_BIAS);

    float acc[4][4][4];
#pragma unroll
    for (int a = 0; a < 4; a++)
#pragma unroll
        for (int b = 0; b < 4; b++)
#pragma unroll
            for (int cc = 0; cc < 4; cc++) acc[a][b][cc] = 0.f;

    {
        float4 av[4];
        ldgA(h, 0, av);
        stsA(base, av);
    }

    const int ti = ln >> 3, li = ln & 7;
    const int aml = (ti & 1) * 8 + li, ak = ti >> 1;
    const int bnl = (ti >> 1) * 8 + li, bk = ti & 1;
    const int nbase = wid * 32;

    float4 av[4];
    for (int c = 0; c < NCHUNK; c++) {
        int b = c & 1;
        if (c >= 1 && c < NCHUNK - 1) {
            issueB(base + OFF_B + (b ^ 1) * 65536, c + 1, v0);
            CP_COMMIT();
        }
        if (c < NCHUNK - 1) {
            ldgA(h, c + 1, av);
            CP_WAIT(1);
        } else {
            CP_WAIT(0);
        }
        __syncthreads();

        uint32_t Ahi = base + b * 16384, Alo = Ahi + 8192;
        uint32_t Bhi = base + OFF_B + b * 65536, Blo = Bhi + 32768;
#pragma unroll
        for (int ks = 0; ks < 4; ks++) {
            uint32_t ah[4][4], al[4][4], bh[4][2], bl[4][2];
#pragma unroll
            for (int mt = 0; mt < 4; mt++) {
                uint32_t off = sw128((uint32_t)((mt * 16 + aml) * 128 + ks * 32 + ak * 16));
                ldsm4(ah[mt], Ahi + off);
                ldsm4(al[mt], Alo + off);
            }
#pragma unroll
            for (int ng = 0; ng < 2; ng++) {
                uint32_t off = sw128((uint32_t)((nbase + ng * 16 + bnl) * 128 + ks * 32 + bk * 16));
                uint32_t r4[4];
                ldsm4(r4, Bhi + off);
                bh[ng * 2][0] = r4[0]; bh[ng * 2][1] = r4[1];
                bh[ng * 2 + 1][0] = r4[2]; bh[ng * 2 + 1][1] = r4[3];
                ldsm4(r4, Blo + off);
                bl[ng * 2][0] = r4[0]; bl[ng * 2][1] = r4[1];
                bl[ng * 2 + 1][0] = r4[2]; bl[ng * 2 + 1][1] = r4[3];
            }
#pragma unroll
            for (int mt = 0; mt < 4; mt++)
#pragma unroll
                for (int nt = 0; nt < 4; nt++) {
                    mma16816(acc[mt][nt], ah[mt], bh[nt]);
                    mma16816(acc[mt][nt], ah[mt], bl[nt]);
                    mma16816(acc[mt][nt], al[mt], bh[nt]);
                }
        }
        if (c < NCHUNK - 1) stsA(base + (b ^ 1) * 16384, av);
        __syncthreads();
    }

    // epilogue: frags + bias -> TILE (buf1 region, dead after mainloop)
    float* tile = (float*)(smb + OFF_TILE);
    const int g = ln >> 2, tg2 = (ln & 3) * 2;
#pragma unroll
    for (int mt = 0; mt < 4; mt++)
#pragma unroll
        for (int nt = 0; nt < 4; nt++) {
            int row0 = mt * 16 + g;
            int col  = nbase + nt * 8 + tg2;
            float b0 = bias_sm[col], b1 = bias_sm[col + 1];
            tile[row0 * 256 + col]           = acc[mt][nt][0] + b0;
            tile[row0 * 256 + col + 1]       = acc[mt][nt][1] + b1;
            tile[(row0 + 8) * 256 + col]     = acc[mt][nt][2] + b0;
            tile[(row0 + 8) * 256 + col + 1] = acc[mt][nt][3] + b1;
        }
    __syncthreads();

    // row scan (argmax + softmax partials); tile stays resident for finalize
#pragma unroll 1
    for (int i8 = 0; i8 < 8; i8++) {
        int r = wid * 8 + i8;
        float4 va = *(const float4*)&tile[r * 256 + ln * 8];
        float4 vb = *(const float4*)&tile[r * 256 + ln * 8 + 4];
        float vals[8] = {va.x, va.y, va.z, va.w, vb.x, vb.y, vb.z, vb.w};
        int c0 = v0 + ln * 8;

        float vm = vals[0]; int vi = c0;
#pragma unroll
        for (int j = 1; j < 8; j++)
            if (vals[j] > vm) { vm = vals[j]; vi = c0 + j; }

        unsigned long long key =
            ((unsigned long long)fmono(vm) << 32) |
            (unsigned int)(~(unsigned int)vi);
#pragma unroll
        for (int o = 16; o >= 1; o >>= 1) {
            unsigned long long other = __shfl_xor_sync(0xFFFFFFFFu, key, o);
            if (other > key) key = other;
        }
        float mrow = fmono_inv((unsigned int)(key >> 32));

        float s = 0.f;
#pragma unroll
        for (int j = 0; j < 8; j++) s += fexp(vals[j] - mrow);
#pragma unroll
        for (int o = 16; o >= 1; o >>= 1)
            s += __shfl_xor_sync(0xFFFFFFFFu, s, o);

        if (ln == 0) {
            atomicMax(&g_amax[par][r], key);
            g_part[par][r][blockIdx.x] = make_float2(mrow, s);
        }
    }
    __syncthreads();
}

// ---------------- the persistent decode kernel (single launch) ----------------
__global__ void __launch_bounds__(256, 1)
k_main(const float* __restrict__ q_att,
       const float* __restrict__ emb,
       const float* __restrict__ W_ih,
       const float* __restrict__ W_hh,
       const float* __restrict__ b_ih,
       const float* __restrict__ b_hh,
       const float* __restrict__ out_W,
       const float* __restrict__ out_b,
       const int*   __restrict__ qix,
       float* __restrict__ out, int steps) {
    extern __shared__ __align__(16) char smem_raw[];
    uint32_t raw  = smem_u32(smem_raw);
    uint32_t base = (raw + 1023) & ~1023u;
    char* smb = smem_raw + (base - raw);
    const int t = threadIdx.x;
    const int v0cta = blockIdx.x * 256;

    // epoch base for monotonic barrier targets (t0 only; others pass 0)
    unsigned int Eval = 0, ebase = 0;
    int nb = 0;
    const unsigned int NBAR = (unsigned int)(1 + 2 * steps);
    if (t == 0) {
        asm volatile("ld.global.acquire.gpu.b32 %0, [%1];"
                     : "=r"(Eval) : "l"(&g_epoch));
        ebase = Eval * NBAR * NCTA;
    }

    // ---- prologue: W split (all CTAs) + state init (CTA 0) ----
    {
        size_t n4 = (size_t)VQ * HID / 4;
        uint2* whi = (uint2*)g_Whi;
        uint2* wlo = (uint2*)g_Wlo;
        for (size_t i = (size_t)blockIdx.x * 256 + t; i < n4; i += (size_t)NCTA * 256) {
            float4 x = ((const float4*)out_W)[i];
            float hx = __bfloat162float(__float2bfloat16_rn(x.x));
            float hy = __bfloat162float(__float2bfloat16_rn(x.y));
            float hz = __bfloat162float(__float2bfloat16_rn(x.z));
            float hw = __bfloat162float(__float2bfloat16_rn(x.w));
            whi[i] = make_uint2(pb2(hx, hy), pb2(hz, hw));
            wlo[i] = make_uint2(pb2(x.x - hx, x.y - hy), pb2(x.z - hz, x.w - hw));
        }
        if (blockIdx.x == 0) {
            if (t < BSZ) {
                g_amax[1][t] = (unsigned long long)(unsigned int)(~(unsigned int)SOS);
                g_amax[0][t] = 0ull;
            }
            for (int i = t; i < BSZ * HID; i += 256) {
                g_hbuf[0][i] = q_att[i];
                g_c[i] = 0.f;
            }
        }
        ((float*)(smb + OFF_BIAS))[t] = out_b[v0cta + t];
    }
    ++nb; gsync(ebase + nb * NCTA);

    for (int s = 0; s < steps; s++) {
        int par = s & 1;

        // prefetch B chunk 0 into buf0 (TILE in buf1 untouched)
        issueB(base + OFF_B, 0, v0cta);
        CP_COMMIT();

        lstm_phase(smb, emb, W_ih, W_hh, b_ih, b_hh, qix, par);
        if (s > 0) finalize_tile(smb, out, s - 1, steps);

        // TILE consumed -> prefetch B chunk 1 into buf1
        issueB(base + OFF_B + 65536, 1, v0cta);
        CP_COMMIT();

        ++nb; gsync(ebase + nb * NCTA);

        logits_phase(smb, base, par);
        ++nb; gsync(ebase + nb * NCTA);
    }

    // bump epoch for the next launch (after the last barrier; pollers use counts only)
    if (blockIdx.x == 0 && t == 0)
        *((volatile unsigned int*)&g_epoch) = Eval + 1;

    finalize_tile(smb, out, steps - 1, steps);
}

// ---------------- launch ----------------
extern "C" void kernel_launch(void* const* d_in, const int* in_sizes, int n_in,
                              void* d_out, int out_size) {
    (void)in_sizes; (void)n_in;
    const float* q_att = (const float*)d_in[1];
    const float* emb   = (const float*)d_in[2];
    const float* W_ih  = (const float*)d_in[3];
    const float* W_hh  = (const float*)d_in[4];
    const float* b_ih  = (const float*)d_in[5];
    const float* b_hh  = (const float*)d_in[6];
    const float* out_W = (const float*)d_in[7];
    const float* out_b = (const float*)d_in[8];
    const int*   qix   = (const int*)d_in[9];

    int steps = out_size / (BSZ * VQ);  // 33

    cudaFuncSetAttribute(k_main, cudaFuncAttributeMaxDynamicSharedMemorySize,
                         SMEM_REQ);

    k_main<<<NCTA, 256, SMEM_REQ>>>(q_att, emb, W_ih, W_hh, b_ih, b_hh,
                                    out_W, out_b, qix, (float*)d_out, steps);
}